// round 4
// baseline (speedup 1.0000x reference)
#include <cuda_runtime.h>
#include <math.h>

#define BB 4
#define T 1024
#define D 512
#define H 8
#define DKK 64
#define LL 2047
#define BT (BB*T)      // 4096
#define BL (BB*LL)     // 8188

__device__ float g_y[BT*D];
__device__ float g_qc[BT*D];   // q + bq + content_bias
__device__ float g_qp[BT*D];   // q + bq + pos_bias
__device__ float g_k[BT*D];
__device__ float g_v[BT*D];
__device__ float g_p[BL*D];
__device__ float g_o[BT*D];

// ---------------- helpers ----------------
__device__ __forceinline__ unsigned f2tf(float f) {
    unsigned u; asm("cvt.rna.tf32.f32 %0, %1;" : "=r"(u) : "f"(f)); return u;
}
__device__ __forceinline__ void mma_tf32(float d[4], const unsigned a[4], const unsigned b[2]) {
    asm volatile("mma.sync.aligned.m16n8k8.row.col.f32.tf32.tf32.f32 "
        "{%0,%1,%2,%3},{%4,%5,%6,%7},{%8,%9},{%0,%1,%2,%3};\n"
        : "+f"(d[0]), "+f"(d[1]), "+f"(d[2]), "+f"(d[3])
        : "r"(a[0]), "r"(a[1]), "r"(a[2]), "r"(a[3]), "r"(b[0]), "r"(b[1]));
}
__device__ __forceinline__ void cpasync16(void* dst, const void* src, bool pred) {
    unsigned d = (unsigned)__cvta_generic_to_shared(dst);
    int sz = pred ? 16 : 0;
    asm volatile("cp.async.cg.shared.global [%0], [%1], 16, %2;\n"
                 :: "r"(d), "l"(src), "r"(sz));
}

// ---------------- LayerNorm ----------------
__global__ void ln_kernel(const float* __restrict__ x,
                          const float* __restrict__ gamma,
                          const float* __restrict__ beta) {
    int row = blockIdx.x;
    const float* xr = x + (size_t)row * D;
    float* yr = g_y + (size_t)row * D;
    int t = threadIdx.x;  // 256
    float v0 = xr[t], v1 = xr[t + 256];
    float s = v0 + v1, sq = v0 * v0 + v1 * v1;
    __shared__ float ss[8], ssq[8], mb[2];
    #pragma unroll
    for (int o = 16; o > 0; o >>= 1) {
        s  += __shfl_xor_sync(0xFFFFFFFFu, s, o);
        sq += __shfl_xor_sync(0xFFFFFFFFu, sq, o);
    }
    if ((t & 31) == 0) { ss[t >> 5] = s; ssq[t >> 5] = sq; }
    __syncthreads();
    if (t == 0) {
        float S = 0.f, SQ = 0.f;
        #pragma unroll
        for (int i = 0; i < 8; i++) { S += ss[i]; SQ += ssq[i]; }
        float mean = S * (1.0f / D);
        float var = SQ * (1.0f / D) - mean * mean;
        mb[0] = mean;
        mb[1] = rsqrtf(var + 1e-3f);
    }
    __syncthreads();
    float mean = mb[0], rstd = mb[1];
    yr[t]       = (v0 - mean) * rstd * gamma[t]       + beta[t];
    yr[t + 256] = (v1 - mean) * rstd * gamma[t + 256] + beta[t + 256];
}

// ---------------- 64x128-tile tf32 GEMM pieces ----------------
struct Proj64Smem {
    float As[2][64][36];
    float Bs[2][32][136];
};

__device__ __forceinline__ void proj64_load(Proj64Smem* S, int buf,
                                            const float* A, const float* W,
                                            int i0, int j0, int kk, int M, int tid) {
    #pragma unroll
    for (int p = 0; p < 2; p++) {
        int idx = p * 256 + tid;
        int r = idx >> 3, c4 = (idx & 7) * 4;
        cpasync16(&S->As[buf][r][c4], &A[(size_t)(i0 + r) * 512 + kk + c4], (i0 + r) < M);
    }
    #pragma unroll
    for (int p = 0; p < 4; p++) {
        int idx = p * 256 + tid;
        int k = idx >> 5, c4 = (idx & 31) * 4;
        cpasync16(&S->Bs[buf][k][c4], &W[(size_t)(kk + k) * 512 + j0 + c4], true);
    }
    asm volatile("cp.async.commit_group;");
}

__device__ __forceinline__ void proj64_core(Proj64Smem* S,
                                            const float* A, const float* W,
                                            int i0, int j0, int M, int tid,
                                            float acc[2][4][4]) {
    int warp = tid >> 5, lane = tid & 31;
    int wy = warp >> 2, wx = warp & 3;
    int g = lane >> 2, q = lane & 3;
    proj64_load(S, 0, A, W, i0, j0, 0, M, tid);
    for (int s = 0; s < 16; s++) {
        if (s < 15) {
            proj64_load(S, (s + 1) & 1, A, W, i0, j0, (s + 1) * 32, M, tid);
            asm volatile("cp.async.wait_group 1;");
        } else {
            asm volatile("cp.async.wait_group 0;");
        }
        __syncthreads();
        int buf = s & 1;
        #pragma unroll
        for (int k8 = 0; k8 < 4; k8++) {
            int kc = k8 * 8 + q;
            unsigned af[2][4], bf[4][2];
            #pragma unroll
            for (int mt = 0; mt < 2; mt++) {
                int r = wy * 32 + mt * 16;
                af[mt][0] = f2tf(S->As[buf][r + g][kc]);
                af[mt][1] = f2tf(S->As[buf][r + g + 8][kc]);
                af[mt][2] = f2tf(S->As[buf][r + g][kc + 4]);
                af[mt][3] = f2tf(S->As[buf][r + g + 8][kc + 4]);
            }
            #pragma unroll
            for (int nt = 0; nt < 4; nt++) {
                int c = wx * 32 + nt * 8 + g;
                bf[nt][0] = f2tf(S->Bs[buf][kc][c]);
                bf[nt][1] = f2tf(S->Bs[buf][kc + 4][c]);
            }
            #pragma unroll
            for (int mt = 0; mt < 2; mt++)
                #pragma unroll
                for (int nt = 0; nt < 4; nt++)
                    mma_tf32(acc[mt][nt], af[mt], bf[nt]);
        }
        __syncthreads();
    }
}

// generic: C = A@W (+bias, +res)
__global__ void __launch_bounds__(256) proj64(
        const float* __restrict__ A, const float* __restrict__ W,
        const float* __restrict__ bias, const float* __restrict__ res,
        float* __restrict__ C, int M) {
    extern __shared__ char raw[];
    Proj64Smem* S = (Proj64Smem*)raw;
    int tid = threadIdx.x;
    int warp = tid >> 5, lane = tid & 31;
    int wy = warp >> 2, wx = warp & 3;
    int g = lane >> 2, q = lane & 3;
    int i0 = blockIdx.y * 64, j0 = blockIdx.x * 128;
    float acc[2][4][4] = {};
    proj64_core(S, A, W, i0, j0, M, tid, acc);
    #pragma unroll
    for (int mt = 0; mt < 2; mt++)
        #pragma unroll
        for (int nt = 0; nt < 4; nt++) {
            int c = j0 + wx * 32 + nt * 8 + q * 2;
            float b0 = bias ? bias[c] : 0.f;
            float b1 = bias ? bias[c + 1] : 0.f;
            #pragma unroll
            for (int half = 0; half < 2; half++) {
                int rr = i0 + wy * 32 + mt * 16 + g + half * 8;
                if (rr >= M) continue;
                float e0 = acc[mt][nt][half * 2 + 0] + b0;
                float e1 = acc[mt][nt][half * 2 + 1] + b1;
                if (res) { e0 += res[(size_t)rr * 512 + c]; e1 += res[(size_t)rr * 512 + c + 1]; }
                *(float2*)&C[(size_t)rr * 512 + c] = make_float2(e0, e1);
            }
        }
}

// fused q/k/v projection; blockIdx.z selects weight; z==0 writes qc AND qp
__global__ void __launch_bounds__(256) qkv_mma(
        const float* __restrict__ Wq, const float* __restrict__ Wk, const float* __restrict__ Wv,
        const float* __restrict__ bq, const float* __restrict__ bk, const float* __restrict__ bv,
        const float* __restrict__ cb, const float* __restrict__ pb) {
    extern __shared__ char raw[];
    Proj64Smem* S = (Proj64Smem*)raw;
    int z = blockIdx.z;
    const float* W    = (z == 0) ? Wq : (z == 1) ? Wk : Wv;
    const float* bias = (z == 0) ? bq : (z == 1) ? bk : bv;
    int tid = threadIdx.x;
    int warp = tid >> 5, lane = tid & 31;
    int wy = warp >> 2, wx = warp & 3;
    int g = lane >> 2, q = lane & 3;
    int i0 = blockIdx.y * 64, j0 = blockIdx.x * 128;
    float acc[2][4][4] = {};
    proj64_core(S, g_y, W, i0, j0, BT, tid, acc);
    float* C1 = (z == 0) ? g_qc : (z == 1) ? g_k : g_v;
    #pragma unroll
    for (int mt = 0; mt < 2; mt++)
        #pragma unroll
        for (int nt = 0; nt < 4; nt++) {
            int c = j0 + wx * 32 + nt * 8 + q * 2;
            float b0 = bias[c], b1 = bias[c + 1];
            #pragma unroll
            for (int half = 0; half < 2; half++) {
                int rr = i0 + wy * 32 + mt * 16 + g + half * 8;
                float e0 = acc[mt][nt][half * 2 + 0] + b0;
                float e1 = acc[mt][nt][half * 2 + 1] + b1;
                if (z == 0) {
                    *(float2*)&C1[(size_t)rr * 512 + c] = make_float2(e0 + cb[c], e1 + cb[c + 1]);
                    *(float2*)&g_qp[(size_t)rr * 512 + c] = make_float2(e0 + pb[c], e1 + pb[c + 1]);
                } else {
                    *(float2*)&C1[(size_t)rr * 512 + c] = make_float2(e0, e1);
                }
            }
        }
}

// ---------------- fused flash attention with rolling positional ring ----------------
struct FlashSmem {
    unsigned Qc[64][68];        // tf32
    unsigned Qp[64][68];        // tf32
    float Ks[2][64][68];        // raw f32, cp.async
    float Vs[2][64][68];
    float Ps[2][64][68];
    float R[64][256];           // positional ring, indexed by l & 255
    unsigned Sx[64][68];
    float mrow[64], srow[64], crow[64];
};

// pos chunk GEMM: R[:, (cbase+cp)&255] = Qp @ Ps^T, cp = 0..63
__device__ __forceinline__ void pos_chunk(FlashSmem* S, const float (*P)[68],
                                          int cbase, int wy, int wx, int g, int q) {
    float accP[2][4] = {};
    #pragma unroll
    for (int k8 = 0; k8 < 8; k8++) {
        int kc = k8 * 8 + q;
        int r = wy * 16;
        unsigned ap[4];
        ap[0] = S->Qp[r + g][kc];     ap[1] = S->Qp[r + g + 8][kc];
        ap[2] = S->Qp[r + g][kc + 4]; ap[3] = S->Qp[r + g + 8][kc + 4];
        #pragma unroll
        for (int nt = 0; nt < 2; nt++) {
            int n = wx * 16 + nt * 8 + g;
            unsigned bf[2] = { f2tf(P[n][kc]), f2tf(P[n][kc + 4]) };
            mma_tf32(accP[nt], ap, bf);
        }
    }
    #pragma unroll
    for (int nt = 0; nt < 2; nt++) {
        int cp = wx * 16 + nt * 8 + q * 2;
        int c0 = (cbase + cp) & 255;
        int c1 = (cbase + cp + 1) & 255;
        int r0 = wy * 16 + g;
        S->R[r0][c0] = accP[nt][0];     S->R[r0][c1] = accP[nt][1];
        S->R[r0 + 8][c0] = accP[nt][2]; S->R[r0 + 8][c1] = accP[nt][3];
    }
}

__global__ void __launch_bounds__(512, 1) flash_kernel() {
    extern __shared__ char raw[];
    FlashSmem* S = (FlashSmem*)raw;
    int z = blockIdx.y; int b = z >> 3, h = z & 7;
    int i0 = blockIdx.x * 64;
    int tid = threadIdx.x;
    int warp = tid >> 5, lane = tid & 31;
    int wy = warp >> 2, wx = warp & 3;   // 4(M) x 4(N)
    int g = lane >> 2, q = lane & 3;

    // ---- prologue loads: Q tiles (converted) + two pos chunks (raw) ----
    const float* qcb = g_qc + ((size_t)(b * T + i0)) * D + h * DKK;
    const float* qpb = g_qp + ((size_t)(b * T + i0)) * D + h * DKK;
    #pragma unroll
    for (int p = 0; p < 2; p++) {
        int idx = p * 512 + tid;
        int r = idx >> 4, c4 = (idx & 15) * 4;
        float4 v = *(const float4*)&qcb[(size_t)r * D + c4];
        { uint4 u = { f2tf(v.x), f2tf(v.y), f2tf(v.z), f2tf(v.w) }; *(uint4*)&S->Qc[r][c4] = u; }
        v = *(const float4*)&qpb[(size_t)r * D + c4];
        { uint4 u = { f2tf(v.x), f2tf(v.y), f2tf(v.z), f2tf(v.w) }; *(uint4*)&S->Qp[r][c4] = u; }
        // prologue P chunks: bases 960-i0 (stage 0) and 1024-i0 (stage 1)
        int l0 = 960 - i0 + r;  l0 = min(max(l0, 0), LL - 1);
        int l1 = 1024 - i0 + r; l1 = min(max(l1, 0), LL - 1);
        *(float4*)&S->Ps[0][r][c4] = *(const float4*)&g_p[((size_t)(b * LL + l0)) * D + h * DKK + c4];
        *(float4*)&S->Ps[1][r][c4] = *(const float4*)&g_p[((size_t)(b * LL + l1)) * D + h * DKK + c4];
    }
    if (tid < 64) { S->mrow[tid] = -1e30f; S->srow[tid] = 0.f; }
    float accO[2][4] = {};
    __syncthreads();

    // prologue pos MMAs fill ring for window jt=0
    pos_chunk(S, S->Ps[0], 960 - i0, wy, wx, g, q);
    pos_chunk(S, S->Ps[1], 1024 - i0, wy, wx, g, q);
    __syncthreads();

    // prefetch jt=0 tiles into stage 0
    {
        const float* kb = g_k + ((size_t)(b * T)) * D + h * DKK;
        const float* vb = g_v + ((size_t)(b * T)) * D + h * DKK;
        #pragma unroll
        for (int p = 0; p < 2; p++) {
            int idx = p * 512 + tid;
            int r = idx >> 4, c4 = (idx & 15) * 4;
            cpasync16(&S->Ks[0][r][c4], &kb[(size_t)r * D + c4], true);
            cpasync16(&S->Vs[0][r][c4], &vb[(size_t)r * D + c4], true);
            int l = 1088 - i0 + r; l = min(max(l, 0), LL - 1);
            cpasync16(&S->Ps[0][r][c4], &g_p[((size_t)(b * LL + l)) * D + h * DKK + c4], true);
        }
        asm volatile("cp.async.commit_group;");
    }

    for (int jt = 0; jt < 16; jt++) {
        asm volatile("cp.async.wait_group 0;");
        __syncthreads();
        int st = jt & 1;
        // prefetch jt+1
        if (jt < 15) {
            int st2 = (jt + 1) & 1;
            const float* kb = g_k + ((size_t)(b * T + (jt + 1) * 64)) * D + h * DKK;
            const float* vb = g_v + ((size_t)(b * T + (jt + 1) * 64)) * D + h * DKK;
            #pragma unroll
            for (int p = 0; p < 2; p++) {
                int idx = p * 512 + tid;
                int r = idx >> 4, c4 = (idx & 15) * 4;
                cpasync16(&S->Ks[st2][r][c4], &kb[(size_t)r * D + c4], true);
                cpasync16(&S->Vs[st2][r][c4], &vb[(size_t)r * D + c4], true);
                int l = 1088 + 64 * (jt + 1) - i0 + r; l = min(max(l, 0), LL - 1);
                cpasync16(&S->Ps[st2][r][c4], &g_p[((size_t)(b * LL + l)) * D + h * DKK + c4], true);
            }
            asm volatile("cp.async.commit_group;");
        }

        // content MMA
        float accC[2][4] = {};
        #pragma unroll
        for (int k8 = 0; k8 < 8; k8++) {
            int kc = k8 * 8 + q;
            int r = wy * 16;
            unsigned ac[4];
            ac[0] = S->Qc[r + g][kc];     ac[1] = S->Qc[r + g + 8][kc];
            ac[2] = S->Qc[r + g][kc + 4]; ac[3] = S->Qc[r + g + 8][kc + 4];
            #pragma unroll
            for (int nt = 0; nt < 2; nt++) {
                int n = wx * 16 + nt * 8 + g;
                unsigned bf[2] = { f2tf(S->Ks[st][n][kc]), f2tf(S->Ks[st][n][kc + 4]) };
                mma_tf32(accC[nt], ac, bf);
            }
        }
        // pos chunk for window jt+1 (ring slots disjoint from this window's reads)
        if (jt < 15)
            pos_chunk(S, S->Ps[st], 1088 + 64 * jt - i0, wy, wx, g, q);

        // combine content + shifted positional -> Sx (scaled)
        int base = 1024 + 64 * jt - i0;
        #pragma unroll
        for (int nt = 0; nt < 2; nt++) {
            int jl = wx * 16 + nt * 8 + q * 2;
            #pragma unroll
            for (int half = 0; half < 2; half++) {
                int il = wy * 16 + g + half * 8;
                int c0 = (base + jl - il) & 255;
                int c1 = (base + jl + 1 - il) & 255;
                S->Sx[il][jl]     = __float_as_uint((accC[nt][half * 2 + 0] + S->R[il][c0]) * 0.125f);
                S->Sx[il][jl + 1] = __float_as_uint((accC[nt][half * 2 + 1] + S->R[il][c1]) * 0.125f);
            }
        }
        // rel_shift wraparound: (i=0, j=1023) -> dot(qp[1], p[0])
        if (i0 == 0 && jt == 15) {
            __syncthreads();
            if (tid < 32) {
                float a0 = g_qp[((size_t)(b * T + 1)) * D + h * DKK + lane];
                float a1 = g_qp[((size_t)(b * T + 1)) * D + h * DKK + lane + 32];
                float p0 = g_p[((size_t)(b * LL)) * D + h * DKK + lane];
                float p1 = g_p[((size_t)(b * LL)) * D + h * DKK + lane + 32];
                float sdot = a0 * p0 + a1 * p1;
                #pragma unroll
                for (int o = 16; o > 0; o >>= 1)
                    sdot += __shfl_xor_sync(0xFFFFFFFFu, sdot, o);
                if (lane == 0) {
                    float old = __uint_as_float(S->Sx[0][63]);
                    S->Sx[0][63] = __float_as_uint(old + 0.125f * (sdot - S->R[0][255]));
                }
            }
        }
        __syncthreads();

        // online softmax: 8 threads per row
        {
            int row = tid >> 3, seg = tid & 7;
            float vals[8];
            float tmax = -1e30f;
            #pragma unroll
            for (int i = 0; i < 8; i++) {
                vals[i] = __uint_as_float(S->Sx[row][seg * 8 + i]);
                tmax = fmaxf(tmax, vals[i]);
            }
            tmax = fmaxf(tmax, __shfl_xor_sync(0xFFFFFFFFu, tmax, 1));
            tmax = fmaxf(tmax, __shfl_xor_sync(0xFFFFFFFFu, tmax, 2));
            tmax = fmaxf(tmax, __shfl_xor_sync(0xFFFFFFFFu, tmax, 4));
            float mold = S->mrow[row];
            float mnew = fmaxf(mold, tmax);
            float corr = __expf(mold - mnew);
            float sum = 0.f;
            #pragma unroll
            for (int i = 0; i < 8; i++) {
                float e = __expf(vals[i] - mnew);
                sum += e;
                S->Sx[row][seg * 8 + i] = f2tf(e);
            }
            sum += __shfl_xor_sync(0xFFFFFFFFu, sum, 1);
            sum += __shfl_xor_sync(0xFFFFFFFFu, sum, 2);
            sum += __shfl_xor_sync(0xFFFFFFFFu, sum, 4);
            if (seg == 0) {
                S->mrow[row] = mnew;
                S->srow[row] = S->srow[row] * corr + sum;
                S->crow[row] = corr;
            }
        }
        __syncthreads();

        // AV accumulate (rescale first)
        {
            float c0 = S->crow[wy * 16 + g];
            float c1 = S->crow[wy * 16 + g + 8];
            #pragma unroll
            for (int nt = 0; nt < 2; nt++) {
                accO[nt][0] *= c0; accO[nt][1] *= c0;
                accO[nt][2] *= c1; accO[nt][3] *= c1;
            }
            #pragma unroll
            for (int k8 = 0; k8 < 8; k8++) {
                int kc = k8 * 8 + q;
                int r = wy * 16;
                unsigned a[4];
                a[0] = S->Sx[r + g][kc];     a[1] = S->Sx[r + g + 8][kc];
                a[2] = S->Sx[r + g][kc + 4]; a[3] = S->Sx[r + g + 8][kc + 4];
                #pragma unroll
                for (int nt = 0; nt < 2; nt++) {
                    int n = wx * 16 + nt * 8 + g;
                    unsigned bf[2] = { f2tf(S->Vs[st][kc][n]), f2tf(S->Vs[st][kc + 4][n]) };
                    mma_tf32(accO[nt], a, bf);
                }
            }
        }
    }
    // finalize
    float inv0 = 1.f / S->srow[wy * 16 + g];
    float inv1 = 1.f / S->srow[wy * 16 + g + 8];
    #pragma unroll
    for (int nt = 0; nt < 2; nt++) {
        int col = h * DKK + wx * 16 + nt * 8 + q * 2;
        int r0 = i0 + wy * 16 + g;
        *(float2*)&g_o[((size_t)(b * T + r0)) * D + col] =
            make_float2(accO[nt][0] * inv0, accO[nt][1] * inv0);
        *(float2*)&g_o[((size_t)(b * T + r0 + 8)) * D + col] =
            make_float2(accO[nt][2] * inv1, accO[nt][3] * inv1);
    }
}

extern "C" void kernel_launch(void* const* d_in, const int* in_sizes, int n_in,
                              void* d_out, int out_size) {
    const float* x     = (const float*)d_in[0];
    const float* pos   = (const float*)d_in[1];
    const float* cb    = (const float*)d_in[2];
    const float* pb    = (const float*)d_in[3];
    const float* gamma = (const float*)d_in[4];
    const float* beta  = (const float*)d_in[5];
    const float* Wq    = (const float*)d_in[6];
    const float* bq    = (const float*)d_in[7];
    const float* Wk    = (const float*)d_in[8];
    const float* bk    = (const float*)d_in[9];
    const float* Wv    = (const float*)d_in[10];
    const float* bv    = (const float*)d_in[11];
    const float* Wp    = (const float*)d_in[12];
    const float* Wo    = (const float*)d_in[13];
    const float* bo    = (const float*)d_in[14];
    float* out = (float*)d_out;

    float *p, *o;
    cudaGetSymbolAddress((void**)&p, g_p);
    cudaGetSymbolAddress((void**)&o, g_o);

    cudaFuncSetAttribute(proj64, cudaFuncAttributeMaxDynamicSharedMemorySize,
                         (int)sizeof(Proj64Smem));
    cudaFuncSetAttribute(qkv_mma, cudaFuncAttributeMaxDynamicSharedMemorySize,
                         (int)sizeof(Proj64Smem));
    cudaFuncSetAttribute(flash_kernel, cudaFuncAttributeMaxDynamicSharedMemorySize,
                         (int)sizeof(FlashSmem));

    // 1. LayerNorm
    ln_kernel<<<BT, 256>>>(x, gamma, beta);

    // 2. projections: fused q/k/v (grid.z) + positional
    qkv_mma<<<dim3(4, 64, 3), 256, sizeof(Proj64Smem)>>>(Wq, Wk, Wv, bq, bk, bv, cb, pb);
    proj64<<<dim3(4, 128), 256, sizeof(Proj64Smem)>>>(pos, Wp, nullptr, nullptr, p, BL);

    // 3-5. fused flash attention (content + rel-shift pos + softmax + AV)
    flash_kernel<<<dim3(16, 32), 512, sizeof(FlashSmem)>>>();

    // 6. output projection + bias + residual
    proj64<<<dim3(4, 64), 256, sizeof(Proj64Smem)>>>(o, Wo, bo, x, out, BT);
}

// round 5
// speedup vs baseline: 1.0530x; 1.0530x over previous
#include <cuda_runtime.h>
#include <math.h>

#define BB 4
#define T 1024
#define D 512
#define H 8
#define DKK 64
#define LL 2047
#define BT (BB*T)      // 4096
#define BL (BB*LL)     // 8188

__device__ float g_y[BT*D];
__device__ float g_qc[BT*D];   // q + bq + content_bias
__device__ float g_qp[BT*D];   // q + bq + pos_bias
__device__ float g_k[BT*D];
__device__ float g_v[BT*D];
__device__ float g_p[BL*D];
__device__ float g_o[BT*D];

// ---------------- helpers ----------------
__device__ __forceinline__ unsigned f2tf(float f) {
    unsigned u; asm("cvt.rna.tf32.f32 %0, %1;" : "=r"(u) : "f"(f)); return u;
}
__device__ __forceinline__ void mma_tf32(float d[4], const unsigned a[4], const unsigned b[2]) {
    asm volatile("mma.sync.aligned.m16n8k8.row.col.f32.tf32.tf32.f32 "
        "{%0,%1,%2,%3},{%4,%5,%6,%7},{%8,%9},{%0,%1,%2,%3};\n"
        : "+f"(d[0]), "+f"(d[1]), "+f"(d[2]), "+f"(d[3])
        : "r"(a[0]), "r"(a[1]), "r"(a[2]), "r"(a[3]), "r"(b[0]), "r"(b[1]));
}
__device__ __forceinline__ void cpasync16(void* dst, const void* src, bool pred) {
    unsigned d = (unsigned)__cvta_generic_to_shared(dst);
    int sz = pred ? 16 : 0;
    asm volatile("cp.async.cg.shared.global [%0], [%1], 16, %2;\n"
                 :: "r"(d), "l"(src), "r"(sz));
}

// ---------------- LayerNorm ----------------
__global__ void ln_kernel(const float* __restrict__ x,
                          const float* __restrict__ gamma,
                          const float* __restrict__ beta) {
    int row = blockIdx.x;
    const float* xr = x + (size_t)row * D;
    float* yr = g_y + (size_t)row * D;
    int t = threadIdx.x;  // 256
    float v0 = xr[t], v1 = xr[t + 256];
    float s = v0 + v1, sq = v0 * v0 + v1 * v1;
    __shared__ float ss[8], ssq[8], mb[2];
    #pragma unroll
    for (int o = 16; o > 0; o >>= 1) {
        s  += __shfl_xor_sync(0xFFFFFFFFu, s, o);
        sq += __shfl_xor_sync(0xFFFFFFFFu, sq, o);
    }
    if ((t & 31) == 0) { ss[t >> 5] = s; ssq[t >> 5] = sq; }
    __syncthreads();
    if (t == 0) {
        float S = 0.f, SQ = 0.f;
        #pragma unroll
        for (int i = 0; i < 8; i++) { S += ss[i]; SQ += ssq[i]; }
        float mean = S * (1.0f / D);
        float var = SQ * (1.0f / D) - mean * mean;
        mb[0] = mean;
        mb[1] = rsqrtf(var + 1e-3f);
    }
    __syncthreads();
    float mean = mb[0], rstd = mb[1];
    yr[t]       = (v0 - mean) * rstd * gamma[t]       + beta[t];
    yr[t + 256] = (v1 - mean) * rstd * gamma[t + 256] + beta[t + 256];
}

// ---------------- 64x128-tile tf32 GEMM pieces ----------------
struct Proj64Smem {
    float As[2][64][36];
    float Bs[2][32][136];
};

__device__ __forceinline__ void proj64_load(Proj64Smem* S, int buf,
                                            const float* A, const float* W,
                                            int i0, int j0, int kk, int M, int tid) {
    #pragma unroll
    for (int p = 0; p < 2; p++) {
        int idx = p * 256 + tid;
        int r = idx >> 3, c4 = (idx & 7) * 4;
        cpasync16(&S->As[buf][r][c4], &A[(size_t)(i0 + r) * 512 + kk + c4], (i0 + r) < M);
    }
    #pragma unroll
    for (int p = 0; p < 4; p++) {
        int idx = p * 256 + tid;
        int k = idx >> 5, c4 = (idx & 31) * 4;
        cpasync16(&S->Bs[buf][k][c4], &W[(size_t)(kk + k) * 512 + j0 + c4], true);
    }
    asm volatile("cp.async.commit_group;");
}

__device__ __forceinline__ void proj64_core(Proj64Smem* S,
                                            const float* A, const float* W,
                                            int i0, int j0, int M, int tid,
                                            float acc[2][4][4]) {
    int warp = tid >> 5, lane = tid & 31;
    int wy = warp >> 2, wx = warp & 3;
    int g = lane >> 2, q = lane & 3;
    proj64_load(S, 0, A, W, i0, j0, 0, M, tid);
    for (int s = 0; s < 16; s++) {
        if (s < 15) {
            proj64_load(S, (s + 1) & 1, A, W, i0, j0, (s + 1) * 32, M, tid);
            asm volatile("cp.async.wait_group 1;");
        } else {
            asm volatile("cp.async.wait_group 0;");
        }
        __syncthreads();
        int buf = s & 1;
        #pragma unroll
        for (int k8 = 0; k8 < 4; k8++) {
            int kc = k8 * 8 + q;
            unsigned af[2][4], bf[4][2];
            #pragma unroll
            for (int mt = 0; mt < 2; mt++) {
                int r = wy * 32 + mt * 16;
                af[mt][0] = f2tf(S->As[buf][r + g][kc]);
                af[mt][1] = f2tf(S->As[buf][r + g + 8][kc]);
                af[mt][2] = f2tf(S->As[buf][r + g][kc + 4]);
                af[mt][3] = f2tf(S->As[buf][r + g + 8][kc + 4]);
            }
            #pragma unroll
            for (int nt = 0; nt < 4; nt++) {
                int c = wx * 32 + nt * 8 + g;
                bf[nt][0] = f2tf(S->Bs[buf][kc][c]);
                bf[nt][1] = f2tf(S->Bs[buf][kc + 4][c]);
            }
            #pragma unroll
            for (int mt = 0; mt < 2; mt++)
                #pragma unroll
                for (int nt = 0; nt < 4; nt++)
                    mma_tf32(acc[mt][nt], af[mt], bf[nt]);
        }
        __syncthreads();
    }
}

// generic: C = A@W (+bias, +res)
__global__ void __launch_bounds__(256) proj64(
        const float* __restrict__ A, const float* __restrict__ W,
        const float* __restrict__ bias, const float* __restrict__ res,
        float* __restrict__ C, int M) {
    extern __shared__ char raw[];
    Proj64Smem* S = (Proj64Smem*)raw;
    int tid = threadIdx.x;
    int warp = tid >> 5, lane = tid & 31;
    int wy = warp >> 2, wx = warp & 3;
    int g = lane >> 2, q = lane & 3;
    int i0 = blockIdx.y * 64, j0 = blockIdx.x * 128;
    float acc[2][4][4] = {};
    proj64_core(S, A, W, i0, j0, M, tid, acc);
    #pragma unroll
    for (int mt = 0; mt < 2; mt++)
        #pragma unroll
        for (int nt = 0; nt < 4; nt++) {
            int c = j0 + wx * 32 + nt * 8 + q * 2;
            float b0 = bias ? bias[c] : 0.f;
            float b1 = bias ? bias[c + 1] : 0.f;
            #pragma unroll
            for (int half = 0; half < 2; half++) {
                int rr = i0 + wy * 32 + mt * 16 + g + half * 8;
                if (rr >= M) continue;
                float e0 = acc[mt][nt][half * 2 + 0] + b0;
                float e1 = acc[mt][nt][half * 2 + 1] + b1;
                if (res) { e0 += res[(size_t)rr * 512 + c]; e1 += res[(size_t)rr * 512 + c + 1]; }
                *(float2*)&C[(size_t)rr * 512 + c] = make_float2(e0, e1);
            }
        }
}

// fused q/k/v projection; blockIdx.z selects weight; z==0 writes qc AND qp
__global__ void __launch_bounds__(256) qkv_mma(
        const float* __restrict__ Wq, const float* __restrict__ Wk, const float* __restrict__ Wv,
        const float* __restrict__ bq, const float* __restrict__ bk, const float* __restrict__ bv,
        const float* __restrict__ cb, const float* __restrict__ pb) {
    extern __shared__ char raw[];
    Proj64Smem* S = (Proj64Smem*)raw;
    int z = blockIdx.z;
    const float* W    = (z == 0) ? Wq : (z == 1) ? Wk : Wv;
    const float* bias = (z == 0) ? bq : (z == 1) ? bk : bv;
    int tid = threadIdx.x;
    int warp = tid >> 5, lane = tid & 31;
    int wy = warp >> 2, wx = warp & 3;
    int g = lane >> 2, q = lane & 3;
    int i0 = blockIdx.y * 64, j0 = blockIdx.x * 128;
    float acc[2][4][4] = {};
    proj64_core(S, g_y, W, i0, j0, BT, tid, acc);
    float* C1 = (z == 0) ? g_qc : (z == 1) ? g_k : g_v;
    #pragma unroll
    for (int mt = 0; mt < 2; mt++)
        #pragma unroll
        for (int nt = 0; nt < 4; nt++) {
            int c = j0 + wx * 32 + nt * 8 + q * 2;
            float b0 = bias[c], b1 = bias[c + 1];
            #pragma unroll
            for (int half = 0; half < 2; half++) {
                int rr = i0 + wy * 32 + mt * 16 + g + half * 8;
                float e0 = acc[mt][nt][half * 2 + 0] + b0;
                float e1 = acc[mt][nt][half * 2 + 1] + b1;
                if (z == 0) {
                    *(float2*)&C1[(size_t)rr * 512 + c] = make_float2(e0 + cb[c], e1 + cb[c + 1]);
                    *(float2*)&g_qp[(size_t)rr * 512 + c] = make_float2(e0 + pb[c], e1 + pb[c + 1]);
                } else {
                    *(float2*)&C1[(size_t)rr * 512 + c] = make_float2(e0, e1);
                }
            }
        }
}

// ---------------- fused flash attention: 8 warps (4Mx2N), pos ring ----------------
struct FlashSmem {
    unsigned Qc[64][68];        // tf32
    unsigned Qp[64][68];        // tf32
    float Ks[2][64][68];        // raw f32, cp.async double buffer
    float Vs[2][64][68];
    float Ps[2][64][68];
    float R[64][256];           // positional ring, indexed by l & 255
    unsigned Sx[64][68];
    float mrow[64], srow[64], crow[64];
};

// pos chunk GEMM (64 new diagonals): R[:, (cbase+cp)&255] = Qp @ Ps^T
// 8 warps: wy (4) x wx (2); per warp nt=4 over 32 cols
__device__ __forceinline__ void pos_chunk(FlashSmem* S, const float (*P)[68],
                                          int cbase, int wy, int wx, int g, int q) {
    float accP[4][4] = {};
    #pragma unroll
    for (int k8 = 0; k8 < 8; k8++) {
        int kc = k8 * 8 + q;
        int r = wy * 16;
        unsigned ap[4];
        ap[0] = S->Qp[r + g][kc];     ap[1] = S->Qp[r + g + 8][kc];
        ap[2] = S->Qp[r + g][kc + 4]; ap[3] = S->Qp[r + g + 8][kc + 4];
        #pragma unroll
        for (int nt = 0; nt < 4; nt++) {
            int n = wx * 32 + nt * 8 + g;
            unsigned bf[2] = { f2tf(P[n][kc]), f2tf(P[n][kc + 4]) };
            mma_tf32(accP[nt], ap, bf);
        }
    }
    #pragma unroll
    for (int nt = 0; nt < 4; nt++) {
        int cp = wx * 32 + nt * 8 + q * 2;
        int c0 = (cbase + cp) & 255;
        int c1 = (cbase + cp + 1) & 255;
        int r0 = wy * 16 + g;
        S->R[r0][c0] = accP[nt][0];     S->R[r0][c1] = accP[nt][1];
        S->R[r0 + 8][c0] = accP[nt][2]; S->R[r0 + 8][c1] = accP[nt][3];
    }
}

__global__ void __launch_bounds__(256, 1) flash_kernel() {
    extern __shared__ char raw[];
    FlashSmem* S = (FlashSmem*)raw;
    int z = blockIdx.y; int b = z >> 3, h = z & 7;
    int i0 = blockIdx.x * 64;
    int tid = threadIdx.x;
    int warp = tid >> 5, lane = tid & 31;
    int wy = warp >> 1, wx = warp & 1;   // 4(M) x 2(N)
    int g = lane >> 2, q = lane & 3;

    // ---- prologue: Q tiles (converted) + two pos chunks (synchronous) ----
    const float* qcb = g_qc + ((size_t)(b * T + i0)) * D + h * DKK;
    const float* qpb = g_qp + ((size_t)(b * T + i0)) * D + h * DKK;
    #pragma unroll
    for (int p = 0; p < 4; p++) {
        int idx = p * 256 + tid;
        int r = idx >> 4, c4 = (idx & 15) * 4;
        float4 v = *(const float4*)&qcb[(size_t)r * D + c4];
        { uint4 u = { f2tf(v.x), f2tf(v.y), f2tf(v.z), f2tf(v.w) }; *(uint4*)&S->Qc[r][c4] = u; }
        v = *(const float4*)&qpb[(size_t)r * D + c4];
        { uint4 u = { f2tf(v.x), f2tf(v.y), f2tf(v.z), f2tf(v.w) }; *(uint4*)&S->Qp[r][c4] = u; }
        int l0 = 960 - i0 + r;  l0 = min(max(l0, 0), LL - 1);
        int l1 = 1024 - i0 + r; l1 = min(max(l1, 0), LL - 1);
        *(float4*)&S->Ps[0][r][c4] = *(const float4*)&g_p[((size_t)(b * LL + l0)) * D + h * DKK + c4];
        *(float4*)&S->Ps[1][r][c4] = *(const float4*)&g_p[((size_t)(b * LL + l1)) * D + h * DKK + c4];
    }
    if (tid < 64) { S->mrow[tid] = -1e30f; S->srow[tid] = 0.f; }
    float accO[4][4] = {};
    __syncthreads();

    pos_chunk(S, S->Ps[0], 960 - i0, wy, wx, g, q);
    pos_chunk(S, S->Ps[1], 1024 - i0, wy, wx, g, q);
    __syncthreads();

    // prefetch jt=0 tiles (K, V, and P chunk 1088-i0) into stage 0
    {
        const float* kb = g_k + ((size_t)(b * T)) * D + h * DKK;
        const float* vb = g_v + ((size_t)(b * T)) * D + h * DKK;
        #pragma unroll
        for (int p = 0; p < 4; p++) {
            int idx = p * 256 + tid;
            int r = idx >> 4, c4 = (idx & 15) * 4;
            cpasync16(&S->Ks[0][r][c4], &kb[(size_t)r * D + c4], true);
            cpasync16(&S->Vs[0][r][c4], &vb[(size_t)r * D + c4], true);
            int l = 1088 - i0 + r; l = min(max(l, 0), LL - 1);
            cpasync16(&S->Ps[0][r][c4], &g_p[((size_t)(b * LL + l)) * D + h * DKK + c4], true);
        }
        asm volatile("cp.async.commit_group;");
    }

    for (int jt = 0; jt < 16; jt++) {
        asm volatile("cp.async.wait_group 0;");
        __syncthreads();
        int st = jt & 1;
        // prefetch jt+1
        if (jt < 15) {
            int st2 = (jt + 1) & 1;
            const float* kb = g_k + ((size_t)(b * T + (jt + 1) * 64)) * D + h * DKK;
            const float* vb = g_v + ((size_t)(b * T + (jt + 1) * 64)) * D + h * DKK;
            #pragma unroll
            for (int p = 0; p < 4; p++) {
                int idx = p * 256 + tid;
                int r = idx >> 4, c4 = (idx & 15) * 4;
                cpasync16(&S->Ks[st2][r][c4], &kb[(size_t)r * D + c4], true);
                cpasync16(&S->Vs[st2][r][c4], &vb[(size_t)r * D + c4], true);
                int l = 1088 + 64 * (jt + 1) - i0 + r; l = min(max(l, 0), LL - 1);
                cpasync16(&S->Ps[st2][r][c4], &g_p[((size_t)(b * LL + l)) * D + h * DKK + c4], true);
            }
            asm volatile("cp.async.commit_group;");
        }

        // content MMA (warp tile 16 x 32)
        float accC[4][4] = {};
        #pragma unroll
        for (int k8 = 0; k8 < 8; k8++) {
            int kc = k8 * 8 + q;
            int r = wy * 16;
            unsigned ac[4];
            ac[0] = S->Qc[r + g][kc];     ac[1] = S->Qc[r + g + 8][kc];
            ac[2] = S->Qc[r + g][kc + 4]; ac[3] = S->Qc[r + g + 8][kc + 4];
            #pragma unroll
            for (int nt = 0; nt < 4; nt++) {
                int n = wx * 32 + nt * 8 + g;
                unsigned bf[2] = { f2tf(S->Ks[st][n][kc]), f2tf(S->Ks[st][n][kc + 4]) };
                mma_tf32(accC[nt], ac, bf);
            }
        }
        // pos chunk for window jt+1 (ring slots disjoint from this window's reads)
        if (jt < 15)
            pos_chunk(S, S->Ps[st], 1088 + 64 * jt - i0, wy, wx, g, q);

        // combine content + shifted positional -> Sx (scaled)
        int base = 1024 + 64 * jt - i0;
        #pragma unroll
        for (int nt = 0; nt < 4; nt++) {
            int jl = wx * 32 + nt * 8 + q * 2;
            #pragma unroll
            for (int half = 0; half < 2; half++) {
                int il = wy * 16 + g + half * 8;
                int c0 = (base + jl - il) & 255;
                int c1 = (base + jl + 1 - il) & 255;
                S->Sx[il][jl]     = __float_as_uint((accC[nt][half * 2 + 0] + S->R[il][c0]) * 0.125f);
                S->Sx[il][jl + 1] = __float_as_uint((accC[nt][half * 2 + 1] + S->R[il][c1]) * 0.125f);
            }
        }
        // rel_shift wraparound: (i=0, j=1023) -> dot(qp[1], p[0])
        if (i0 == 0 && jt == 15) {
            __syncthreads();
            if (tid < 32) {
                float a0 = g_qp[((size_t)(b * T + 1)) * D + h * DKK + lane];
                float a1 = g_qp[((size_t)(b * T + 1)) * D + h * DKK + lane + 32];
                float p0 = g_p[((size_t)(b * LL)) * D + h * DKK + lane];
                float p1 = g_p[((size_t)(b * LL)) * D + h * DKK + lane + 32];
                float sdot = a0 * p0 + a1 * p1;
                #pragma unroll
                for (int o = 16; o > 0; o >>= 1)
                    sdot += __shfl_xor_sync(0xFFFFFFFFu, sdot, o);
                if (lane == 0) {
                    float old = __uint_as_float(S->Sx[0][63]);
                    S->Sx[0][63] = __float_as_uint(old + 0.125f * (sdot - S->R[0][255]));
                }
            }
        }
        __syncthreads();

        // online softmax: 4 threads per row, 16 vals each
        {
            int row = tid >> 2, seg = tid & 3;
            float vals[16];
            float tmax = -1e30f;
            #pragma unroll
            for (int i = 0; i < 16; i++) {
                vals[i] = __uint_as_float(S->Sx[row][seg * 16 + i]);
                tmax = fmaxf(tmax, vals[i]);
            }
            tmax = fmaxf(tmax, __shfl_xor_sync(0xFFFFFFFFu, tmax, 1));
            tmax = fmaxf(tmax, __shfl_xor_sync(0xFFFFFFFFu, tmax, 2));
            float mold = S->mrow[row];
            float mnew = fmaxf(mold, tmax);
            float corr = __expf(mold - mnew);
            float sum = 0.f;
            #pragma unroll
            for (int i = 0; i < 16; i++) {
                float e = __expf(vals[i] - mnew);
                sum += e;
                S->Sx[row][seg * 16 + i] = f2tf(e);
            }
            sum += __shfl_xor_sync(0xFFFFFFFFu, sum, 1);
            sum += __shfl_xor_sync(0xFFFFFFFFu, sum, 2);
            if (seg == 0) {
                S->mrow[row] = mnew;
                S->srow[row] = S->srow[row] * corr + sum;
                S->crow[row] = corr;
            }
        }
        __syncthreads();

        // AV accumulate (rescale first); warp tile 16 x 32 over DK=64
        {
            float c0 = S->crow[wy * 16 + g];
            float c1 = S->crow[wy * 16 + g + 8];
            #pragma unroll
            for (int nt = 0; nt < 4; nt++) {
                accO[nt][0] *= c0; accO[nt][1] *= c0;
                accO[nt][2] *= c1; accO[nt][3] *= c1;
            }
            #pragma unroll
            for (int k8 = 0; k8 < 8; k8++) {
                int kc = k8 * 8 + q;
                int r = wy * 16;
                unsigned a[4];
                a[0] = S->Sx[r + g][kc];     a[1] = S->Sx[r + g + 8][kc];
                a[2] = S->Sx[r + g][kc + 4]; a[3] = S->Sx[r + g + 8][kc + 4];
                #pragma unroll
                for (int nt = 0; nt < 4; nt++) {
                    int n = wx * 32 + nt * 8 + g;
                    unsigned bf[2] = { f2tf(S->Vs[st][kc][n]), f2tf(S->Vs[st][kc + 4][n]) };
                    mma_tf32(accO[nt], a, bf);
                }
            }
        }
    }
    // finalize
    float inv0 = 1.f / S->srow[wy * 16 + g];
    float inv1 = 1.f / S->srow[wy * 16 + g + 8];
    #pragma unroll
    for (int nt = 0; nt < 4; nt++) {
        int col = h * DKK + wx * 32 + nt * 8 + q * 2;
        int r0 = i0 + wy * 16 + g;
        *(float2*)&g_o[((size_t)(b * T + r0)) * D + col] =
            make_float2(accO[nt][0] * inv0, accO[nt][1] * inv0);
        *(float2*)&g_o[((size_t)(b * T + r0 + 8)) * D + col] =
            make_float2(accO[nt][2] * inv1, accO[nt][3] * inv1);
    }
}

extern "C" void kernel_launch(void* const* d_in, const int* in_sizes, int n_in,
                              void* d_out, int out_size) {
    const float* x     = (const float*)d_in[0];
    const float* pos   = (const float*)d_in[1];
    const float* cb    = (const float*)d_in[2];
    const float* pb    = (const float*)d_in[3];
    const float* gamma = (const float*)d_in[4];
    const float* beta  = (const float*)d_in[5];
    const float* Wq    = (const float*)d_in[6];
    const float* bq    = (const float*)d_in[7];
    const float* Wk    = (const float*)d_in[8];
    const float* bk    = (const float*)d_in[9];
    const float* Wv    = (const float*)d_in[10];
    const float* bv    = (const float*)d_in[11];
    const float* Wp    = (const float*)d_in[12];
    const float* Wo    = (const float*)d_in[13];
    const float* bo    = (const float*)d_in[14];
    float* out = (float*)d_out;

    float *p, *o;
    cudaGetSymbolAddress((void**)&p, g_p);
    cudaGetSymbolAddress((void**)&o, g_o);

    cudaFuncSetAttribute(proj64, cudaFuncAttributeMaxDynamicSharedMemorySize,
                         (int)sizeof(Proj64Smem));
    cudaFuncSetAttribute(qkv_mma, cudaFuncAttributeMaxDynamicSharedMemorySize,
                         (int)sizeof(Proj64Smem));
    cudaFuncSetAttribute(flash_kernel, cudaFuncAttributeMaxDynamicSharedMemorySize,
                         (int)sizeof(FlashSmem));

    // 1. LayerNorm
    ln_kernel<<<BT, 256>>>(x, gamma, beta);

    // 2. projections: fused q/k/v (grid.z) + positional
    qkv_mma<<<dim3(4, 64, 3), 256, sizeof(Proj64Smem)>>>(Wq, Wk, Wv, bq, bk, bv, cb, pb);
    proj64<<<dim3(4, 128), 256, sizeof(Proj64Smem)>>>(pos, Wp, nullptr, nullptr, p, BL);

    // 3-5. fused flash attention (content + rel-shift pos + softmax + AV)
    flash_kernel<<<dim3(16, 32), 256, sizeof(FlashSmem)>>>();

    // 6. output projection + bias + residual
    proj64<<<dim3(4, 64), 256, sizeof(Proj64Smem)>>>(o, Wo, bo, x, out, BT);
}

// round 6
// speedup vs baseline: 1.5586x; 1.4802x over previous
#include <cuda_runtime.h>
#include <cuda_bf16.h>
#include <math.h>

#define BB 4
#define T 1024
#define D 512
#define H 8
#define LL 2047
#define BT (BB*T)      // 4096
#define BL (BB*LL)     // 8188

__device__ float g_y[BT*D];
__device__ float g_q[BT*D];    // q + bq (raw f32)
__device__ float g_k[BT*D];    // tf32-rounded
__device__ float g_v[BT*D];    // tf32-rounded
__device__ float g_p[BL*D];    // tf32-rounded
__device__ float g_o[BT*D];
__device__ float g_fixv[BB*H];

// ---------------- helpers ----------------
__device__ __forceinline__ unsigned f2tf(float f) {
    unsigned u; asm("cvt.rna.tf32.f32 %0, %1;" : "=r"(u) : "f"(f)); return u;
}
__device__ __forceinline__ void mma_tf32(float d[4], const unsigned a[4], const unsigned b[2]) {
    asm volatile("mma.sync.aligned.m16n8k8.row.col.f32.tf32.tf32.f32 "
        "{%0,%1,%2,%3},{%4,%5,%6,%7},{%8,%9},{%0,%1,%2,%3};\n"
        : "+f"(d[0]), "+f"(d[1]), "+f"(d[2]), "+f"(d[3])
        : "r"(a[0]), "r"(a[1]), "r"(a[2]), "r"(a[3]), "r"(b[0]), "r"(b[1]));
}
__device__ __forceinline__ void cpasync16(void* dst, const void* src, bool pred) {
    unsigned d = (unsigned)__cvta_generic_to_shared(dst);
    int sz = pred ? 16 : 0;
    asm volatile("cp.async.cg.shared.global [%0], [%1], 16, %2;\n"
                 :: "r"(d), "l"(src), "r"(sz));
}

// ---------------- LayerNorm ----------------
__global__ void ln_kernel(const float* __restrict__ x,
                          const float* __restrict__ gamma,
                          const float* __restrict__ beta) {
    int row = blockIdx.x;
    const float* xr = x + (size_t)row * D;
    float* yr = g_y + (size_t)row * D;
    int t = threadIdx.x;  // 256
    float v0 = xr[t], v1 = xr[t + 256];
    float s = v0 + v1, sq = v0 * v0 + v1 * v1;
    __shared__ float ss[8], ssq[8], mb[2];
    #pragma unroll
    for (int o = 16; o > 0; o >>= 1) {
        s  += __shfl_xor_sync(0xFFFFFFFFu, s, o);
        sq += __shfl_xor_sync(0xFFFFFFFFu, sq, o);
    }
    if ((t & 31) == 0) { ss[t >> 5] = s; ssq[t >> 5] = sq; }
    __syncthreads();
    if (t == 0) {
        float S = 0.f, SQ = 0.f;
        #pragma unroll
        for (int i = 0; i < 8; i++) { S += ss[i]; SQ += ssq[i]; }
        float mean = S * (1.0f / D);
        float var = SQ * (1.0f / D) - mean * mean;
        mb[0] = mean;
        mb[1] = rsqrtf(var + 1e-3f);
    }
    __syncthreads();
    float mean = mb[0], rstd = mb[1];
    yr[t]       = (v0 - mean) * rstd * gamma[t]       + beta[t];
    yr[t + 256] = (v1 - mean) * rstd * gamma[t + 256] + beta[t + 256];
}

// ---------------- 64x128-tile tf32 GEMM ----------------
struct Proj64Smem {
    float As[2][64][36];
    float Bs[2][32][136];
};

__device__ __forceinline__ void proj64_load(Proj64Smem* S, int buf,
                                            const float* A, const float* W,
                                            int i0, int j0, int kk, int M, int tid) {
    #pragma unroll
    for (int p = 0; p < 2; p++) {
        int idx = p * 256 + tid;
        int r = idx >> 3, c4 = (idx & 7) * 4;
        cpasync16(&S->As[buf][r][c4], &A[(size_t)(i0 + r) * 512 + kk + c4], (i0 + r) < M);
    }
    #pragma unroll
    for (int p = 0; p < 4; p++) {
        int idx = p * 256 + tid;
        int k = idx >> 5, c4 = (idx & 31) * 4;
        cpasync16(&S->Bs[buf][k][c4], &W[(size_t)(kk + k) * 512 + j0 + c4], true);
    }
    asm volatile("cp.async.commit_group;");
}

__device__ __forceinline__ void proj64_core(Proj64Smem* S,
                                            const float* A, const float* W,
                                            int i0, int j0, int M, int tid,
                                            float acc[2][4][4]) {
    int warp = tid >> 5, lane = tid & 31;
    int wy = warp >> 2, wx = warp & 3;
    int g = lane >> 2, q = lane & 3;
    proj64_load(S, 0, A, W, i0, j0, 0, M, tid);
    for (int s = 0; s < 16; s++) {
        if (s < 15) {
            proj64_load(S, (s + 1) & 1, A, W, i0, j0, (s + 1) * 32, M, tid);
            asm volatile("cp.async.wait_group 1;");
        } else {
            asm volatile("cp.async.wait_group 0;");
        }
        __syncthreads();
        int buf = s & 1;
        #pragma unroll
        for (int k8 = 0; k8 < 4; k8++) {
            int kc = k8 * 8 + q;
            unsigned af[2][4], bf[4][2];
            #pragma unroll
            for (int mt = 0; mt < 2; mt++) {
                int r = wy * 32 + mt * 16;
                af[mt][0] = f2tf(S->As[buf][r + g][kc]);
                af[mt][1] = f2tf(S->As[buf][r + g + 8][kc]);
                af[mt][2] = f2tf(S->As[buf][r + g][kc + 4]);
                af[mt][3] = f2tf(S->As[buf][r + g + 8][kc + 4]);
            }
            #pragma unroll
            for (int nt = 0; nt < 4; nt++) {
                int c = wx * 32 + nt * 8 + g;
                bf[nt][0] = f2tf(S->Bs[buf][kc][c]);
                bf[nt][1] = f2tf(S->Bs[buf][kc + 4][c]);
            }
            #pragma unroll
            for (int mt = 0; mt < 2; mt++)
                #pragma unroll
                for (int nt = 0; nt < 4; nt++)
                    mma_tf32(acc[mt][nt], af[mt], bf[nt]);
        }
        __syncthreads();
    }
}

// generic: C = A@W (+bias, +res); rnd: tf32-round outputs
__global__ void __launch_bounds__(256) proj64(
        const float* __restrict__ A, const float* __restrict__ W,
        const float* __restrict__ bias, const float* __restrict__ res,
        float* __restrict__ C, int M, int rnd) {
    extern __shared__ char raw[];
    Proj64Smem* S = (Proj64Smem*)raw;
    int tid = threadIdx.x;
    int warp = tid >> 5, lane = tid & 31;
    int wy = warp >> 2, wx = warp & 3;
    int g = lane >> 2, q = lane & 3;
    int i0 = blockIdx.y * 64, j0 = blockIdx.x * 128;
    float acc[2][4][4] = {};
    proj64_core(S, A, W, i0, j0, M, tid, acc);
    #pragma unroll
    for (int mt = 0; mt < 2; mt++)
        #pragma unroll
        for (int nt = 0; nt < 4; nt++) {
            int c = j0 + wx * 32 + nt * 8 + q * 2;
            float b0 = bias ? bias[c] : 0.f;
            float b1 = bias ? bias[c + 1] : 0.f;
            #pragma unroll
            for (int half = 0; half < 2; half++) {
                int rr = i0 + wy * 32 + mt * 16 + g + half * 8;
                if (rr >= M) continue;
                float e0 = acc[mt][nt][half * 2 + 0] + b0;
                float e1 = acc[mt][nt][half * 2 + 1] + b1;
                if (res) { e0 += res[(size_t)rr * 512 + c]; e1 += res[(size_t)rr * 512 + c + 1]; }
                if (rnd) { e0 = __uint_as_float(f2tf(e0)); e1 = __uint_as_float(f2tf(e1)); }
                *(float2*)&C[(size_t)rr * 512 + c] = make_float2(e0, e1);
            }
        }
}

// fused q/k/v projection; z=0 -> g_q raw; z=1 -> g_k rounded; z=2 -> g_v rounded
__global__ void __launch_bounds__(256) qkv_mma(
        const float* __restrict__ Wq, const float* __restrict__ Wk, const float* __restrict__ Wv,
        const float* __restrict__ bq, const float* __restrict__ bk, const float* __restrict__ bv) {
    extern __shared__ char raw[];
    Proj64Smem* S = (Proj64Smem*)raw;
    int z = blockIdx.z;
    const float* W    = (z == 0) ? Wq : (z == 1) ? Wk : Wv;
    const float* bias = (z == 0) ? bq : (z == 1) ? bk : bv;
    float* C = (z == 0) ? g_q : (z == 1) ? g_k : g_v;
    int tid = threadIdx.x;
    int warp = tid >> 5, lane = tid & 31;
    int wy = warp >> 2, wx = warp & 3;
    int g = lane >> 2, q = lane & 3;
    int i0 = blockIdx.y * 64, j0 = blockIdx.x * 128;
    float acc[2][4][4] = {};
    proj64_core(S, g_y, W, i0, j0, BT, tid, acc);
    #pragma unroll
    for (int mt = 0; mt < 2; mt++)
        #pragma unroll
        for (int nt = 0; nt < 4; nt++) {
            int c = j0 + wx * 32 + nt * 8 + q * 2;
            float b0 = bias[c], b1 = bias[c + 1];
            #pragma unroll
            for (int half = 0; half < 2; half++) {
                int rr = i0 + wy * 32 + mt * 16 + g + half * 8;
                float e0 = acc[mt][nt][half * 2 + 0] + b0;
                float e1 = acc[mt][nt][half * 2 + 1] + b1;
                if (z != 0) { e0 = __uint_as_float(f2tf(e0)); e1 = __uint_as_float(f2tf(e1)); }
                *(float2*)&C[(size_t)rr * 512 + c] = make_float2(e0, e1);
            }
        }
}

// rel_shift wraparound value: g_fixv[z] = dot(tf32(q[b,1,h]+pb), p[b,0,h])
__global__ void fix_kernel(const float* __restrict__ pb) {
    int z = blockIdx.x; int b = z >> 3, h = z & 7;
    int t = threadIdx.x;  // 32
    float a0 = g_q[((size_t)(b * T + 1)) * D + h * 64 + t]      + pb[h * 64 + t];
    float a1 = g_q[((size_t)(b * T + 1)) * D + h * 64 + t + 32] + pb[h * 64 + t + 32];
    float p0 = g_p[((size_t)(b * LL)) * D + h * 64 + t];
    float p1 = g_p[((size_t)(b * LL)) * D + h * 64 + t + 32];
    float s = __uint_as_float(f2tf(a0)) * p0 + __uint_as_float(f2tf(a1)) * p1;
    #pragma unroll
    for (int o = 16; o > 0; o >>= 1) s += __shfl_xor_sync(0xFFFFFFFFu, s, o);
    if (t == 0) g_fixv[z] = s;
}

// ---------------- flash attention: FA2-style, warp-owns-rows, no-max softmax ----------------
struct FlashSmem {
    float Qs[128][68];           // raw q+bq
    float Ks[2][64][68];         // tf32-rounded f32
    float Vs[2][64][68];
    float Ps[2][64][68];
    __nv_bfloat16 R[128][264];   // positional ring, slot = l & 255
    float cbS[64], pbS[64];
};

__device__ __forceinline__ void pos_chunk(FlashSmem* S, const float (*P)[68],
                                          int cbase, const unsigned (*apf)[4],
                                          int row0, int g, int q) {
    float accP[8][4] = {};
    #pragma unroll
    for (int k8 = 0; k8 < 8; k8++) {
        int kc = k8 * 8 + q;
        #pragma unroll
        for (int nt = 0; nt < 8; nt++) {
            int n = nt * 8 + g;
            unsigned bf[2] = { __float_as_uint(P[n][kc]), __float_as_uint(P[n][kc + 4]) };
            mma_tf32(accP[nt], apf[k8], bf);
        }
    }
    #pragma unroll
    for (int nt = 0; nt < 8; nt++) {
        int s0 = (cbase + nt * 8 + 2 * q) & 255;   // cbase % 64 == 0 -> no wrap inside pair
        *(__nv_bfloat162*)&S->R[row0][s0]     = __floats2bfloat162_rn(accP[nt][0], accP[nt][1]);
        *(__nv_bfloat162*)&S->R[row0 + 8][s0] = __floats2bfloat162_rn(accP[nt][2], accP[nt][3]);
    }
}

__global__ void __launch_bounds__(256, 1) flash_kernel(const float* __restrict__ cb,
                                                       const float* __restrict__ pb) {
    extern __shared__ char raw[];
    FlashSmem* S = (FlashSmem*)raw;
    int z = blockIdx.y; int b = z >> 3, h = z & 7;
    int i0 = blockIdx.x * 128;
    int tid = threadIdx.x;
    int warp = tid >> 5, lane = tid & 31;
    int g = lane >> 2, q = lane & 3;
    int row0 = warp * 16 + g;
    const int base0 = 1024 - i0 - 128;   // >= 0 (i0 <= 896), multiple of 64

    // ---- prologue: Q tile + biases + first pos chunk buffer ----
    #pragma unroll
    for (int p = 0; p < 8; p++) {
        int idx = p * 256 + tid;
        int r = idx >> 4, c4 = (idx & 15) * 4;
        *(float4*)&S->Qs[r][c4] =
            *(const float4*)&g_q[((size_t)(b * T + i0 + r)) * D + h * 64 + c4];
    }
    if (tid < 16) {
        *(float4*)&S->cbS[tid * 4] = *(const float4*)&cb[h * 64 + tid * 4];
        *(float4*)&S->pbS[tid * 4] = *(const float4*)&pb[h * 64 + tid * 4];
    }
    #pragma unroll
    for (int p = 0; p < 4; p++) {
        int idx = p * 256 + tid;
        int r = idx >> 4, c4 = (idx & 15) * 4;
        int l = base0 + r; l = min(max(l, 0), LL - 1);
        *(float4*)&S->Ps[0][r][c4] =
            *(const float4*)&g_p[((size_t)(b * LL + l)) * D + h * 64 + c4];
    }
    __syncthreads();

    // build persistent Q fragments (tf32), content + positional variants
    unsigned acf[8][4], apf[8][4];
    #pragma unroll
    for (int k8 = 0; k8 < 8; k8++) {
        int kc = k8 * 8 + q;
        float q0 = S->Qs[row0][kc],     q1 = S->Qs[row0 + 8][kc];
        float q2 = S->Qs[row0][kc + 4], q3 = S->Qs[row0 + 8][kc + 4];
        float c0 = S->cbS[kc], c4v = S->cbS[kc + 4];
        float p0 = S->pbS[kc], p4v = S->pbS[kc + 4];
        acf[k8][0] = f2tf(q0 + c0);  acf[k8][1] = f2tf(q1 + c0);
        acf[k8][2] = f2tf(q2 + c4v); acf[k8][3] = f2tf(q3 + c4v);
        apf[k8][0] = f2tf(q0 + p0);  apf[k8][1] = f2tf(q1 + p0);
        apf[k8][2] = f2tf(q2 + p4v); apf[k8][3] = f2tf(q3 + p4v);
    }

    // prologue pos chunks c0, c1, c2 (fill ring for window jt=0)
    pos_chunk(S, S->Ps[0], base0, apf, row0, g, q);
    #pragma unroll
    for (int p = 0; p < 4; p++) {
        int idx = p * 256 + tid;
        int r = idx >> 4, c4 = (idx & 15) * 4;
        int l = base0 + 64 + r; l = min(max(l, 0), LL - 1);
        *(float4*)&S->Ps[1][r][c4] =
            *(const float4*)&g_p[((size_t)(b * LL + l)) * D + h * 64 + c4];
    }
    __syncthreads();
    pos_chunk(S, S->Ps[1], base0 + 64, apf, row0, g, q);
    #pragma unroll
    for (int p = 0; p < 4; p++) {
        int idx = p * 256 + tid;
        int r = idx >> 4, c4 = (idx & 15) * 4;
        int l = base0 + 128 + r; l = min(max(l, 0), LL - 1);
        *(float4*)&S->Ps[0][r][c4] =
            *(const float4*)&g_p[((size_t)(b * LL + l)) * D + h * 64 + c4];
    }
    __syncthreads();
    pos_chunk(S, S->Ps[0], base0 + 128, apf, row0, g, q);
    __syncthreads();   // protect Ps[0] before prefetch overwrites it

    // prefetch jt=0: K, V tiles + P chunk (base0+192) into stage 0
    {
        const float* kb = g_k + ((size_t)(b * T)) * D + h * 64;
        const float* vb = g_v + ((size_t)(b * T)) * D + h * 64;
        #pragma unroll
        for (int p = 0; p < 4; p++) {
            int idx = p * 256 + tid;
            int r = idx >> 4, c4 = (idx & 15) * 4;
            cpasync16(&S->Ks[0][r][c4], &kb[(size_t)r * D + c4], true);
            cpasync16(&S->Vs[0][r][c4], &vb[(size_t)r * D + c4], true);
            int l = base0 + 192 + r; l = min(max(l, 0), LL - 1);
            cpasync16(&S->Ps[0][r][c4], &g_p[((size_t)(b * LL + l)) * D + h * 64 + c4], true);
        }
        asm volatile("cp.async.commit_group;");
    }

    float accO[8][4] = {};
    float sumA = 0.f, sumB = 0.f;
    float gfixv = g_fixv[z];
    int srcA = (lane & 28) | (q >> 1);
    int srcB = srcA | 2;
    bool odd = (q & 1);

    for (int jt = 0; jt < 16; jt++) {
        asm volatile("cp.async.wait_group 0;");
        __syncthreads();
        int st = jt & 1;
        if (jt < 15) {
            int st2 = st ^ 1;
            const float* kb = g_k + ((size_t)(b * T + (jt + 1) * 64)) * D + h * 64;
            const float* vb = g_v + ((size_t)(b * T + (jt + 1) * 64)) * D + h * 64;
            #pragma unroll
            for (int p = 0; p < 4; p++) {
                int idx = p * 256 + tid;
                int r = idx >> 4, c4 = (idx & 15) * 4;
                cpasync16(&S->Ks[st2][r][c4], &kb[(size_t)r * D + c4], true);
                cpasync16(&S->Vs[st2][r][c4], &vb[(size_t)r * D + c4], true);
                int l = base0 + 192 + 64 * (jt + 1) + r; l = min(max(l, 0), LL - 1);
                cpasync16(&S->Ps[st2][r][c4], &g_p[((size_t)(b * LL + l)) * D + h * 64 + c4], true);
            }
            asm volatile("cp.async.commit_group;");
        }

        // content scores (warp tile 16 x 64, registers)
        float accC[8][4] = {};
        #pragma unroll
        for (int k8 = 0; k8 < 8; k8++) {
            int kc = k8 * 8 + q;
            #pragma unroll
            for (int nt = 0; nt < 8; nt++) {
                int n = nt * 8 + g;
                unsigned bf[2] = { __float_as_uint(S->Ks[st][n][kc]),
                                   __float_as_uint(S->Ks[st][n][kc + 4]) };
                mma_tf32(accC[nt], acf[k8], bf);
            }
        }
        // pos chunk serving window jt+1
        if (jt < 15)
            pos_chunk(S, S->Ps[st], base0 + 192 + 64 * jt, apf, row0, g, q);

        // combine + exp (no max-subtraction; logits bounded) + AV
        int basew = 1024 + 64 * jt - i0;
        bool fixc = (i0 == 0) && (jt == 15) && (warp == 0) && (g == 0) && (q == 3);
        #pragma unroll
        for (int nt = 0; nt < 8; nt++) {
            int jl = nt * 8 + 2 * q;
            int il0 = row0, il1 = row0 + 8;
            float r00 = __bfloat162float(S->R[il0][(basew + jl - il0) & 255]);
            float r01 = __bfloat162float(S->R[il0][(basew + jl + 1 - il0) & 255]);
            float r10 = __bfloat162float(S->R[il1][(basew + jl - il1) & 255]);
            float r11 = __bfloat162float(S->R[il1][(basew + jl + 1 - il1) & 255]);
            if (fixc && nt == 7) r01 = gfixv;   // rel_shift wraparound (i=0, j=1023)
            float e0 = __expf((accC[nt][0] + r00) * 0.125f);
            float e1 = __expf((accC[nt][1] + r01) * 0.125f);
            float e2 = __expf((accC[nt][2] + r10) * 0.125f);
            float e3 = __expf((accC[nt][3] + r11) * 0.125f);
            sumA += e0 + e1; sumB += e2 + e3;
            // redistribute to tf32 A-fragment layout via quad shuffles
            float s0 = __shfl_sync(0xFFFFFFFFu, e0, srcA);
            float s1 = __shfl_sync(0xFFFFFFFFu, e1, srcA);
            float s2 = __shfl_sync(0xFFFFFFFFu, e2, srcA);
            float s3 = __shfl_sync(0xFFFFFFFFu, e3, srcA);
            float t0 = __shfl_sync(0xFFFFFFFFu, e0, srcB);
            float t1 = __shfl_sync(0xFFFFFFFFu, e1, srcB);
            float t2 = __shfl_sync(0xFFFFFFFFu, e2, srcB);
            float t3 = __shfl_sync(0xFFFFFFFFu, e3, srcB);
            unsigned a[4];
            a[0] = f2tf(odd ? s1 : s0);   // (g,   key q)
            a[1] = f2tf(odd ? s3 : s2);   // (g+8, key q)
            a[2] = f2tf(odd ? t1 : t0);   // (g,   key q+4)
            a[3] = f2tf(odd ? t3 : t2);   // (g+8, key q+4)
            int kcv = nt * 8 + q;
            #pragma unroll
            for (int n2 = 0; n2 < 8; n2++) {
                int n = n2 * 8 + g;
                unsigned bf[2] = { __float_as_uint(S->Vs[st][kcv][n]),
                                   __float_as_uint(S->Vs[st][kcv + 4][n]) };
                mma_tf32(accO[n2], a, bf);
            }
        }
    }

    // finalize: row sums across quad, normalize, write
    sumA += __shfl_xor_sync(0xFFFFFFFFu, sumA, 1);
    sumA += __shfl_xor_sync(0xFFFFFFFFu, sumA, 2);
    sumB += __shfl_xor_sync(0xFFFFFFFFu, sumB, 1);
    sumB += __shfl_xor_sync(0xFFFFFFFFu, sumB, 2);
    float invA = 1.f / sumA, invB = 1.f / sumB;
    #pragma unroll
    for (int n2 = 0; n2 < 8; n2++) {
        int col = h * 64 + n2 * 8 + 2 * q;
        size_t r = (size_t)(b * T + i0 + row0);
        *(float2*)&g_o[r * D + col] =
            make_float2(accO[n2][0] * invA, accO[n2][1] * invA);
        *(float2*)&g_o[(r + 8) * D + col] =
            make_float2(accO[n2][2] * invB, accO[n2][3] * invB);
    }
}

extern "C" void kernel_launch(void* const* d_in, const int* in_sizes, int n_in,
                              void* d_out, int out_size) {
    const float* x     = (const float*)d_in[0];
    const float* pos   = (const float*)d_in[1];
    const float* cb    = (const float*)d_in[2];
    const float* pb    = (const float*)d_in[3];
    const float* gamma = (const float*)d_in[4];
    const float* beta  = (const float*)d_in[5];
    const float* Wq    = (const float*)d_in[6];
    const float* bq    = (const float*)d_in[7];
    const float* Wk    = (const float*)d_in[8];
    const float* bk    = (const float*)d_in[9];
    const float* Wv    = (const float*)d_in[10];
    const float* bv    = (const float*)d_in[11];
    const float* Wp    = (const float*)d_in[12];
    const float* Wo    = (const float*)d_in[13];
    const float* bo    = (const float*)d_in[14];
    float* out = (float*)d_out;

    float *p, *o;
    cudaGetSymbolAddress((void**)&p, g_p);
    cudaGetSymbolAddress((void**)&o, g_o);

    cudaFuncSetAttribute(proj64, cudaFuncAttributeMaxDynamicSharedMemorySize,
                         (int)sizeof(Proj64Smem));
    cudaFuncSetAttribute(qkv_mma, cudaFuncAttributeMaxDynamicSharedMemorySize,
                         (int)sizeof(Proj64Smem));
    cudaFuncSetAttribute(flash_kernel, cudaFuncAttributeMaxDynamicSharedMemorySize,
                         (int)sizeof(FlashSmem));

    // 1. LayerNorm
    ln_kernel<<<BT, 256>>>(x, gamma, beta);

    // 2. projections: fused q/k/v (grid.z; k,v tf32-rounded) + positional (rounded)
    qkv_mma<<<dim3(4, 64, 3), 256, sizeof(Proj64Smem)>>>(Wq, Wk, Wv, bq, bk, bv);
    proj64<<<dim3(4, 128), 256, sizeof(Proj64Smem)>>>(pos, Wp, nullptr, nullptr, p, BL, 1);

    // 3. wraparound fix value
    fix_kernel<<<BB * H, 32>>>(pb);

    // 4. fused flash attention (content + rel-shift pos + softmax + AV)
    flash_kernel<<<dim3(8, 32), 256, sizeof(FlashSmem)>>>(cb, pb);

    // 5. output projection + bias + residual (no rounding)
    proj64<<<dim3(4, 64), 256, sizeof(Proj64Smem)>>>(o, Wo, bo, x, out, BT, 0);
}

// round 7
// speedup vs baseline: 1.9468x; 1.2491x over previous
#include <cuda_runtime.h>
#include <cuda_bf16.h>
#include <math.h>

#define BB 4
#define T 1024
#define D 512
#define H 8
#define LL 2047
#define BT (BB*T)      // 4096
#define BL (BB*LL)     // 8188

__device__ float g_y[BT*D];
__device__ float g_q[BT*D];    // q + bq (raw f32)
__device__ float g_v[BT*D];    // f32 (pre-transpose)
__device__ float g_o[BT*D];
__device__ __nv_bfloat16 g_kb[BT*D];
__device__ __nv_bfloat16 g_pb[(size_t)BL*D];
__device__ __nv_bfloat16 g_vt[(size_t)BB*H*64*1024];  // [b*H+h][d][j]
__device__ float g_fixv[BB*H];

// ---------------- helpers ----------------
__device__ __forceinline__ unsigned f2tf(float f) {
    unsigned u; asm("cvt.rna.tf32.f32 %0, %1;" : "=r"(u) : "f"(f)); return u;
}
__device__ __forceinline__ unsigned pack_bf16(float a, float b) {
    __nv_bfloat162 h = __floats2bfloat162_rn(a, b);
    return *(unsigned*)&h;
}
__device__ __forceinline__ void mma_tf32(float d[4], const unsigned a[4], const unsigned b[2]) {
    asm volatile("mma.sync.aligned.m16n8k8.row.col.f32.tf32.tf32.f32 "
        "{%0,%1,%2,%3},{%4,%5,%6,%7},{%8,%9},{%0,%1,%2,%3};\n"
        : "+f"(d[0]), "+f"(d[1]), "+f"(d[2]), "+f"(d[3])
        : "r"(a[0]), "r"(a[1]), "r"(a[2]), "r"(a[3]), "r"(b[0]), "r"(b[1]));
}
__device__ __forceinline__ void mma_bf16(float d[4], const unsigned a[4], const unsigned b[2]) {
    asm volatile("mma.sync.aligned.m16n8k16.row.col.f32.bf16.bf16.f32 "
        "{%0,%1,%2,%3},{%4,%5,%6,%7},{%8,%9},{%0,%1,%2,%3};\n"
        : "+f"(d[0]), "+f"(d[1]), "+f"(d[2]), "+f"(d[3])
        : "r"(a[0]), "r"(a[1]), "r"(a[2]), "r"(a[3]), "r"(b[0]), "r"(b[1]));
}
__device__ __forceinline__ void cpasync16(void* dst, const void* src, bool pred) {
    unsigned d = (unsigned)__cvta_generic_to_shared(dst);
    int sz = pred ? 16 : 0;
    asm volatile("cp.async.cg.shared.global [%0], [%1], 16, %2;\n"
                 :: "r"(d), "l"(src), "r"(sz));
}

// ---------------- LayerNorm ----------------
__global__ void ln_kernel(const float* __restrict__ x,
                          const float* __restrict__ gamma,
                          const float* __restrict__ beta) {
    int row = blockIdx.x;
    const float* xr = x + (size_t)row * D;
    float* yr = g_y + (size_t)row * D;
    int t = threadIdx.x;  // 256
    float v0 = xr[t], v1 = xr[t + 256];
    float s = v0 + v1, sq = v0 * v0 + v1 * v1;
    __shared__ float ss[8], ssq[8], mb[2];
    #pragma unroll
    for (int o = 16; o > 0; o >>= 1) {
        s  += __shfl_xor_sync(0xFFFFFFFFu, s, o);
        sq += __shfl_xor_sync(0xFFFFFFFFu, sq, o);
    }
    if ((t & 31) == 0) { ss[t >> 5] = s; ssq[t >> 5] = sq; }
    __syncthreads();
    if (t == 0) {
        float S = 0.f, SQ = 0.f;
        #pragma unroll
        for (int i = 0; i < 8; i++) { S += ss[i]; SQ += ssq[i]; }
        float mean = S * (1.0f / D);
        float var = SQ * (1.0f / D) - mean * mean;
        mb[0] = mean;
        mb[1] = rsqrtf(var + 1e-3f);
    }
    __syncthreads();
    float mean = mb[0], rstd = mb[1];
    yr[t]       = (v0 - mean) * rstd * gamma[t]       + beta[t];
    yr[t + 256] = (v1 - mean) * rstd * gamma[t + 256] + beta[t + 256];
}

// ---------------- 64x128-tile tf32 GEMM ----------------
struct Proj64Smem {
    float As[2][64][36];
    float Bs[2][32][136];
};

__device__ __forceinline__ void proj64_load(Proj64Smem* S, int buf,
                                            const float* A, const float* W,
                                            int i0, int j0, int kk, int M, int tid) {
    #pragma unroll
    for (int p = 0; p < 2; p++) {
        int idx = p * 256 + tid;
        int r = idx >> 3, c4 = (idx & 7) * 4;
        cpasync16(&S->As[buf][r][c4], &A[(size_t)(i0 + r) * 512 + kk + c4], (i0 + r) < M);
    }
    #pragma unroll
    for (int p = 0; p < 4; p++) {
        int idx = p * 256 + tid;
        int k = idx >> 5, c4 = (idx & 31) * 4;
        cpasync16(&S->Bs[buf][k][c4], &W[(size_t)(kk + k) * 512 + j0 + c4], true);
    }
    asm volatile("cp.async.commit_group;");
}

__device__ __forceinline__ void proj64_core(Proj64Smem* S,
                                            const float* A, const float* W,
                                            int i0, int j0, int M, int tid,
                                            float acc[2][4][4]) {
    int warp = tid >> 5, lane = tid & 31;
    int wy = warp >> 2, wx = warp & 3;
    int g = lane >> 2, q = lane & 3;
    proj64_load(S, 0, A, W, i0, j0, 0, M, tid);
    for (int s = 0; s < 16; s++) {
        if (s < 15) {
            proj64_load(S, (s + 1) & 1, A, W, i0, j0, (s + 1) * 32, M, tid);
            asm volatile("cp.async.wait_group 1;");
        } else {
            asm volatile("cp.async.wait_group 0;");
        }
        __syncthreads();
        int buf = s & 1;
        #pragma unroll
        for (int k8 = 0; k8 < 4; k8++) {
            int kc = k8 * 8 + q;
            unsigned af[2][4], bf[4][2];
            #pragma unroll
            for (int mt = 0; mt < 2; mt++) {
                int r = wy * 32 + mt * 16;
                af[mt][0] = f2tf(S->As[buf][r + g][kc]);
                af[mt][1] = f2tf(S->As[buf][r + g + 8][kc]);
                af[mt][2] = f2tf(S->As[buf][r + g][kc + 4]);
                af[mt][3] = f2tf(S->As[buf][r + g + 8][kc + 4]);
            }
            #pragma unroll
            for (int nt = 0; nt < 4; nt++) {
                int c = wx * 32 + nt * 8 + g;
                bf[nt][0] = f2tf(S->Bs[buf][kc][c]);
                bf[nt][1] = f2tf(S->Bs[buf][kc + 4][c]);
            }
            #pragma unroll
            for (int mt = 0; mt < 2; mt++)
                #pragma unroll
                for (int nt = 0; nt < 4; nt++)
                    mma_tf32(acc[mt][nt], af[mt], bf[nt]);
        }
        __syncthreads();
    }
}

// generic: C = A@W (+bias, +res); Cb != null -> bf16 output
__global__ void __launch_bounds__(256) proj64(
        const float* __restrict__ A, const float* __restrict__ W,
        const float* __restrict__ bias, const float* __restrict__ res,
        float* __restrict__ Cf, __nv_bfloat16* __restrict__ Cb, int M) {
    extern __shared__ char raw[];
    Proj64Smem* S = (Proj64Smem*)raw;
    int tid = threadIdx.x;
    int warp = tid >> 5, lane = tid & 31;
    int wy = warp >> 2, wx = warp & 3;
    int g = lane >> 2, q = lane & 3;
    int i0 = blockIdx.y * 64, j0 = blockIdx.x * 128;
    float acc[2][4][4] = {};
    proj64_core(S, A, W, i0, j0, M, tid, acc);
    #pragma unroll
    for (int mt = 0; mt < 2; mt++)
        #pragma unroll
        for (int nt = 0; nt < 4; nt++) {
            int c = j0 + wx * 32 + nt * 8 + q * 2;
            float b0 = bias ? bias[c] : 0.f;
            float b1 = bias ? bias[c + 1] : 0.f;
            #pragma unroll
            for (int half = 0; half < 2; half++) {
                int rr = i0 + wy * 32 + mt * 16 + g + half * 8;
                if (rr >= M) continue;
                float e0 = acc[mt][nt][half * 2 + 0] + b0;
                float e1 = acc[mt][nt][half * 2 + 1] + b1;
                if (res) { e0 += res[(size_t)rr * 512 + c]; e1 += res[(size_t)rr * 512 + c + 1]; }
                if (Cb) ((unsigned*)Cb)[((size_t)rr * 512 + c) >> 1] = pack_bf16(e0, e1);
                else    *(float2*)&Cf[(size_t)rr * 512 + c] = make_float2(e0, e1);
            }
        }
}

// fused q/k/v projection; z=0 -> g_q f32; z=1 -> g_kb bf16; z=2 -> g_v f32
__global__ void __launch_bounds__(256) qkv_mma(
        const float* __restrict__ Wq, const float* __restrict__ Wk, const float* __restrict__ Wv,
        const float* __restrict__ bq, const float* __restrict__ bk, const float* __restrict__ bv) {
    extern __shared__ char raw[];
    Proj64Smem* S = (Proj64Smem*)raw;
    int z = blockIdx.z;
    const float* W    = (z == 0) ? Wq : (z == 1) ? Wk : Wv;
    const float* bias = (z == 0) ? bq : (z == 1) ? bk : bv;
    int tid = threadIdx.x;
    int warp = tid >> 5, lane = tid & 31;
    int wy = warp >> 2, wx = warp & 3;
    int g = lane >> 2, q = lane & 3;
    int i0 = blockIdx.y * 64, j0 = blockIdx.x * 128;
    float acc[2][4][4] = {};
    proj64_core(S, g_y, W, i0, j0, BT, tid, acc);
    #pragma unroll
    for (int mt = 0; mt < 2; mt++)
        #pragma unroll
        for (int nt = 0; nt < 4; nt++) {
            int c = j0 + wx * 32 + nt * 8 + q * 2;
            float b0 = bias[c], b1 = bias[c + 1];
            #pragma unroll
            for (int half = 0; half < 2; half++) {
                int rr = i0 + wy * 32 + mt * 16 + g + half * 8;
                float e0 = acc[mt][nt][half * 2 + 0] + b0;
                float e1 = acc[mt][nt][half * 2 + 1] + b1;
                if (z == 1) {
                    ((unsigned*)g_kb)[((size_t)rr * 512 + c) >> 1] = pack_bf16(e0, e1);
                } else {
                    float* C = (z == 0) ? g_q : g_v;
                    *(float2*)&C[(size_t)rr * 512 + c] = make_float2(e0, e1);
                }
            }
        }
}

// ---------------- V transpose + bf16 convert: g_v -> g_vt[b*H+h][d][j] ----------------
__global__ void __launch_bounds__(256) vt_kernel() {
    __shared__ float st[128][65];
    int bh = blockIdx.y;
    int b = bh >> 3, h = bh & 7;
    int j0 = blockIdx.x * 128;
    int tid = threadIdx.x;
    #pragma unroll
    for (int p = 0; p < 8; p++) {
        int idx = p * 256 + tid;
        int j = idx >> 4, d4 = (idx & 15) * 4;
        float4 v = *(const float4*)&g_v[((size_t)(b * T + j0 + j)) * D + h * 64 + d4];
        st[j][d4] = v.x; st[j][d4 + 1] = v.y; st[j][d4 + 2] = v.z; st[j][d4 + 3] = v.w;
    }
    __syncthreads();
    #pragma unroll
    for (int p = 0; p < 16; p++) {
        int idx = p * 256 + tid;
        int d = idx >> 6, jp = (idx & 63) * 2;
        unsigned u = pack_bf16(st[jp][d], st[jp + 1][d]);
        *(unsigned*)&g_vt[((size_t)bh * 64 + d) * 1024 + j0 + jp] = u;
    }
}

// rel_shift wraparound: g_fixv[z] = dot(bf16(q[b,1,h]+pb), p_bf16[b,0,h])
__global__ void fix_kernel(const float* __restrict__ pb) {
    int z = blockIdx.x; int b = z >> 3, h = z & 7;
    int t = threadIdx.x;  // 32
    float a0 = __bfloat162float(__float2bfloat16_rn(
        g_q[((size_t)(b * T + 1)) * D + h * 64 + t] + pb[h * 64 + t]));
    float a1 = __bfloat162float(__float2bfloat16_rn(
        g_q[((size_t)(b * T + 1)) * D + h * 64 + t + 32] + pb[h * 64 + t + 32]));
    float p0 = __bfloat162float(g_pb[((size_t)(b * LL)) * D + h * 64 + t]);
    float p1 = __bfloat162float(g_pb[((size_t)(b * LL)) * D + h * 64 + t + 32]);
    float s = a0 * p0 + a1 * p1;
    #pragma unroll
    for (int o = 16; o > 0; o >>= 1) s += __shfl_xor_sync(0xFFFFFFFFu, s, o);
    if (t == 0) g_fixv[z] = s;
}

// ---------------- flash attention: bf16 k16, 64-row tiles, 4 warps, 2 CTAs/SM ----------------
struct FlashSmem {
    unsigned Ks[2][64][36];      // bf16 pairs: row=key, 64 feats (pad 72)
    unsigned Ps[2][64][36];      // row = l - cbase
    unsigned Vt[2][64][36];      // row = d, 64 j's
    __nv_bfloat16 R[64][264];    // positional ring, slot = l & 255 (warp-private rows)
    float Qs[64][68];
    float cbS[64], pbS[64];
};

__device__ __forceinline__ void pos_chunk(FlashSmem* S, int stage, int cbase,
                                          const unsigned apf[4][4], int row0, int g, int q) {
    float accP[8][4] = {};
    #pragma unroll
    for (int kb = 0; kb < 4; kb++) {
        #pragma unroll
        for (int nt = 0; nt < 8; nt++) {
            unsigned bf[2] = { S->Ps[stage][nt * 8 + g][kb * 8 + q],
                               S->Ps[stage][nt * 8 + g][kb * 8 + q + 4] };
            mma_bf16(accP[nt], apf[kb], bf);
        }
    }
    #pragma unroll
    for (int nt = 0; nt < 8; nt++) {
        int s0 = (cbase + nt * 8 + 2 * q) & 255;   // cbase%64==0, 2q even -> pair stays in-slot
        *(__nv_bfloat162*)&S->R[row0][s0]     = __floats2bfloat162_rn(accP[nt][0], accP[nt][1]);
        *(__nv_bfloat162*)&S->R[row0 + 8][s0] = __floats2bfloat162_rn(accP[nt][2], accP[nt][3]);
    }
}

__global__ void __launch_bounds__(128, 2) flash_kernel(const float* __restrict__ cb,
                                                       const float* __restrict__ pb) {
    extern __shared__ char raw[];
    FlashSmem* S = (FlashSmem*)raw;
    int z = blockIdx.y; int b = z >> 3, h = z & 7;
    int i0 = blockIdx.x * 64;
    int tid = threadIdx.x;
    int warp = tid >> 5, lane = tid & 31;
    int g = lane >> 2, q = lane & 3;
    int row0 = warp * 16 + g;
    const int base0 = 1024 - i0 - 128;

    // prologue: Qs (f32) + P chunks 0,1 (bf16) via cp.async
    const float* qsrc = g_q + ((size_t)(b * T + i0)) * D + h * 64;
    #pragma unroll
    for (int p = 0; p < 8; p++) {
        int idx = p * 128 + tid;
        int r = idx >> 4, c4 = (idx & 15) * 4;
        cpasync16(&S->Qs[r][c4], &qsrc[(size_t)r * D + c4], true);
    }
    #pragma unroll
    for (int p = 0; p < 4; p++) {
        int idx = p * 128 + tid;
        int r = idx >> 3, c8 = (idx & 7) * 8;
        int l0 = base0 + r;      l0 = min(max(l0, 0), LL - 1);
        int l1 = base0 + 64 + r; l1 = min(max(l1, 0), LL - 1);
        cpasync16(&S->Ps[0][r][c8 >> 1], &g_pb[((size_t)(b * LL + l0)) * D + h * 64 + c8], true);
        cpasync16(&S->Ps[1][r][c8 >> 1], &g_pb[((size_t)(b * LL + l1)) * D + h * 64 + c8], true);
    }
    asm volatile("cp.async.commit_group;");
    if (tid < 16) {
        *(float4*)&S->cbS[tid * 4] = *(const float4*)&cb[h * 64 + tid * 4];
        *(float4*)&S->pbS[tid * 4] = *(const float4*)&pb[h * 64 + tid * 4];
    }
    asm volatile("cp.async.wait_group 0;");
    __syncthreads();

    // persistent Q fragments (bf16, m16n8k16 A layout), content + pos variants
    unsigned acf[4][4], apf[4][4];
    #pragma unroll
    for (int kb = 0; kb < 4; kb++) {
        int k0 = kb * 16 + 2 * q;
        float q00 = S->Qs[row0][k0],       q01 = S->Qs[row0][k0 + 1];
        float q10 = S->Qs[row0 + 8][k0],   q11 = S->Qs[row0 + 8][k0 + 1];
        float q02 = S->Qs[row0][k0 + 8],   q03 = S->Qs[row0][k0 + 9];
        float q12 = S->Qs[row0 + 8][k0 + 8], q13 = S->Qs[row0 + 8][k0 + 9];
        float c0 = S->cbS[k0], c1 = S->cbS[k0 + 1], c8v = S->cbS[k0 + 8], c9 = S->cbS[k0 + 9];
        float p0 = S->pbS[k0], p1 = S->pbS[k0 + 1], p8 = S->pbS[k0 + 8], p9 = S->pbS[k0 + 9];
        acf[kb][0] = pack_bf16(q00 + c0, q01 + c1);
        acf[kb][1] = pack_bf16(q10 + c0, q11 + c1);
        acf[kb][2] = pack_bf16(q02 + c8v, q03 + c9);
        acf[kb][3] = pack_bf16(q12 + c8v, q13 + c9);
        apf[kb][0] = pack_bf16(q00 + p0, q01 + p1);
        apf[kb][1] = pack_bf16(q10 + p0, q11 + p1);
        apf[kb][2] = pack_bf16(q02 + p8, q03 + p9);
        apf[kb][3] = pack_bf16(q12 + p8, q13 + p9);
    }

    pos_chunk(S, 0, base0, apf, row0, g, q);
    pos_chunk(S, 1, base0 + 64, apf, row0, g, q);
    __syncthreads();
    #pragma unroll
    for (int p = 0; p < 4; p++) {
        int idx = p * 128 + tid;
        int r = idx >> 3, c8 = (idx & 7) * 8;
        int l = base0 + 128 + r; l = min(max(l, 0), LL - 1);
        cpasync16(&S->Ps[0][r][c8 >> 1], &g_pb[((size_t)(b * LL + l)) * D + h * 64 + c8], true);
    }
    asm volatile("cp.async.commit_group;");
    asm volatile("cp.async.wait_group 0;");
    __syncthreads();
    pos_chunk(S, 0, base0 + 128, apf, row0, g, q);
    __syncthreads();

    // prefetch jt=0: K, Vt, P(base0+192) into stage 0
    {
        const __nv_bfloat16* kb_ = g_kb + ((size_t)(b * T)) * D + h * 64;
        const __nv_bfloat16* vt_ = g_vt + ((size_t)z) * 64 * 1024;
        #pragma unroll
        for (int p = 0; p < 4; p++) {
            int idx = p * 128 + tid;
            int r = idx >> 3, c8 = (idx & 7) * 8;
            cpasync16(&S->Ks[0][r][c8 >> 1], &kb_[(size_t)r * D + c8], true);
            cpasync16(&S->Vt[0][r][c8 >> 1], &vt_[(size_t)r * 1024 + c8], true);
            int l = base0 + 192 + r; l = min(max(l, 0), LL - 1);
            cpasync16(&S->Ps[0][r][c8 >> 1], &g_pb[((size_t)(b * LL + l)) * D + h * 64 + c8], true);
        }
        asm volatile("cp.async.commit_group;");
    }

    float accO[8][4] = {};
    float sumA = 0.f, sumB = 0.f;
    float gfixv = g_fixv[z];

    for (int jt = 0; jt < 16; jt++) {
        asm volatile("cp.async.wait_group 0;");
        __syncthreads();
        int st = jt & 1;
        if (jt < 15) {
            int st2 = st ^ 1;
            const __nv_bfloat16* kb_ = g_kb + ((size_t)(b * T + (jt + 1) * 64)) * D + h * 64;
            const __nv_bfloat16* vt_ = g_vt + ((size_t)z) * 64 * 1024 + (jt + 1) * 64;
            #pragma unroll
            for (int p = 0; p < 4; p++) {
                int idx = p * 128 + tid;
                int r = idx >> 3, c8 = (idx & 7) * 8;
                cpasync16(&S->Ks[st2][r][c8 >> 1], &kb_[(size_t)r * D + c8], true);
                cpasync16(&S->Vt[st2][r][c8 >> 1], &vt_[(size_t)r * 1024 + c8], true);
                int l = base0 + 192 + 64 * (jt + 1) + r; l = min(max(l, 0), LL - 1);
                cpasync16(&S->Ps[st2][r][c8 >> 1], &g_pb[((size_t)(b * LL + l)) * D + h * 64 + c8], true);
            }
            asm volatile("cp.async.commit_group;");
        }

        // content scores: 4 k-blocks x 8 n-blocks
        float accC[8][4] = {};
        #pragma unroll
        for (int kb2 = 0; kb2 < 4; kb2++) {
            #pragma unroll
            for (int nt = 0; nt < 8; nt++) {
                unsigned bf[2] = { S->Ks[st][nt * 8 + g][kb2 * 8 + q],
                                   S->Ks[st][nt * 8 + g][kb2 * 8 + q + 4] };
                mma_bf16(accC[nt], acf[kb2], bf);
            }
        }
        if (jt < 15) pos_chunk(S, st, base0 + 192 + 64 * jt, apf, row0, g, q);

        // combine + exp + AV (C-fragment feeds A-fragment directly; no shuffles)
        int basew = 1024 + 64 * jt - i0;
        bool fixc = (i0 == 0) && (jt == 15) && (warp == 0) && (g == 0) && (q == 3);
        #pragma unroll
        for (int kb2 = 0; kb2 < 4; kb2++) {
            unsigned a[4];
            #pragma unroll
            for (int half = 0; half < 2; half++) {
                int nt = kb2 * 2 + half;
                int jl = nt * 8 + 2 * q;
                int il0 = row0, il1 = row0 + 8;
                float r00 = __bfloat162float(S->R[il0][(basew + jl - il0) & 255]);
                float r01 = __bfloat162float(S->R[il0][(basew + jl + 1 - il0) & 255]);
                float r10 = __bfloat162float(S->R[il1][(basew + jl - il1) & 255]);
                float r11 = __bfloat162float(S->R[il1][(basew + jl + 1 - il1) & 255]);
                if (fixc && nt == 7) r01 = gfixv;   // (i=0, j=1023) wraparound
                float e0 = __expf((accC[nt][0] + r00) * 0.125f);
                float e1 = __expf((accC[nt][1] + r01) * 0.125f);
                float e2 = __expf((accC[nt][2] + r10) * 0.125f);
                float e3 = __expf((accC[nt][3] + r11) * 0.125f);
                sumA += e0 + e1; sumB += e2 + e3;
                a[half * 2]     = pack_bf16(e0, e1);   // row g,   k-half
                a[half * 2 + 1] = pack_bf16(e2, e3);   // row g+8, k-half
            }
            // reorder to {r0k0, r8k0, r0k8, r8k8}
            unsigned af[4] = { a[0], a[1], a[2], a[3] };
            #pragma unroll
            for (int n2 = 0; n2 < 8; n2++) {
                unsigned bf[2] = { S->Vt[st][n2 * 8 + g][kb2 * 8 + q],
                                   S->Vt[st][n2 * 8 + g][kb2 * 8 + q + 4] };
                mma_bf16(accO[n2], af, bf);
            }
        }
    }

    // finalize
    sumA += __shfl_xor_sync(0xFFFFFFFFu, sumA, 1);
    sumA += __shfl_xor_sync(0xFFFFFFFFu, sumA, 2);
    sumB += __shfl_xor_sync(0xFFFFFFFFu, sumB, 1);
    sumB += __shfl_xor_sync(0xFFFFFFFFu, sumB, 2);
    float invA = 1.f / sumA, invB = 1.f / sumB;
    #pragma unroll
    for (int n2 = 0; n2 < 8; n2++) {
        int col = h * 64 + n2 * 8 + 2 * q;
        size_t r = (size_t)(b * T + i0 + row0);
        *(float2*)&g_o[r * D + col] = make_float2(accO[n2][0] * invA, accO[n2][1] * invA);
        *(float2*)&g_o[(r + 8) * D + col] = make_float2(accO[n2][2] * invB, accO[n2][3] * invB);
    }
}

extern "C" void kernel_launch(void* const* d_in, const int* in_sizes, int n_in,
                              void* d_out, int out_size) {
    const float* x     = (const float*)d_in[0];
    const float* pos   = (const float*)d_in[1];
    const float* cb    = (const float*)d_in[2];
    const float* pb    = (const float*)d_in[3];
    const float* gamma = (const float*)d_in[4];
    const float* beta  = (const float*)d_in[5];
    const float* Wq    = (const float*)d_in[6];
    const float* bq    = (const float*)d_in[7];
    const float* Wk    = (const float*)d_in[8];
    const float* bk    = (const float*)d_in[9];
    const float* Wv    = (const float*)d_in[10];
    const float* bv    = (const float*)d_in[11];
    const float* Wp    = (const float*)d_in[12];
    const float* Wo    = (const float*)d_in[13];
    const float* bo    = (const float*)d_in[14];
    float* out = (float*)d_out;

    float *o;
    __nv_bfloat16* pbuf;
    cudaGetSymbolAddress((void**)&o, g_o);
    cudaGetSymbolAddress((void**)&pbuf, g_pb);

    cudaFuncSetAttribute(proj64, cudaFuncAttributeMaxDynamicSharedMemorySize,
                         (int)sizeof(Proj64Smem));
    cudaFuncSetAttribute(qkv_mma, cudaFuncAttributeMaxDynamicSharedMemorySize,
                         (int)sizeof(Proj64Smem));
    cudaFuncSetAttribute(flash_kernel, cudaFuncAttributeMaxDynamicSharedMemorySize,
                         (int)sizeof(FlashSmem));

    // 1. LayerNorm
    ln_kernel<<<BT, 256>>>(x, gamma, beta);

    // 2. projections: q/k/v fused (k -> bf16), pos -> bf16
    qkv_mma<<<dim3(4, 64, 3), 256, sizeof(Proj64Smem)>>>(Wq, Wk, Wv, bq, bk, bv);
    proj64<<<dim3(4, 128), 256, sizeof(Proj64Smem)>>>(pos, Wp, nullptr, nullptr,
                                                      nullptr, pbuf, BL);

    // 3. v transpose+convert, wraparound fix value
    vt_kernel<<<dim3(8, 32), 256>>>();
    fix_kernel<<<BB * H, 32>>>(pb);

    // 4. fused flash attention (bf16 mma, 2 CTAs/SM)
    flash_kernel<<<dim3(16, 32), 128, sizeof(FlashSmem)>>>(cb, pb);

    // 5. output projection + bias + residual
    proj64<<<dim3(4, 64), 256, sizeof(Proj64Smem)>>>(o, Wo, bo, x, out, nullptr, BT);
}

// round 8
// speedup vs baseline: 2.2811x; 1.1717x over previous
#include <cuda_runtime.h>
#include <cuda_bf16.h>
#include <math.h>

#define BB 4
#define T 1024
#define D 512
#define H 8
#define LL 2047
#define BT (BB*T)      // 4096
#define BL (BB*LL)     // 8188

__device__ __nv_bfloat16 g_yb[BT*D];           // LN output, bf16
__device__ __nv_bfloat16 g_wt[4*512*512];      // transposed bf16 weights: q,k,v,p
__device__ __nv_bfloat16 g_posb[(size_t)BL*D]; // pos in bf16
__device__ float g_q[BT*D];    // q + bq (f32)
__device__ float g_v[BT*D];    // f32 (pre-transpose)
__device__ float g_o[BT*D];
__device__ __nv_bfloat16 g_kb[BT*D];
__device__ __nv_bfloat16 g_pb[(size_t)BL*D];
__device__ __nv_bfloat16 g_vt[(size_t)BB*H*64*1024];  // [b*H+h][d][j]
__device__ float g_fixv[BB*H];

// ---------------- helpers ----------------
__device__ __forceinline__ unsigned f2tf(float f) {
    unsigned u; asm("cvt.rna.tf32.f32 %0, %1;" : "=r"(u) : "f"(f)); return u;
}
__device__ __forceinline__ unsigned pack_bf16(float a, float b) {
    __nv_bfloat162 h = __floats2bfloat162_rn(a, b);
    return *(unsigned*)&h;
}
__device__ __forceinline__ void mma_tf32(float d[4], const unsigned a[4], const unsigned b[2]) {
    asm volatile("mma.sync.aligned.m16n8k8.row.col.f32.tf32.tf32.f32 "
        "{%0,%1,%2,%3},{%4,%5,%6,%7},{%8,%9},{%0,%1,%2,%3};\n"
        : "+f"(d[0]), "+f"(d[1]), "+f"(d[2]), "+f"(d[3])
        : "r"(a[0]), "r"(a[1]), "r"(a[2]), "r"(a[3]), "r"(b[0]), "r"(b[1]));
}
__device__ __forceinline__ void mma_bf16(float d[4], const unsigned a[4], const unsigned b[2]) {
    asm volatile("mma.sync.aligned.m16n8k16.row.col.f32.bf16.bf16.f32 "
        "{%0,%1,%2,%3},{%4,%5,%6,%7},{%8,%9},{%0,%1,%2,%3};\n"
        : "+f"(d[0]), "+f"(d[1]), "+f"(d[2]), "+f"(d[3])
        : "r"(a[0]), "r"(a[1]), "r"(a[2]), "r"(a[3]), "r"(b[0]), "r"(b[1]));
}
__device__ __forceinline__ void cpasync16(void* dst, const void* src, bool pred) {
    unsigned d = (unsigned)__cvta_generic_to_shared(dst);
    int sz = pred ? 16 : 0;
    asm volatile("cp.async.cg.shared.global [%0], [%1], 16, %2;\n"
                 :: "r"(d), "l"(src), "r"(sz));
}

// ---------------- LayerNorm (writes bf16) ----------------
__global__ void ln_kernel(const float* __restrict__ x,
                          const float* __restrict__ gamma,
                          const float* __restrict__ beta) {
    int row = blockIdx.x;
    const float* xr = x + (size_t)row * D;
    __nv_bfloat16* yr = g_yb + (size_t)row * D;
    int t = threadIdx.x;  // 256
    float v0 = xr[t], v1 = xr[t + 256];
    float s = v0 + v1, sq = v0 * v0 + v1 * v1;
    __shared__ float ss[8], ssq[8], mb[2];
    #pragma unroll
    for (int o = 16; o > 0; o >>= 1) {
        s  += __shfl_xor_sync(0xFFFFFFFFu, s, o);
        sq += __shfl_xor_sync(0xFFFFFFFFu, sq, o);
    }
    if ((t & 31) == 0) { ss[t >> 5] = s; ssq[t >> 5] = sq; }
    __syncthreads();
    if (t == 0) {
        float S = 0.f, SQ = 0.f;
        #pragma unroll
        for (int i = 0; i < 8; i++) { S += ss[i]; SQ += ssq[i]; }
        float mean = S * (1.0f / D);
        float var = SQ * (1.0f / D) - mean * mean;
        mb[0] = mean;
        mb[1] = rsqrtf(var + 1e-3f);
    }
    __syncthreads();
    float mean = mb[0], rstd = mb[1];
    yr[t]       = __float2bfloat16_rn((v0 - mean) * rstd * gamma[t]       + beta[t]);
    yr[t + 256] = __float2bfloat16_rn((v1 - mean) * rstd * gamma[t + 256] + beta[t + 256]);
}

// ---------------- weight transpose + bf16 convert ----------------
__global__ void wt_kernel(const float* __restrict__ Wq, const float* __restrict__ Wk,
                          const float* __restrict__ Wv, const float* __restrict__ Wp) {
    __shared__ float tile[32][33];
    int z = blockIdx.z;
    const float* W = (z == 0) ? Wq : (z == 1) ? Wk : (z == 2) ? Wv : Wp;
    int k0 = blockIdx.y * 32, n0 = blockIdx.x * 32;
    int tid = threadIdx.x;
    #pragma unroll
    for (int p = 0; p < 4; p++) {
        int r = p * 8 + (tid >> 5), c = tid & 31;
        tile[r][c] = W[(size_t)(k0 + r) * 512 + n0 + c];
    }
    __syncthreads();
    #pragma unroll
    for (int p = 0; p < 4; p++) {
        int r = p * 8 + (tid >> 5), c = tid & 31;
        g_wt[(size_t)z * 262144 + (size_t)(n0 + r) * 512 + k0 + c] =
            __float2bfloat16_rn(tile[c][r]);
    }
}

// ---------------- pos -> bf16 ----------------
__global__ void posb_kernel(const float* __restrict__ pos) {
    size_t i = ((size_t)blockIdx.x * 256 + threadIdx.x) * 2;
    float2 v = *(const float2*)&pos[i];
    ((unsigned*)g_posb)[i >> 1] = pack_bf16(v.x, v.y);
}

// ---------------- bf16 m16n8k16 projection GEMM (64m x 128n tile) ----------------
struct ProjBSmem {
    unsigned As[2][64][20];    // 64 rows x 32 bf16 (16 u32, pad 20)
    unsigned Bs[2][128][20];   // 128 n-rows x 32 bf16
};

__device__ __forceinline__ void projb_load(ProjBSmem* S, int buf,
                                           const __nv_bfloat16* A, const __nv_bfloat16* Bt,
                                           int i0, int j0, int kk, int M, int tid) {
    {
        int r = tid >> 2, seg = tid & 3;
        cpasync16(&S->As[buf][r][seg * 4],
                  &A[(size_t)(i0 + r) * 512 + kk + seg * 8], (i0 + r) < M);
    }
    #pragma unroll
    for (int p = 0; p < 2; p++) {
        int idx = p * 256 + tid;
        int r = idx >> 2, seg = idx & 3;
        cpasync16(&S->Bs[buf][r][seg * 4],
                  &Bt[(size_t)(j0 + r) * 512 + kk + seg * 8], true);
    }
    asm volatile("cp.async.commit_group;");
}

__device__ __forceinline__ void projb_body(
        const __nv_bfloat16* __restrict__ A, const __nv_bfloat16* __restrict__ Bt,
        const float* __restrict__ bias,
        float* __restrict__ outF, __nv_bfloat16* __restrict__ outB,
        int i0, int j0, int M) {
    extern __shared__ char raw[];
    ProjBSmem* S = (ProjBSmem*)raw;
    int tid = threadIdx.x;
    int warp = tid >> 5, lane = tid & 31;
    int wy = warp >> 2, wx = warp & 3;
    int g = lane >> 2, q = lane & 3;
    float acc[2][4][4] = {};

    projb_load(S, 0, A, Bt, i0, j0, 0, M, tid);
    for (int s = 0; s < 16; s++) {
        if (s < 15) {
            projb_load(S, (s + 1) & 1, A, Bt, i0, j0, (s + 1) * 32, M, tid);
            asm volatile("cp.async.wait_group 1;");
        } else {
            asm volatile("cp.async.wait_group 0;");
        }
        __syncthreads();
        int buf = s & 1;
        #pragma unroll
        for (int kb = 0; kb < 2; kb++) {
            unsigned af[2][4], bf[4][2];
            #pragma unroll
            for (int mt = 0; mt < 2; mt++) {
                int r = wy * 32 + mt * 16 + g;
                af[mt][0] = S->As[buf][r][kb * 8 + q];
                af[mt][1] = S->As[buf][r + 8][kb * 8 + q];
                af[mt][2] = S->As[buf][r][kb * 8 + q + 4];
                af[mt][3] = S->As[buf][r + 8][kb * 8 + q + 4];
            }
            #pragma unroll
            for (int nt = 0; nt < 4; nt++) {
                int n = wx * 32 + nt * 8 + g;
                bf[nt][0] = S->Bs[buf][n][kb * 8 + q];
                bf[nt][1] = S->Bs[buf][n][kb * 8 + q + 4];
            }
            #pragma unroll
            for (int mt = 0; mt < 2; mt++)
                #pragma unroll
                for (int nt = 0; nt < 4; nt++)
                    mma_bf16(acc[mt][nt], af[mt], bf[nt]);
        }
        __syncthreads();
    }
    #pragma unroll
    for (int mt = 0; mt < 2; mt++)
        #pragma unroll
        for (int nt = 0; nt < 4; nt++) {
            int c = j0 + wx * 32 + nt * 8 + q * 2;
            float b0 = bias ? bias[c] : 0.f;
            float b1 = bias ? bias[c + 1] : 0.f;
            #pragma unroll
            for (int half = 0; half < 2; half++) {
                int rr = i0 + wy * 32 + mt * 16 + g + half * 8;
                if (rr >= M) continue;
                float e0 = acc[mt][nt][half * 2 + 0] + b0;
                float e1 = acc[mt][nt][half * 2 + 1] + b1;
                if (outB) ((unsigned*)outB)[((size_t)rr * 512 + c) >> 1] = pack_bf16(e0, e1);
                else      *(float2*)&outF[(size_t)rr * 512 + c] = make_float2(e0, e1);
            }
        }
}

// fused q/k/v: z=0 -> g_q f32; z=1 -> g_kb bf16; z=2 -> g_v f32
__global__ void __launch_bounds__(256) qkvb_kernel(
        const float* __restrict__ bq, const float* __restrict__ bk,
        const float* __restrict__ bv) {
    int z = blockIdx.z;
    const float* bias = (z == 0) ? bq : (z == 1) ? bk : bv;
    float* outF = (z == 0) ? g_q : (z == 2) ? g_v : nullptr;
    __nv_bfloat16* outB = (z == 1) ? g_kb : nullptr;
    projb_body(g_yb, g_wt + (size_t)z * 262144, bias, outF, outB,
               blockIdx.y * 64, blockIdx.x * 128, BT);
}

// pos projection -> g_pb bf16
__global__ void __launch_bounds__(256) posproj_kernel() {
    projb_body(g_posb, g_wt + (size_t)3 * 262144, nullptr, nullptr, g_pb,
               blockIdx.y * 64, blockIdx.x * 128, BL);
}

// ---------------- tf32 output projection (64x128 tile) ----------------
struct Proj64Smem {
    float As[2][64][36];
    float Bs[2][32][136];
};

__device__ __forceinline__ void proj64_load(Proj64Smem* S, int buf,
                                            const float* A, const float* W,
                                            int i0, int j0, int kk, int M, int tid) {
    #pragma unroll
    for (int p = 0; p < 2; p++) {
        int idx = p * 256 + tid;
        int r = idx >> 3, c4 = (idx & 7) * 4;
        cpasync16(&S->As[buf][r][c4], &A[(size_t)(i0 + r) * 512 + kk + c4], (i0 + r) < M);
    }
    #pragma unroll
    for (int p = 0; p < 4; p++) {
        int idx = p * 256 + tid;
        int k = idx >> 5, c4 = (idx & 31) * 4;
        cpasync16(&S->Bs[buf][k][c4], &W[(size_t)(kk + k) * 512 + j0 + c4], true);
    }
    asm volatile("cp.async.commit_group;");
}

__global__ void __launch_bounds__(256) proj64(
        const float* __restrict__ A, const float* __restrict__ W,
        const float* __restrict__ bias, const float* __restrict__ res,
        float* __restrict__ C, int M) {
    extern __shared__ char raw[];
    Proj64Smem* S = (Proj64Smem*)raw;
    int tid = threadIdx.x;
    int warp = tid >> 5, lane = tid & 31;
    int wy = warp >> 2, wx = warp & 3;
    int g = lane >> 2, q = lane & 3;
    int i0 = blockIdx.y * 64, j0 = blockIdx.x * 128;
    float acc[2][4][4] = {};
    proj64_load(S, 0, A, W, i0, j0, 0, M, tid);
    for (int s = 0; s < 16; s++) {
        if (s < 15) {
            proj64_load(S, (s + 1) & 1, A, W, i0, j0, (s + 1) * 32, M, tid);
            asm volatile("cp.async.wait_group 1;");
        } else {
            asm volatile("cp.async.wait_group 0;");
        }
        __syncthreads();
        int buf = s & 1;
        #pragma unroll
        for (int k8 = 0; k8 < 4; k8++) {
            int kc = k8 * 8 + q;
            unsigned af[2][4], bf[4][2];
            #pragma unroll
            for (int mt = 0; mt < 2; mt++) {
                int r = wy * 32 + mt * 16;
                af[mt][0] = f2tf(S->As[buf][r + g][kc]);
                af[mt][1] = f2tf(S->As[buf][r + g + 8][kc]);
                af[mt][2] = f2tf(S->As[buf][r + g][kc + 4]);
                af[mt][3] = f2tf(S->As[buf][r + g + 8][kc + 4]);
            }
            #pragma unroll
            for (int nt = 0; nt < 4; nt++) {
                int c = wx * 32 + nt * 8 + g;
                bf[nt][0] = f2tf(S->Bs[buf][kc][c]);
                bf[nt][1] = f2tf(S->Bs[buf][kc + 4][c]);
            }
            #pragma unroll
            for (int mt = 0; mt < 2; mt++)
                #pragma unroll
                for (int nt = 0; nt < 4; nt++)
                    mma_tf32(acc[mt][nt], af[mt], bf[nt]);
        }
        __syncthreads();
    }
    #pragma unroll
    for (int mt = 0; mt < 2; mt++)
        #pragma unroll
        for (int nt = 0; nt < 4; nt++) {
            int c = j0 + wx * 32 + nt * 8 + q * 2;
            float b0 = bias[c], b1 = bias[c + 1];
            #pragma unroll
            for (int half = 0; half < 2; half++) {
                int rr = i0 + wy * 32 + mt * 16 + g + half * 8;
                float e0 = acc[mt][nt][half * 2 + 0] + b0 + res[(size_t)rr * 512 + c];
                float e1 = acc[mt][nt][half * 2 + 1] + b1 + res[(size_t)rr * 512 + c + 1];
                *(float2*)&C[(size_t)rr * 512 + c] = make_float2(e0, e1);
            }
        }
}

// ---------------- V transpose + bf16 convert ----------------
__global__ void __launch_bounds__(256) vt_kernel() {
    __shared__ float st[128][65];
    int bh = blockIdx.y;
    int b = bh >> 3, h = bh & 7;
    int j0 = blockIdx.x * 128;
    int tid = threadIdx.x;
    #pragma unroll
    for (int p = 0; p < 8; p++) {
        int idx = p * 256 + tid;
        int j = idx >> 4, d4 = (idx & 15) * 4;
        float4 v = *(const float4*)&g_v[((size_t)(b * T + j0 + j)) * D + h * 64 + d4];
        st[j][d4] = v.x; st[j][d4 + 1] = v.y; st[j][d4 + 2] = v.z; st[j][d4 + 3] = v.w;
    }
    __syncthreads();
    #pragma unroll
    for (int p = 0; p < 16; p++) {
        int idx = p * 256 + tid;
        int d = idx >> 6, jp = (idx & 63) * 2;
        unsigned u = pack_bf16(st[jp][d], st[jp + 1][d]);
        *(unsigned*)&g_vt[((size_t)bh * 64 + d) * 1024 + j0 + jp] = u;
    }
}

// rel_shift wraparound value
__global__ void fix_kernel(const float* __restrict__ pb) {
    int z = blockIdx.x; int b = z >> 3, h = z & 7;
    int t = threadIdx.x;  // 32
    float a0 = __bfloat162float(__float2bfloat16_rn(
        g_q[((size_t)(b * T + 1)) * D + h * 64 + t] + pb[h * 64 + t]));
    float a1 = __bfloat162float(__float2bfloat16_rn(
        g_q[((size_t)(b * T + 1)) * D + h * 64 + t + 32] + pb[h * 64 + t + 32]));
    float p0 = __bfloat162float(g_pb[((size_t)(b * LL)) * D + h * 64 + t]);
    float p1 = __bfloat162float(g_pb[((size_t)(b * LL)) * D + h * 64 + t + 32]);
    float s = a0 * p0 + a1 * p1;
    #pragma unroll
    for (int o = 16; o > 0; o >>= 1) s += __shfl_xor_sync(0xFFFFFFFFu, s, o);
    if (t == 0) g_fixv[z] = s;
}

// ---------------- flash attention: bf16 k16, 64-row tiles, 4 warps, 2 CTAs/SM ----------------
struct FlashSmem {
    unsigned Ks[2][64][36];
    unsigned Ps[2][64][36];
    unsigned Vt[2][64][36];
    __nv_bfloat16 R[64][264];
    float Qs[64][68];
    float cbS[64], pbS[64];
};

__device__ __forceinline__ void pos_chunk(FlashSmem* S, int stage, int cbase,
                                          const unsigned apf[4][4], int row0, int g, int q) {
    float accP[8][4] = {};
    #pragma unroll
    for (int kb = 0; kb < 4; kb++) {
        #pragma unroll
        for (int nt = 0; nt < 8; nt++) {
            unsigned bf[2] = { S->Ps[stage][nt * 8 + g][kb * 8 + q],
                               S->Ps[stage][nt * 8 + g][kb * 8 + q + 4] };
            mma_bf16(accP[nt], apf[kb], bf);
        }
    }
    #pragma unroll
    for (int nt = 0; nt < 8; nt++) {
        int s0 = (cbase + nt * 8 + 2 * q) & 255;
        *(__nv_bfloat162*)&S->R[row0][s0]     = __floats2bfloat162_rn(accP[nt][0], accP[nt][1]);
        *(__nv_bfloat162*)&S->R[row0 + 8][s0] = __floats2bfloat162_rn(accP[nt][2], accP[nt][3]);
    }
}

__global__ void __launch_bounds__(128, 2) flash_kernel(const float* __restrict__ cb,
                                                       const float* __restrict__ pb) {
    extern __shared__ char raw[];
    FlashSmem* S = (FlashSmem*)raw;
    int z = blockIdx.y; int b = z >> 3, h = z & 7;
    int i0 = blockIdx.x * 64;
    int tid = threadIdx.x;
    int warp = tid >> 5, lane = tid & 31;
    int g = lane >> 2, q = lane & 3;
    int row0 = warp * 16 + g;
    const int base0 = 1024 - i0 - 128;

    const float* qsrc = g_q + ((size_t)(b * T + i0)) * D + h * 64;
    #pragma unroll
    for (int p = 0; p < 8; p++) {
        int idx = p * 128 + tid;
        int r = idx >> 4, c4 = (idx & 15) * 4;
        cpasync16(&S->Qs[r][c4], &qsrc[(size_t)r * D + c4], true);
    }
    #pragma unroll
    for (int p = 0; p < 4; p++) {
        int idx = p * 128 + tid;
        int r = idx >> 3, c8 = (idx & 7) * 8;
        int l0 = base0 + r;      l0 = min(max(l0, 0), LL - 1);
        int l1 = base0 + 64 + r; l1 = min(max(l1, 0), LL - 1);
        cpasync16(&S->Ps[0][r][c8 >> 1], &g_pb[((size_t)(b * LL + l0)) * D + h * 64 + c8], true);
        cpasync16(&S->Ps[1][r][c8 >> 1], &g_pb[((size_t)(b * LL + l1)) * D + h * 64 + c8], true);
    }
    asm volatile("cp.async.commit_group;");
    if (tid < 16) {
        *(float4*)&S->cbS[tid * 4] = *(const float4*)&cb[h * 64 + tid * 4];
        *(float4*)&S->pbS[tid * 4] = *(const float4*)&pb[h * 64 + tid * 4];
    }
    asm volatile("cp.async.wait_group 0;");
    __syncthreads();

    unsigned acf[4][4], apf[4][4];
    #pragma unroll
    for (int kb = 0; kb < 4; kb++) {
        int k0 = kb * 16 + 2 * q;
        float q00 = S->Qs[row0][k0],       q01 = S->Qs[row0][k0 + 1];
        float q10 = S->Qs[row0 + 8][k0],   q11 = S->Qs[row0 + 8][k0 + 1];
        float q02 = S->Qs[row0][k0 + 8],   q03 = S->Qs[row0][k0 + 9];
        float q12 = S->Qs[row0 + 8][k0 + 8], q13 = S->Qs[row0 + 8][k0 + 9];
        float c0 = S->cbS[k0], c1 = S->cbS[k0 + 1], c8v = S->cbS[k0 + 8], c9 = S->cbS[k0 + 9];
        float p0 = S->pbS[k0], p1 = S->pbS[k0 + 1], p8 = S->pbS[k0 + 8], p9 = S->pbS[k0 + 9];
        acf[kb][0] = pack_bf16(q00 + c0, q01 + c1);
        acf[kb][1] = pack_bf16(q10 + c0, q11 + c1);
        acf[kb][2] = pack_bf16(q02 + c8v, q03 + c9);
        acf[kb][3] = pack_bf16(q12 + c8v, q13 + c9);
        apf[kb][0] = pack_bf16(q00 + p0, q01 + p1);
        apf[kb][1] = pack_bf16(q10 + p0, q11 + p1);
        apf[kb][2] = pack_bf16(q02 + p8, q03 + p9);
        apf[kb][3] = pack_bf16(q12 + p8, q13 + p9);
    }

    pos_chunk(S, 0, base0, apf, row0, g, q);
    pos_chunk(S, 1, base0 + 64, apf, row0, g, q);
    __syncthreads();
    #pragma unroll
    for (int p = 0; p < 4; p++) {
        int idx = p * 128 + tid;
        int r = idx >> 3, c8 = (idx & 7) * 8;
        int l = base0 + 128 + r; l = min(max(l, 0), LL - 1);
        cpasync16(&S->Ps[0][r][c8 >> 1], &g_pb[((size_t)(b * LL + l)) * D + h * 64 + c8], true);
    }
    asm volatile("cp.async.commit_group;");
    asm volatile("cp.async.wait_group 0;");
    __syncthreads();
    pos_chunk(S, 0, base0 + 128, apf, row0, g, q);
    __syncthreads();

    {
        const __nv_bfloat16* kb_ = g_kb + ((size_t)(b * T)) * D + h * 64;
        const __nv_bfloat16* vt_ = g_vt + ((size_t)z) * 64 * 1024;
        #pragma unroll
        for (int p = 0; p < 4; p++) {
            int idx = p * 128 + tid;
            int r = idx >> 3, c8 = (idx & 7) * 8;
            cpasync16(&S->Ks[0][r][c8 >> 1], &kb_[(size_t)r * D + c8], true);
            cpasync16(&S->Vt[0][r][c8 >> 1], &vt_[(size_t)r * 1024 + c8], true);
            int l = base0 + 192 + r; l = min(max(l, 0), LL - 1);
            cpasync16(&S->Ps[0][r][c8 >> 1], &g_pb[((size_t)(b * LL + l)) * D + h * 64 + c8], true);
        }
        asm volatile("cp.async.commit_group;");
    }

    float accO[8][4] = {};
    float sumA = 0.f, sumB = 0.f;
    float gfixv = g_fixv[z];

    for (int jt = 0; jt < 16; jt++) {
        asm volatile("cp.async.wait_group 0;");
        __syncthreads();
        int st = jt & 1;
        if (jt < 15) {
            int st2 = st ^ 1;
            const __nv_bfloat16* kb_ = g_kb + ((size_t)(b * T + (jt + 1) * 64)) * D + h * 64;
            const __nv_bfloat16* vt_ = g_vt + ((size_t)z) * 64 * 1024 + (jt + 1) * 64;
            #pragma unroll
            for (int p = 0; p < 4; p++) {
                int idx = p * 128 + tid;
                int r = idx >> 3, c8 = (idx & 7) * 8;
                cpasync16(&S->Ks[st2][r][c8 >> 1], &kb_[(size_t)r * D + c8], true);
                cpasync16(&S->Vt[st2][r][c8 >> 1], &vt_[(size_t)r * 1024 + c8], true);
                int l = base0 + 192 + 64 * (jt + 1) + r; l = min(max(l, 0), LL - 1);
                cpasync16(&S->Ps[st2][r][c8 >> 1], &g_pb[((size_t)(b * LL + l)) * D + h * 64 + c8], true);
            }
            asm volatile("cp.async.commit_group;");
        }

        float accC[8][4] = {};
        #pragma unroll
        for (int kb2 = 0; kb2 < 4; kb2++) {
            #pragma unroll
            for (int nt = 0; nt < 8; nt++) {
                unsigned bf[2] = { S->Ks[st][nt * 8 + g][kb2 * 8 + q],
                                   S->Ks[st][nt * 8 + g][kb2 * 8 + q + 4] };
                mma_bf16(accC[nt], acf[kb2], bf);
            }
        }
        if (jt < 15) pos_chunk(S, st, base0 + 192 + 64 * jt, apf, row0, g, q);

        int basew = 1024 + 64 * jt - i0;
        bool fixc = (i0 == 0) && (jt == 15) && (warp == 0) && (g == 0) && (q == 3);
        #pragma unroll
        for (int kb2 = 0; kb2 < 4; kb2++) {
            unsigned a[4];
            #pragma unroll
            for (int half = 0; half < 2; half++) {
                int nt = kb2 * 2 + half;
                int jl = nt * 8 + 2 * q;
                int il0 = row0, il1 = row0 + 8;
                float r00 = __bfloat162float(S->R[il0][(basew + jl - il0) & 255]);
                float r01 = __bfloat162float(S->R[il0][(basew + jl + 1 - il0) & 255]);
                float r10 = __bfloat162float(S->R[il1][(basew + jl - il1) & 255]);
                float r11 = __bfloat162float(S->R[il1][(basew + jl + 1 - il1) & 255]);
                if (fixc && nt == 7) r01 = gfixv;
                float e0 = __expf((accC[nt][0] + r00) * 0.125f);
                float e1 = __expf((accC[nt][1] + r01) * 0.125f);
                float e2 = __expf((accC[nt][2] + r10) * 0.125f);
                float e3 = __expf((accC[nt][3] + r11) * 0.125f);
                sumA += e0 + e1; sumB += e2 + e3;
                a[half * 2]     = pack_bf16(e0, e1);
                a[half * 2 + 1] = pack_bf16(e2, e3);
            }
            unsigned af[4] = { a[0], a[1], a[2], a[3] };
            #pragma unroll
            for (int n2 = 0; n2 < 8; n2++) {
                unsigned bf[2] = { S->Vt[st][n2 * 8 + g][kb2 * 8 + q],
                                   S->Vt[st][n2 * 8 + g][kb2 * 8 + q + 4] };
                mma_bf16(accO[n2], af, bf);
            }
        }
    }

    sumA += __shfl_xor_sync(0xFFFFFFFFu, sumA, 1);
    sumA += __shfl_xor_sync(0xFFFFFFFFu, sumA, 2);
    sumB += __shfl_xor_sync(0xFFFFFFFFu, sumB, 1);
    sumB += __shfl_xor_sync(0xFFFFFFFFu, sumB, 2);
    float invA = 1.f / sumA, invB = 1.f / sumB;
    #pragma unroll
    for (int n2 = 0; n2 < 8; n2++) {
        int col = h * 64 + n2 * 8 + 2 * q;
        size_t r = (size_t)(b * T + i0 + row0);
        *(float2*)&g_o[r * D + col] = make_float2(accO[n2][0] * invA, accO[n2][1] * invA);
        *(float2*)&g_o[(r + 8) * D + col] = make_float2(accO[n2][2] * invB, accO[n2][3] * invB);
    }
}

extern "C" void kernel_launch(void* const* d_in, const int* in_sizes, int n_in,
                              void* d_out, int out_size) {
    const float* x     = (const float*)d_in[0];
    const float* pos   = (const float*)d_in[1];
    const float* cb    = (const float*)d_in[2];
    const float* pb    = (const float*)d_in[3];
    const float* gamma = (const float*)d_in[4];
    const float* beta  = (const float*)d_in[5];
    const float* Wq    = (const float*)d_in[6];
    const float* bq    = (const float*)d_in[7];
    const float* Wk    = (const float*)d_in[8];
    const float* bk    = (const float*)d_in[9];
    const float* Wv    = (const float*)d_in[10];
    const float* bv    = (const float*)d_in[11];
    const float* Wp    = (const float*)d_in[12];
    const float* Wo    = (const float*)d_in[13];
    const float* bo    = (const float*)d_in[14];
    float* out = (float*)d_out;

    float* o;
    cudaGetSymbolAddress((void**)&o, g_o);

    cudaFuncSetAttribute(qkvb_kernel, cudaFuncAttributeMaxDynamicSharedMemorySize,
                         (int)sizeof(ProjBSmem));
    cudaFuncSetAttribute(posproj_kernel, cudaFuncAttributeMaxDynamicSharedMemorySize,
                         (int)sizeof(ProjBSmem));
    cudaFuncSetAttribute(proj64, cudaFuncAttributeMaxDynamicSharedMemorySize,
                         (int)sizeof(Proj64Smem));
    cudaFuncSetAttribute(flash_kernel, cudaFuncAttributeMaxDynamicSharedMemorySize,
                         (int)sizeof(FlashSmem));

    // 1. converts + LayerNorm
    wt_kernel<<<dim3(16, 16, 4), 256>>>(Wq, Wk, Wv, Wp);
    posb_kernel<<<BL * 512 / 512, 256>>>(pos);
    ln_kernel<<<BT, 256>>>(x, gamma, beta);

    // 2. projections (bf16 m16n8k16): q/k/v fused + positional
    qkvb_kernel<<<dim3(4, 64, 3), 256, sizeof(ProjBSmem)>>>(bq, bk, bv);
    posproj_kernel<<<dim3(4, 128), 256, sizeof(ProjBSmem)>>>();

    // 3. v transpose+convert, wraparound fix value
    vt_kernel<<<dim3(8, 32), 256>>>();
    fix_kernel<<<BB * H, 32>>>(pb);

    // 4. fused flash attention (bf16 mma, 2 CTAs/SM)
    flash_kernel<<<dim3(16, 32), 128, sizeof(FlashSmem)>>>(cb, pb);

    // 5. output projection + bias + residual (tf32 for precision)
    proj64<<<dim3(4, 64), 256, sizeof(Proj64Smem)>>>(o, Wo, bo, x, out, BT);
}

// round 9
// speedup vs baseline: 2.6410x; 1.1578x over previous
#include <cuda_runtime.h>
#include <cuda_bf16.h>
#include <math.h>

#define BB 4
#define T 1024
#define D 512
#define H 8
#define LL 2047
#define BT (BB*T)      // 4096
#define BL (BB*LL)     // 8188

__device__ __nv_bfloat16 g_yb[BT*D];           // LN output, bf16
__device__ __nv_bfloat16 g_wt[4*512*512];      // transposed bf16 weights: q,k,v,p
__device__ __nv_bfloat16 g_posb[(size_t)BL*D]; // pos in bf16
__device__ float g_q[BT*D];    // q + bq (f32)
__device__ float g_o[BT*D];
__device__ __nv_bfloat16 g_kb[BT*D];
__device__ __nv_bfloat16 g_pb[(size_t)BL*D];
__device__ __nv_bfloat16 g_vt[(size_t)BB*H*64*1024];  // [b*H+h][d][j]

// ---------------- helpers ----------------
__device__ __forceinline__ unsigned f2tf(float f) {
    unsigned u; asm("cvt.rna.tf32.f32 %0, %1;" : "=r"(u) : "f"(f)); return u;
}
__device__ __forceinline__ unsigned pack_bf16(float a, float b) {
    __nv_bfloat162 h = __floats2bfloat162_rn(a, b);
    return *(unsigned*)&h;
}
__device__ __forceinline__ void mma_tf32(float d[4], const unsigned a[4], const unsigned b[2]) {
    asm volatile("mma.sync.aligned.m16n8k8.row.col.f32.tf32.tf32.f32 "
        "{%0,%1,%2,%3},{%4,%5,%6,%7},{%8,%9},{%0,%1,%2,%3};\n"
        : "+f"(d[0]), "+f"(d[1]), "+f"(d[2]), "+f"(d[3])
        : "r"(a[0]), "r"(a[1]), "r"(a[2]), "r"(a[3]), "r"(b[0]), "r"(b[1]));
}
__device__ __forceinline__ void mma_bf16(float d[4], const unsigned a[4], const unsigned b[2]) {
    asm volatile("mma.sync.aligned.m16n8k16.row.col.f32.bf16.bf16.f32 "
        "{%0,%1,%2,%3},{%4,%5,%6,%7},{%8,%9},{%0,%1,%2,%3};\n"
        : "+f"(d[0]), "+f"(d[1]), "+f"(d[2]), "+f"(d[3])
        : "r"(a[0]), "r"(a[1]), "r"(a[2]), "r"(a[3]), "r"(b[0]), "r"(b[1]));
}
__device__ __forceinline__ void cpasync16(void* dst, const void* src, bool pred) {
    unsigned d = (unsigned)__cvta_generic_to_shared(dst);
    int sz = pred ? 16 : 0;
    asm volatile("cp.async.cg.shared.global [%0], [%1], 16, %2;\n"
                 :: "r"(d), "l"(src), "r"(sz));
}

// ---------------- LayerNorm (writes bf16) ----------------
__global__ void ln_kernel(const float* __restrict__ x,
                          const float* __restrict__ gamma,
                          const float* __restrict__ beta) {
    int row = blockIdx.x;
    const float* xr = x + (size_t)row * D;
    __nv_bfloat16* yr = g_yb + (size_t)row * D;
    int t = threadIdx.x;  // 256
    float v0 = xr[t], v1 = xr[t + 256];
    float s = v0 + v1, sq = v0 * v0 + v1 * v1;
    __shared__ float ss[8], ssq[8], mb[2];
    #pragma unroll
    for (int o = 16; o > 0; o >>= 1) {
        s  += __shfl_xor_sync(0xFFFFFFFFu, s, o);
        sq += __shfl_xor_sync(0xFFFFFFFFu, sq, o);
    }
    if ((t & 31) == 0) { ss[t >> 5] = s; ssq[t >> 5] = sq; }
    __syncthreads();
    if (t == 0) {
        float S = 0.f, SQ = 0.f;
        #pragma unroll
        for (int i = 0; i < 8; i++) { S += ss[i]; SQ += ssq[i]; }
        float mean = S * (1.0f / D);
        float var = SQ * (1.0f / D) - mean * mean;
        mb[0] = mean;
        mb[1] = rsqrtf(var + 1e-3f);
    }
    __syncthreads();
    float mean = mb[0], rstd = mb[1];
    yr[t]       = __float2bfloat16_rn((v0 - mean) * rstd * gamma[t]       + beta[t]);
    yr[t + 256] = __float2bfloat16_rn((v1 - mean) * rstd * gamma[t + 256] + beta[t + 256]);
}

// ---------------- weight transpose + bf16 convert ----------------
__global__ void wt_kernel(const float* __restrict__ Wq, const float* __restrict__ Wk,
                          const float* __restrict__ Wv, const float* __restrict__ Wp) {
    __shared__ float tile[32][33];
    int z = blockIdx.z;
    const float* W = (z == 0) ? Wq : (z == 1) ? Wk : (z == 2) ? Wv : Wp;
    int k0 = blockIdx.y * 32, n0 = blockIdx.x * 32;
    int tid = threadIdx.x;
    #pragma unroll
    for (int p = 0; p < 4; p++) {
        int r = p * 8 + (tid >> 5), c = tid & 31;
        tile[r][c] = W[(size_t)(k0 + r) * 512 + n0 + c];
    }
    __syncthreads();
    #pragma unroll
    for (int p = 0; p < 4; p++) {
        int r = p * 8 + (tid >> 5), c = tid & 31;
        g_wt[(size_t)z * 262144 + (size_t)(n0 + r) * 512 + k0 + c] =
            __float2bfloat16_rn(tile[c][r]);
    }
}

// ---------------- pos -> bf16 ----------------
__global__ void posb_kernel(const float* __restrict__ pos) {
    size_t i = ((size_t)blockIdx.x * 256 + threadIdx.x) * 2;
    float2 v = *(const float2*)&pos[i];
    ((unsigned*)g_posb)[i >> 1] = pack_bf16(v.x, v.y);
}

// ---------------- unified bf16 projection: q/k/v/pos, 128x128x(K64) tiles ----------------
struct PSmem {
    unsigned As[2][128][36];   // 64 bf16 per row = 32 u32, pad 36
    unsigned Bs[2][128][36];
};

__device__ __forceinline__ void pall_load(PSmem* S, int buf,
                                          const __nv_bfloat16* A, const __nv_bfloat16* Bt,
                                          int i0, int j0, int kk, int M, int tid) {
    #pragma unroll
    for (int p = 0; p < 4; p++) {
        int idx = p * 256 + tid;
        int r = idx >> 3, c4 = (idx & 7) * 4;    // u32 col c4 -> bf16 offset 2*c4
        cpasync16(&S->As[buf][r][c4], &A[(size_t)(i0 + r) * 512 + kk + c4 * 2], (i0 + r) < M);
    }
    #pragma unroll
    for (int p = 0; p < 4; p++) {
        int idx = p * 256 + tid;
        int r = idx >> 3, c4 = (idx & 7) * 4;
        cpasync16(&S->Bs[buf][r][c4], &Bt[(size_t)(j0 + r) * 512 + kk + c4 * 2], true);
    }
    asm volatile("cp.async.commit_group;");
}

__global__ void __launch_bounds__(256, 2) projall_kernel(
        const float* __restrict__ bq, const float* __restrict__ bk,
        const float* __restrict__ bv) {
    extern __shared__ char raw[];
    PSmem* S = (PSmem*)raw;
    int y = blockIdx.y;
    int zi, i0;
    if (y < 96) { zi = y >> 5; i0 = (y & 31) * 128; }
    else        { zi = 3;      i0 = (y - 96) * 128; }
    int M = (zi == 3) ? BL : BT;
    const __nv_bfloat16* A  = (zi == 3) ? g_posb : g_yb;
    const __nv_bfloat16* Bt = g_wt + (size_t)zi * 262144;
    const float* bias = (zi == 0) ? bq : (zi == 1) ? bk : (zi == 2) ? bv : nullptr;
    int j0 = blockIdx.x * 128;
    int tid = threadIdx.x;
    int warp = tid >> 5, lane = tid & 31;
    int wy = warp >> 2, wx = warp & 3;     // 2(M) x 4(N); warp tile 64 x 32
    int g = lane >> 2, q = lane & 3;
    float acc[4][4][4] = {};

    pall_load(S, 0, A, Bt, i0, j0, 0, M, tid);
    for (int s = 0; s < 8; s++) {
        if (s < 7) {
            pall_load(S, (s + 1) & 1, A, Bt, i0, j0, (s + 1) * 64, M, tid);
            asm volatile("cp.async.wait_group 1;");
        } else {
            asm volatile("cp.async.wait_group 0;");
        }
        __syncthreads();
        int buf = s & 1;
        #pragma unroll
        for (int kb = 0; kb < 4; kb++) {
            unsigned af[4][4], bfv[4][2];
            #pragma unroll
            for (int mt = 0; mt < 4; mt++) {
                int r = wy * 64 + mt * 16 + g;
                af[mt][0] = S->As[buf][r][kb * 8 + q];
                af[mt][1] = S->As[buf][r + 8][kb * 8 + q];
                af[mt][2] = S->As[buf][r][kb * 8 + q + 4];
                af[mt][3] = S->As[buf][r + 8][kb * 8 + q + 4];
            }
            #pragma unroll
            for (int nt = 0; nt < 4; nt++) {
                int n = wx * 32 + nt * 8 + g;
                bfv[nt][0] = S->Bs[buf][n][kb * 8 + q];
                bfv[nt][1] = S->Bs[buf][n][kb * 8 + q + 4];
            }
            #pragma unroll
            for (int mt = 0; mt < 4; mt++)
                #pragma unroll
                for (int nt = 0; nt < 4; nt++)
                    mma_bf16(acc[mt][nt], af[mt], bfv[nt]);
        }
        __syncthreads();
    }

    if (zi == 2) {
        // V: stage tile in smem (bias added), then write transposed bf16 to g_vt
        __nv_bfloat16* st = (__nv_bfloat16*)S->As;   // pitch 130 bf16; 128*130*2B fits in As
        #pragma unroll
        for (int mt = 0; mt < 4; mt++)
            #pragma unroll
            for (int nt = 0; nt < 4; nt++) {
                int cl = wx * 32 + nt * 8 + q * 2;
                float b0 = bias[j0 + cl], b1 = bias[j0 + cl + 1];
                #pragma unroll
                for (int half = 0; half < 2; half++) {
                    int rl = wy * 64 + mt * 16 + g + half * 8;
                    *(unsigned*)&st[rl * 130 + cl] =
                        pack_bf16(acc[mt][nt][half * 2 + 0] + b0,
                                  acc[mt][nt][half * 2 + 1] + b1);
                }
            }
        __syncthreads();
        int b_ = i0 >> 10;
        int irow = i0 & 1023;
        #pragma unroll
        for (int rep = 0; rep < 32; rep++) {
            int dp = rep * 4 + (tid >> 6);          // local col 0..127
            int m2 = (tid & 63) * 2;                // row pair
            int gc = j0 + dp;
            int h_ = gc >> 6, d_ = gc & 63;
            __nv_bfloat162 hh;
            hh.x = st[m2 * 130 + dp];
            hh.y = st[(m2 + 1) * 130 + dp];
            *(unsigned*)&g_vt[(((size_t)(b_ * 8 + h_)) * 64 + d_) * 1024 + irow + m2] =
                *(unsigned*)&hh;
        }
        return;
    }

    #pragma unroll
    for (int mt = 0; mt < 4; mt++)
        #pragma unroll
        for (int nt = 0; nt < 4; nt++) {
            int c = j0 + wx * 32 + nt * 8 + q * 2;
            float b0 = bias ? bias[c] : 0.f;
            float b1 = bias ? bias[c + 1] : 0.f;
            #pragma unroll
            for (int half = 0; half < 2; half++) {
                int rr = i0 + wy * 64 + mt * 16 + g + half * 8;
                if (rr >= M) continue;
                float e0 = acc[mt][nt][half * 2 + 0] + b0;
                float e1 = acc[mt][nt][half * 2 + 1] + b1;
                if (zi == 0)
                    *(float2*)&g_q[(size_t)rr * 512 + c] = make_float2(e0, e1);
                else if (zi == 1)
                    ((unsigned*)g_kb)[((size_t)rr * 512 + c) >> 1] = pack_bf16(e0, e1);
                else
                    ((unsigned*)g_pb)[((size_t)rr * 512 + c) >> 1] = pack_bf16(e0, e1);
            }
        }
}

// ---------------- tf32 output projection (64x128 tile) ----------------
struct Proj64Smem {
    float As[2][64][36];
    float Bs[2][32][136];
};

__device__ __forceinline__ void proj64_load(Proj64Smem* S, int buf,
                                            const float* A, const float* W,
                                            int i0, int j0, int kk, int M, int tid) {
    #pragma unroll
    for (int p = 0; p < 2; p++) {
        int idx = p * 256 + tid;
        int r = idx >> 3, c4 = (idx & 7) * 4;
        cpasync16(&S->As[buf][r][c4], &A[(size_t)(i0 + r) * 512 + kk + c4], (i0 + r) < M);
    }
    #pragma unroll
    for (int p = 0; p < 4; p++) {
        int idx = p * 256 + tid;
        int k = idx >> 5, c4 = (idx & 31) * 4;
        cpasync16(&S->Bs[buf][k][c4], &W[(size_t)(kk + k) * 512 + j0 + c4], true);
    }
    asm volatile("cp.async.commit_group;");
}

__global__ void __launch_bounds__(256) proj64(
        const float* __restrict__ A, const float* __restrict__ W,
        const float* __restrict__ bias, const float* __restrict__ res,
        float* __restrict__ C, int M) {
    extern __shared__ char raw[];
    Proj64Smem* S = (Proj64Smem*)raw;
    int tid = threadIdx.x;
    int warp = tid >> 5, lane = tid & 31;
    int wy = warp >> 2, wx = warp & 3;
    int g = lane >> 2, q = lane & 3;
    int i0 = blockIdx.y * 64, j0 = blockIdx.x * 128;
    float acc[2][4][4] = {};
    proj64_load(S, 0, A, W, i0, j0, 0, M, tid);
    for (int s = 0; s < 16; s++) {
        if (s < 15) {
            proj64_load(S, (s + 1) & 1, A, W, i0, j0, (s + 1) * 32, M, tid);
            asm volatile("cp.async.wait_group 1;");
        } else {
            asm volatile("cp.async.wait_group 0;");
        }
        __syncthreads();
        int buf = s & 1;
        #pragma unroll
        for (int k8 = 0; k8 < 4; k8++) {
            int kc = k8 * 8 + q;
            unsigned af[2][4], bf[4][2];
            #pragma unroll
            for (int mt = 0; mt < 2; mt++) {
                int r = wy * 32 + mt * 16;
                af[mt][0] = f2tf(S->As[buf][r + g][kc]);
                af[mt][1] = f2tf(S->As[buf][r + g + 8][kc]);
                af[mt][2] = f2tf(S->As[buf][r + g][kc + 4]);
                af[mt][3] = f2tf(S->As[buf][r + g + 8][kc + 4]);
            }
            #pragma unroll
            for (int nt = 0; nt < 4; nt++) {
                int c = wx * 32 + nt * 8 + g;
                bf[nt][0] = f2tf(S->Bs[buf][kc][c]);
                bf[nt][1] = f2tf(S->Bs[buf][kc + 4][c]);
            }
            #pragma unroll
            for (int mt = 0; mt < 2; mt++)
                #pragma unroll
                for (int nt = 0; nt < 4; nt++)
                    mma_tf32(acc[mt][nt], af[mt], bf[nt]);
        }
        __syncthreads();
    }
    #pragma unroll
    for (int mt = 0; mt < 2; mt++)
        #pragma unroll
        for (int nt = 0; nt < 4; nt++) {
            int c = j0 + wx * 32 + nt * 8 + q * 2;
            float b0 = bias[c], b1 = bias[c + 1];
            #pragma unroll
            for (int half = 0; half < 2; half++) {
                int rr = i0 + wy * 32 + mt * 16 + g + half * 8;
                float e0 = acc[mt][nt][half * 2 + 0] + b0 + res[(size_t)rr * 512 + c];
                float e1 = acc[mt][nt][half * 2 + 1] + b1 + res[(size_t)rr * 512 + c + 1];
                *(float2*)&C[(size_t)rr * 512 + c] = make_float2(e0, e1);
            }
        }
}

// ---------------- flash attention: bf16 k16, 64-row tiles, 4 warps, 2 CTAs/SM ----------------
struct FlashSmem {
    unsigned Ks[2][64][36];
    unsigned Ps[2][64][36];
    unsigned Vt[2][64][36];
    __nv_bfloat16 R[64][264];
    float Qs[64][68];
    float cbS[64], pbS[64];
};

__device__ __forceinline__ void pos_chunk(FlashSmem* S, int stage, int cbase,
                                          const unsigned apf[4][4], int row0, int g, int q) {
    float accP[8][4] = {};
    #pragma unroll
    for (int kb = 0; kb < 4; kb++) {
        #pragma unroll
        for (int nt = 0; nt < 8; nt++) {
            unsigned bf[2] = { S->Ps[stage][nt * 8 + g][kb * 8 + q],
                               S->Ps[stage][nt * 8 + g][kb * 8 + q + 4] };
            mma_bf16(accP[nt], apf[kb], bf);
        }
    }
    #pragma unroll
    for (int nt = 0; nt < 8; nt++) {
        int s0 = (cbase + nt * 8 + 2 * q) & 255;
        *(__nv_bfloat162*)&S->R[row0][s0]     = __floats2bfloat162_rn(accP[nt][0], accP[nt][1]);
        *(__nv_bfloat162*)&S->R[row0 + 8][s0] = __floats2bfloat162_rn(accP[nt][2], accP[nt][3]);
    }
}

__global__ void __launch_bounds__(128, 2) flash_kernel(const float* __restrict__ cb,
                                                       const float* __restrict__ pb) {
    extern __shared__ char raw[];
    FlashSmem* S = (FlashSmem*)raw;
    int z = blockIdx.y; int b = z >> 3, h = z & 7;
    int i0 = blockIdx.x * 64;
    int tid = threadIdx.x;
    int warp = tid >> 5, lane = tid & 31;
    int g = lane >> 2, q = lane & 3;
    int row0 = warp * 16 + g;
    const int base0 = 1024 - i0 - 128;

    const float* qsrc = g_q + ((size_t)(b * T + i0)) * D + h * 64;
    #pragma unroll
    for (int p = 0; p < 8; p++) {
        int idx = p * 128 + tid;
        int r = idx >> 4, c4 = (idx & 15) * 4;
        cpasync16(&S->Qs[r][c4], &qsrc[(size_t)r * D + c4], true);
    }
    #pragma unroll
    for (int p = 0; p < 4; p++) {
        int idx = p * 128 + tid;
        int r = idx >> 3, c8 = (idx & 7) * 8;
        int l0 = base0 + r;      l0 = min(max(l0, 0), LL - 1);
        int l1 = base0 + 64 + r; l1 = min(max(l1, 0), LL - 1);
        cpasync16(&S->Ps[0][r][c8 >> 1], &g_pb[((size_t)(b * LL + l0)) * D + h * 64 + c8], true);
        cpasync16(&S->Ps[1][r][c8 >> 1], &g_pb[((size_t)(b * LL + l1)) * D + h * 64 + c8], true);
    }
    asm volatile("cp.async.commit_group;");
    if (tid < 16) {
        *(float4*)&S->cbS[tid * 4] = *(const float4*)&cb[h * 64 + tid * 4];
        *(float4*)&S->pbS[tid * 4] = *(const float4*)&pb[h * 64 + tid * 4];
    }

    // inline rel_shift wraparound value (only needed by i0==0 CTAs)
    float gfixv = 0.f;
    if (i0 == 0 && warp == 0) {
        float a0 = __bfloat162float(__float2bfloat16_rn(
            g_q[((size_t)(b * T + 1)) * D + h * 64 + lane] + pb[h * 64 + lane]));
        float a1 = __bfloat162float(__float2bfloat16_rn(
            g_q[((size_t)(b * T + 1)) * D + h * 64 + lane + 32] + pb[h * 64 + lane + 32]));
        float p0 = __bfloat162float(g_pb[((size_t)(b * LL)) * D + h * 64 + lane]);
        float p1 = __bfloat162float(g_pb[((size_t)(b * LL)) * D + h * 64 + lane + 32]);
        float sd = a0 * p0 + a1 * p1;
        #pragma unroll
        for (int o = 16; o > 0; o >>= 1) sd += __shfl_xor_sync(0xFFFFFFFFu, sd, o);
        gfixv = sd;
    }

    asm volatile("cp.async.wait_group 0;");
    __syncthreads();

    unsigned acf[4][4], apf[4][4];
    #pragma unroll
    for (int kb = 0; kb < 4; kb++) {
        int k0 = kb * 16 + 2 * q;
        float q00 = S->Qs[row0][k0],       q01 = S->Qs[row0][k0 + 1];
        float q10 = S->Qs[row0 + 8][k0],   q11 = S->Qs[row0 + 8][k0 + 1];
        float q02 = S->Qs[row0][k0 + 8],   q03 = S->Qs[row0][k0 + 9];
        float q12 = S->Qs[row0 + 8][k0 + 8], q13 = S->Qs[row0 + 8][k0 + 9];
        float c0 = S->cbS[k0], c1 = S->cbS[k0 + 1], c8v = S->cbS[k0 + 8], c9 = S->cbS[k0 + 9];
        float p0 = S->pbS[k0], p1 = S->pbS[k0 + 1], p8 = S->pbS[k0 + 8], p9 = S->pbS[k0 + 9];
        acf[kb][0] = pack_bf16(q00 + c0, q01 + c1);
        acf[kb][1] = pack_bf16(q10 + c0, q11 + c1);
        acf[kb][2] = pack_bf16(q02 + c8v, q03 + c9);
        acf[kb][3] = pack_bf16(q12 + c8v, q13 + c9);
        apf[kb][0] = pack_bf16(q00 + p0, q01 + p1);
        apf[kb][1] = pack_bf16(q10 + p0, q11 + p1);
        apf[kb][2] = pack_bf16(q02 + p8, q03 + p9);
        apf[kb][3] = pack_bf16(q12 + p8, q13 + p9);
    }

    pos_chunk(S, 0, base0, apf, row0, g, q);
    pos_chunk(S, 1, base0 + 64, apf, row0, g, q);
    __syncthreads();
    #pragma unroll
    for (int p = 0; p < 4; p++) {
        int idx = p * 128 + tid;
        int r = idx >> 3, c8 = (idx & 7) * 8;
        int l = base0 + 128 + r; l = min(max(l, 0), LL - 1);
        cpasync16(&S->Ps[0][r][c8 >> 1], &g_pb[((size_t)(b * LL + l)) * D + h * 64 + c8], true);
    }
    asm volatile("cp.async.commit_group;");
    asm volatile("cp.async.wait_group 0;");
    __syncthreads();
    pos_chunk(S, 0, base0 + 128, apf, row0, g, q);
    __syncthreads();

    {
        const __nv_bfloat16* kb_ = g_kb + ((size_t)(b * T)) * D + h * 64;
        const __nv_bfloat16* vt_ = g_vt + ((size_t)z) * 64 * 1024;
        #pragma unroll
        for (int p = 0; p < 4; p++) {
            int idx = p * 128 + tid;
            int r = idx >> 3, c8 = (idx & 7) * 8;
            cpasync16(&S->Ks[0][r][c8 >> 1], &kb_[(size_t)r * D + c8], true);
            cpasync16(&S->Vt[0][r][c8 >> 1], &vt_[(size_t)r * 1024 + c8], true);
            int l = base0 + 192 + r; l = min(max(l, 0), LL - 1);
            cpasync16(&S->Ps[0][r][c8 >> 1], &g_pb[((size_t)(b * LL + l)) * D + h * 64 + c8], true);
        }
        asm volatile("cp.async.commit_group;");
    }

    float accO[8][4] = {};
    float sumA = 0.f, sumB = 0.f;

    for (int jt = 0; jt < 16; jt++) {
        asm volatile("cp.async.wait_group 0;");
        __syncthreads();
        int st = jt & 1;
        if (jt < 15) {
            int st2 = st ^ 1;
            const __nv_bfloat16* kb_ = g_kb + ((size_t)(b * T + (jt + 1) * 64)) * D + h * 64;
            const __nv_bfloat16* vt_ = g_vt + ((size_t)z) * 64 * 1024 + (jt + 1) * 64;
            #pragma unroll
            for (int p = 0; p < 4; p++) {
                int idx = p * 128 + tid;
                int r = idx >> 3, c8 = (idx & 7) * 8;
                cpasync16(&S->Ks[st2][r][c8 >> 1], &kb_[(size_t)r * D + c8], true);
                cpasync16(&S->Vt[st2][r][c8 >> 1], &vt_[(size_t)r * 1024 + c8], true);
                int l = base0 + 192 + 64 * (jt + 1) + r; l = min(max(l, 0), LL - 1);
                cpasync16(&S->Ps[st2][r][c8 >> 1], &g_pb[((size_t)(b * LL + l)) * D + h * 64 + c8], true);
            }
            asm volatile("cp.async.commit_group;");
        }

        float accC[8][4] = {};
        #pragma unroll
        for (int kb2 = 0; kb2 < 4; kb2++) {
            #pragma unroll
            for (int nt = 0; nt < 8; nt++) {
                unsigned bf[2] = { S->Ks[st][nt * 8 + g][kb2 * 8 + q],
                                   S->Ks[st][nt * 8 + g][kb2 * 8 + q + 4] };
                mma_bf16(accC[nt], acf[kb2], bf);
            }
        }
        if (jt < 15) pos_chunk(S, st, base0 + 192 + 64 * jt, apf, row0, g, q);

        int basew = 1024 + 64 * jt - i0;
        bool fixc = (i0 == 0) && (jt == 15) && (warp == 0) && (g == 0) && (q == 3);
        #pragma unroll
        for (int kb2 = 0; kb2 < 4; kb2++) {
            unsigned a[4];
            #pragma unroll
            for (int half = 0; half < 2; half++) {
                int nt = kb2 * 2 + half;
                int jl = nt * 8 + 2 * q;
                int il0 = row0, il1 = row0 + 8;
                float r00 = __bfloat162float(S->R[il0][(basew + jl - il0) & 255]);
                float r01 = __bfloat162float(S->R[il0][(basew + jl + 1 - il0) & 255]);
                float r10 = __bfloat162float(S->R[il1][(basew + jl - il1) & 255]);
                float r11 = __bfloat162float(S->R[il1][(basew + jl + 1 - il1) & 255]);
                if (fixc && nt == 7) r01 = gfixv;
                float e0 = __expf((accC[nt][0] + r00) * 0.125f);
                float e1 = __expf((accC[nt][1] + r01) * 0.125f);
                float e2 = __expf((accC[nt][2] + r10) * 0.125f);
                float e3 = __expf((accC[nt][3] + r11) * 0.125f);
                sumA += e0 + e1; sumB += e2 + e3;
                a[half * 2]     = pack_bf16(e0, e1);
                a[half * 2 + 1] = pack_bf16(e2, e3);
            }
            unsigned af[4] = { a[0], a[1], a[2], a[3] };
            #pragma unroll
            for (int n2 = 0; n2 < 8; n2++) {
                unsigned bf[2] = { S->Vt[st][n2 * 8 + g][kb2 * 8 + q],
                                   S->Vt[st][n2 * 8 + g][kb2 * 8 + q + 4] };
                mma_bf16(accO[n2], af, bf);
            }
        }
    }

    sumA += __shfl_xor_sync(0xFFFFFFFFu, sumA, 1);
    sumA += __shfl_xor_sync(0xFFFFFFFFu, sumA, 2);
    sumB += __shfl_xor_sync(0xFFFFFFFFu, sumB, 1);
    sumB += __shfl_xor_sync(0xFFFFFFFFu, sumB, 2);
    float invA = 1.f / sumA, invB = 1.f / sumB;
    #pragma unroll
    for (int n2 = 0; n2 < 8; n2++) {
        int col = h * 64 + n2 * 8 + 2 * q;
        size_t r = (size_t)(b * T + i0 + row0);
        *(float2*)&g_o[r * D + col] = make_float2(accO[n2][0] * invA, accO[n2][1] * invA);
        *(float2*)&g_o[(r + 8) * D + col] = make_float2(accO[n2][2] * invB, accO[n2][3] * invB);
    }
}

extern "C" void kernel_launch(void* const* d_in, const int* in_sizes, int n_in,
                              void* d_out, int out_size) {
    const float* x     = (const float*)d_in[0];
    const float* pos   = (const float*)d_in[1];
    const float* cb    = (const float*)d_in[2];
    const float* pb    = (const float*)d_in[3];
    const float* gamma = (const float*)d_in[4];
    const float* beta  = (const float*)d_in[5];
    const float* Wq    = (const float*)d_in[6];
    const float* bq    = (const float*)d_in[7];
    const float* Wk    = (const float*)d_in[8];
    const float* bk    = (const float*)d_in[9];
    const float* Wv    = (const float*)d_in[10];
    const float* bv    = (const float*)d_in[11];
    const float* Wp    = (const float*)d_in[12];
    const float* Wo    = (const float*)d_in[13];
    const float* bo    = (const float*)d_in[14];
    float* out = (float*)d_out;

    float* o;
    cudaGetSymbolAddress((void**)&o, g_o);

    cudaFuncSetAttribute(projall_kernel, cudaFuncAttributeMaxDynamicSharedMemorySize,
                         (int)sizeof(PSmem));
    cudaFuncSetAttribute(proj64, cudaFuncAttributeMaxDynamicSharedMemorySize,
                         (int)sizeof(Proj64Smem));
    cudaFuncSetAttribute(flash_kernel, cudaFuncAttributeMaxDynamicSharedMemorySize,
                         (int)sizeof(FlashSmem));

    // 1. converts + LayerNorm
    wt_kernel<<<dim3(16, 16, 4), 256>>>(Wq, Wk, Wv, Wp);
    posb_kernel<<<BL * 512 / 512, 256>>>(pos);
    ln_kernel<<<BT, 256>>>(x, gamma, beta);

    // 2. unified projections (q/k/v/pos, bf16, 128x128 tiles; v written transposed)
    projall_kernel<<<dim3(4, 160), 256, sizeof(PSmem)>>>(bq, bk, bv);

    // 3. fused flash attention (bf16 mma, inline wraparound fix)
    flash_kernel<<<dim3(16, 32), 128, sizeof(FlashSmem)>>>(cb, pb);

    // 4. output projection + bias + residual (tf32 for precision)
    proj64<<<dim3(4, 64), 256, sizeof(Proj64Smem)>>>(o, Wo, bo, x, out, BT);
}

// round 10
// speedup vs baseline: 2.8520x; 1.0799x over previous
#include <cuda_runtime.h>
#include <cuda_bf16.h>
#include <math.h>

#define BB 4
#define T 1024
#define D 512
#define H 8
#define LL 2047
#define BT (BB*T)      // 4096
#define BL (BB*LL)     // 8188

__device__ __nv_bfloat16 g_yb[BT*D];           // LN output, bf16
__device__ __nv_bfloat16 g_wt[4*512*512];      // transposed bf16 weights: q,k,v,p
__device__ __nv_bfloat16 g_posb[(size_t)BL*D]; // pos in bf16
__device__ float g_q[BT*D];    // q + bq (f32)
__device__ float g_o[BT*D];
__device__ __nv_bfloat16 g_kb[BT*D];
__device__ __nv_bfloat16 g_pb[(size_t)BL*D];
__device__ __nv_bfloat16 g_vt[(size_t)BB*H*64*1024];  // [b*H+h][d][j]

// ---------------- helpers ----------------
__device__ __forceinline__ unsigned f2tf(float f) {
    unsigned u; asm("cvt.rna.tf32.f32 %0, %1;" : "=r"(u) : "f"(f)); return u;
}
__device__ __forceinline__ unsigned pack_bf16(float a, float b) {
    __nv_bfloat162 h = __floats2bfloat162_rn(a, b);
    return *(unsigned*)&h;
}
__device__ __forceinline__ unsigned sptr(const void* p) {
    return (unsigned)__cvta_generic_to_shared(p);
}
__device__ __forceinline__ void ldsm4(unsigned r[4], unsigned saddr) {
    asm volatile("ldmatrix.sync.aligned.m8n8.x4.shared.b16 {%0,%1,%2,%3}, [%4];"
        : "=r"(r[0]), "=r"(r[1]), "=r"(r[2]), "=r"(r[3]) : "r"(saddr));
}
__device__ __forceinline__ void mma_tf32(float d[4], const unsigned a[4], const unsigned b[2]) {
    asm volatile("mma.sync.aligned.m16n8k8.row.col.f32.tf32.tf32.f32 "
        "{%0,%1,%2,%3},{%4,%5,%6,%7},{%8,%9},{%0,%1,%2,%3};\n"
        : "+f"(d[0]), "+f"(d[1]), "+f"(d[2]), "+f"(d[3])
        : "r"(a[0]), "r"(a[1]), "r"(a[2]), "r"(a[3]), "r"(b[0]), "r"(b[1]));
}
__device__ __forceinline__ void mma_bf16(float d[4], const unsigned a[4], const unsigned b[2]) {
    asm volatile("mma.sync.aligned.m16n8k16.row.col.f32.bf16.bf16.f32 "
        "{%0,%1,%2,%3},{%4,%5,%6,%7},{%8,%9},{%0,%1,%2,%3};\n"
        : "+f"(d[0]), "+f"(d[1]), "+f"(d[2]), "+f"(d[3])
        : "r"(a[0]), "r"(a[1]), "r"(a[2]), "r"(a[3]), "r"(b[0]), "r"(b[1]));
}
__device__ __forceinline__ void cpasync16(void* dst, const void* src, bool pred) {
    unsigned d = (unsigned)__cvta_generic_to_shared(dst);
    int sz = pred ? 16 : 0;
    asm volatile("cp.async.cg.shared.global [%0], [%1], 16, %2;\n"
                 :: "r"(d), "l"(src), "r"(sz));
}

// ---------------- merged prep: weight transpose + pos->bf16 + LayerNorm ----------------
__global__ void prep_kernel(const float* __restrict__ x, const float* __restrict__ gamma,
                            const float* __restrict__ beta, const float* __restrict__ pos,
                            const float* __restrict__ Wq, const float* __restrict__ Wk,
                            const float* __restrict__ Wv, const float* __restrict__ Wp) {
    __shared__ float tile[32][33];
    __shared__ float ss[8], ssq[8], mb[2];
    int bid = blockIdx.x;
    int tid = threadIdx.x;
    if (bid < 1024) {
        int z = bid >> 8;
        int w = bid & 255;
        const float* W = (z == 0) ? Wq : (z == 1) ? Wk : (z == 2) ? Wv : Wp;
        int k0 = (w >> 4) * 32, n0 = (w & 15) * 32;
        #pragma unroll
        for (int p = 0; p < 4; p++) {
            int r = p * 8 + (tid >> 5), c = tid & 31;
            tile[r][c] = W[(size_t)(k0 + r) * 512 + n0 + c];
        }
        __syncthreads();
        #pragma unroll
        for (int p = 0; p < 4; p++) {
            int r = p * 8 + (tid >> 5), c = tid & 31;
            g_wt[(size_t)z * 262144 + (size_t)(n0 + r) * 512 + k0 + c] =
                __float2bfloat16_rn(tile[c][r]);
        }
    } else if (bid < 1024 + 8188) {
        size_t i = ((size_t)(bid - 1024) * 256 + tid) * 2;
        float2 v = *(const float2*)&pos[i];
        ((unsigned*)g_posb)[i >> 1] = pack_bf16(v.x, v.y);
    } else {
        int row = bid - 9212;
        const float* xr = x + (size_t)row * D;
        __nv_bfloat16* yr = g_yb + (size_t)row * D;
        float v0 = xr[tid], v1 = xr[tid + 256];
        float s = v0 + v1, sq = v0 * v0 + v1 * v1;
        #pragma unroll
        for (int o = 16; o > 0; o >>= 1) {
            s  += __shfl_xor_sync(0xFFFFFFFFu, s, o);
            sq += __shfl_xor_sync(0xFFFFFFFFu, sq, o);
        }
        if ((tid & 31) == 0) { ss[tid >> 5] = s; ssq[tid >> 5] = sq; }
        __syncthreads();
        if (tid == 0) {
            float S = 0.f, SQ = 0.f;
            #pragma unroll
            for (int i2 = 0; i2 < 8; i2++) { S += ss[i2]; SQ += ssq[i2]; }
            float mean = S * (1.0f / D);
            float var = SQ * (1.0f / D) - mean * mean;
            mb[0] = mean;
            mb[1] = rsqrtf(var + 1e-3f);
        }
        __syncthreads();
        float mean = mb[0], rstd = mb[1];
        yr[tid]       = __float2bfloat16_rn((v0 - mean) * rstd * gamma[tid]       + beta[tid]);
        yr[tid + 256] = __float2bfloat16_rn((v1 - mean) * rstd * gamma[tid + 256] + beta[tid + 256]);
    }
}

// ---------------- unified bf16 projection: q/k/v/pos, 128x128x(K64) tiles, 3-stage ----------------
struct PSmem {
    unsigned As[3][128][36];   // 64 bf16 per row = 32 u32, pad 36
    unsigned Bs[3][128][36];
};

__device__ __forceinline__ void pall_load(PSmem* S, int buf,
                                          const __nv_bfloat16* A, const __nv_bfloat16* Bt,
                                          int i0, int j0, int kk, int M, int tid) {
    #pragma unroll
    for (int p = 0; p < 4; p++) {
        int idx = p * 256 + tid;
        int r = idx >> 3, c4 = (idx & 7) * 4;
        cpasync16(&S->As[buf][r][c4], &A[(size_t)(i0 + r) * 512 + kk + c4 * 2], (i0 + r) < M);
    }
    #pragma unroll
    for (int p = 0; p < 4; p++) {
        int idx = p * 256 + tid;
        int r = idx >> 3, c4 = (idx & 7) * 4;
        cpasync16(&S->Bs[buf][r][c4], &Bt[(size_t)(j0 + r) * 512 + kk + c4 * 2], true);
    }
    asm volatile("cp.async.commit_group;");
}

__global__ void __launch_bounds__(256, 2) projall_kernel(
        const float* __restrict__ bq, const float* __restrict__ bk,
        const float* __restrict__ bv) {
    extern __shared__ char raw[];
    PSmem* S = (PSmem*)raw;
    int y = blockIdx.y;
    int zi, i0;
    if (y < 96) { zi = y >> 5; i0 = (y & 31) * 128; }
    else        { zi = 3;      i0 = (y - 96) * 128; }
    int M = (zi == 3) ? BL : BT;
    const __nv_bfloat16* A  = (zi == 3) ? g_posb : g_yb;
    const __nv_bfloat16* Bt = g_wt + (size_t)zi * 262144;
    const float* bias = (zi == 0) ? bq : (zi == 1) ? bk : (zi == 2) ? bv : nullptr;
    int j0 = blockIdx.x * 128;
    int tid = threadIdx.x;
    int warp = tid >> 5, lane = tid & 31;
    int wy = warp >> 2, wx = warp & 3;     // 2(M) x 4(N); warp tile 64 x 32
    int g = lane >> 2, q = lane & 3;
    // ldmatrix lane selectors
    int rsel = lane & 15;
    int csel = (lane & 16) ? 4 : 0;
    int nsel = (lane & 7) + ((lane & 16) ? 8 : 0);
    int bcsel = (lane & 8) ? 4 : 0;
    float acc[4][4][4] = {};

    pall_load(S, 0, A, Bt, i0, j0, 0, M, tid);
    pall_load(S, 1, A, Bt, i0, j0, 64, M, tid);
    int buf = 0, ldb = 2;
    for (int s = 0; s < 8; s++) {
        if (s < 7) asm volatile("cp.async.wait_group 1;");
        else       asm volatile("cp.async.wait_group 0;");
        __syncthreads();
        if (s < 6) {
            pall_load(S, ldb, A, Bt, i0, j0, (s + 2) * 64, M, tid);
            ldb = (ldb == 2) ? 0 : ldb + 1;
        }
        unsigned abase[4], bbase[2];
        #pragma unroll
        for (int mt = 0; mt < 4; mt++)
            abase[mt] = sptr(&S->As[buf][wy * 64 + mt * 16 + rsel][csel]);
        #pragma unroll
        for (int ntp = 0; ntp < 2; ntp++)
            bbase[ntp] = sptr(&S->Bs[buf][wx * 32 + ntp * 16 + nsel][bcsel]);
        #pragma unroll
        for (int kb = 0; kb < 4; kb++) {
            unsigned afr[4][4], bfr[2][4];
            #pragma unroll
            for (int mt = 0; mt < 4; mt++) ldsm4(afr[mt], abase[mt] + kb * 32);
            #pragma unroll
            for (int ntp = 0; ntp < 2; ntp++) ldsm4(bfr[ntp], bbase[ntp] + kb * 32);
            #pragma unroll
            for (int mt = 0; mt < 4; mt++)
                #pragma unroll
                for (int nt = 0; nt < 4; nt++)
                    mma_bf16(acc[mt][nt], afr[mt], &bfr[nt >> 1][(nt & 1) * 2]);
        }
        buf = (buf == 2) ? 0 : buf + 1;
    }

    if (zi == 2) {
        // V: stage tile in smem (bias added), then write transposed bf16 to g_vt
        __syncthreads();   // protect As reuse as staging buffer
        __nv_bfloat16* st = (__nv_bfloat16*)S->As;   // pitch 130 bf16
        #pragma unroll
        for (int mt = 0; mt < 4; mt++)
            #pragma unroll
            for (int nt = 0; nt < 4; nt++) {
                int cl = wx * 32 + nt * 8 + q * 2;
                float b0 = bias[j0 + cl], b1 = bias[j0 + cl + 1];
                #pragma unroll
                for (int half = 0; half < 2; half++) {
                    int rl = wy * 64 + mt * 16 + g + half * 8;
                    *(unsigned*)&st[rl * 130 + cl] =
                        pack_bf16(acc[mt][nt][half * 2 + 0] + b0,
                                  acc[mt][nt][half * 2 + 1] + b1);
                }
            }
        __syncthreads();
        int b_ = i0 >> 10;
        int irow = i0 & 1023;
        #pragma unroll
        for (int rep = 0; rep < 32; rep++) {
            int dp = rep * 4 + (tid >> 6);          // local col 0..127
            int m2 = (tid & 63) * 2;                // row pair
            int gc = j0 + dp;
            int h_ = gc >> 6, d_ = gc & 63;
            __nv_bfloat162 hh;
            hh.x = st[m2 * 130 + dp];
            hh.y = st[(m2 + 1) * 130 + dp];
            *(unsigned*)&g_vt[(((size_t)(b_ * 8 + h_)) * 64 + d_) * 1024 + irow + m2] =
                *(unsigned*)&hh;
        }
        return;
    }

    #pragma unroll
    for (int mt = 0; mt < 4; mt++)
        #pragma unroll
        for (int nt = 0; nt < 4; nt++) {
            int c = j0 + wx * 32 + nt * 8 + q * 2;
            float b0 = bias ? bias[c] : 0.f;
            float b1 = bias ? bias[c + 1] : 0.f;
            #pragma unroll
            for (int half = 0; half < 2; half++) {
                int rr = i0 + wy * 64 + mt * 16 + g + half * 8;
                if (rr >= M) continue;
                float e0 = acc[mt][nt][half * 2 + 0] + b0;
                float e1 = acc[mt][nt][half * 2 + 1] + b1;
                if (zi == 0)
                    *(float2*)&g_q[(size_t)rr * 512 + c] = make_float2(e0, e1);
                else if (zi == 1)
                    ((unsigned*)g_kb)[((size_t)rr * 512 + c) >> 1] = pack_bf16(e0, e1);
                else
                    ((unsigned*)g_pb)[((size_t)rr * 512 + c) >> 1] = pack_bf16(e0, e1);
            }
        }
}

// ---------------- tf32 output projection (64x128 tile, single-sync) ----------------
struct Proj64Smem {
    float As[2][64][36];
    float Bs[2][32][136];
};

__device__ __forceinline__ void proj64_load(Proj64Smem* S, int buf,
                                            const float* A, const float* W,
                                            int i0, int j0, int kk, int M, int tid) {
    #pragma unroll
    for (int p = 0; p < 2; p++) {
        int idx = p * 256 + tid;
        int r = idx >> 3, c4 = (idx & 7) * 4;
        cpasync16(&S->As[buf][r][c4], &A[(size_t)(i0 + r) * 512 + kk + c4], (i0 + r) < M);
    }
    #pragma unroll
    for (int p = 0; p < 4; p++) {
        int idx = p * 256 + tid;
        int k = idx >> 5, c4 = (idx & 31) * 4;
        cpasync16(&S->Bs[buf][k][c4], &W[(size_t)(kk + k) * 512 + j0 + c4], true);
    }
    asm volatile("cp.async.commit_group;");
}

__global__ void __launch_bounds__(256) proj64(
        const float* __restrict__ A, const float* __restrict__ W,
        const float* __restrict__ bias, const float* __restrict__ res,
        float* __restrict__ C, int M) {
    extern __shared__ char raw[];
    Proj64Smem* S = (Proj64Smem*)raw;
    int tid = threadIdx.x;
    int warp = tid >> 5, lane = tid & 31;
    int wy = warp >> 2, wx = warp & 3;
    int g = lane >> 2, q = lane & 3;
    int i0 = blockIdx.y * 64, j0 = blockIdx.x * 128;
    float acc[2][4][4] = {};
    proj64_load(S, 0, A, W, i0, j0, 0, M, tid);
    for (int s = 0; s < 16; s++) {
        asm volatile("cp.async.wait_group 0;");
        __syncthreads();
        if (s < 15)
            proj64_load(S, (s + 1) & 1, A, W, i0, j0, (s + 1) * 32, M, tid);
        int buf = s & 1;
        #pragma unroll
        for (int k8 = 0; k8 < 4; k8++) {
            int kc = k8 * 8 + q;
            unsigned af[2][4], bf[4][2];
            #pragma unroll
            for (int mt = 0; mt < 2; mt++) {
                int r = wy * 32 + mt * 16;
                af[mt][0] = f2tf(S->As[buf][r + g][kc]);
                af[mt][1] = f2tf(S->As[buf][r + g + 8][kc]);
                af[mt][2] = f2tf(S->As[buf][r + g][kc + 4]);
                af[mt][3] = f2tf(S->As[buf][r + g + 8][kc + 4]);
            }
            #pragma unroll
            for (int nt = 0; nt < 4; nt++) {
                int c = wx * 32 + nt * 8 + g;
                bf[nt][0] = f2tf(S->Bs[buf][kc][c]);
                bf[nt][1] = f2tf(S->Bs[buf][kc + 4][c]);
            }
            #pragma unroll
            for (int mt = 0; mt < 2; mt++)
                #pragma unroll
                for (int nt = 0; nt < 4; nt++)
                    mma_tf32(acc[mt][nt], af[mt], bf[nt]);
        }
    }
    #pragma unroll
    for (int mt = 0; mt < 2; mt++)
        #pragma unroll
        for (int nt = 0; nt < 4; nt++) {
            int c = j0 + wx * 32 + nt * 8 + q * 2;
            float b0 = bias[c], b1 = bias[c + 1];
            #pragma unroll
            for (int half = 0; half < 2; half++) {
                int rr = i0 + wy * 32 + mt * 16 + g + half * 8;
                float e0 = acc[mt][nt][half * 2 + 0] + b0 + res[(size_t)rr * 512 + c];
                float e1 = acc[mt][nt][half * 2 + 1] + b1 + res[(size_t)rr * 512 + c + 1];
                *(float2*)&C[(size_t)rr * 512 + c] = make_float2(e0, e1);
            }
        }
}

// ---------------- flash attention: bf16 k16, ldmatrix operands, 2 CTAs/SM ----------------
struct FlashSmem {
    unsigned Ks[2][64][36];
    unsigned Ps[2][64][36];
    unsigned Vt[2][64][36];
    __nv_bfloat16 R[64][264];
    float Qs[64][68];
    float cbS[64], pbS[64];
};

__device__ __forceinline__ void pos_chunk(FlashSmem* S, int stage, int cbase,
                                          const unsigned apf[4][4], int row0,
                                          int nsel, int bcsel, int q) {
    float accP[8][4] = {};
    #pragma unroll
    for (int ntp = 0; ntp < 4; ntp++) {
        unsigned base = sptr(&S->Ps[stage][ntp * 16 + nsel][bcsel]);
        #pragma unroll
        for (int kb = 0; kb < 4; kb++) {
            unsigned bfr[4];
            ldsm4(bfr, base + kb * 32);
            mma_bf16(accP[ntp * 2],     apf[kb], bfr);
            mma_bf16(accP[ntp * 2 + 1], apf[kb], bfr + 2);
        }
    }
    #pragma unroll
    for (int nt = 0; nt < 8; nt++) {
        int s0 = (cbase + nt * 8 + 2 * q) & 255;
        *(__nv_bfloat162*)&S->R[row0][s0]     = __floats2bfloat162_rn(accP[nt][0], accP[nt][1]);
        *(__nv_bfloat162*)&S->R[row0 + 8][s0] = __floats2bfloat162_rn(accP[nt][2], accP[nt][3]);
    }
}

__global__ void __launch_bounds__(128, 2) flash_kernel(const float* __restrict__ cb,
                                                       const float* __restrict__ pb) {
    extern __shared__ char raw[];
    FlashSmem* S = (FlashSmem*)raw;
    int z = blockIdx.y; int b = z >> 3, h = z & 7;
    int i0 = blockIdx.x * 64;
    int tid = threadIdx.x;
    int warp = tid >> 5, lane = tid & 31;
    int g = lane >> 2, q = lane & 3;
    int row0 = warp * 16 + g;
    int nsel = (lane & 7) + ((lane & 16) ? 8 : 0);
    int bcsel = (lane & 8) ? 4 : 0;
    const int base0 = 1024 - i0 - 128;

    const float* qsrc = g_q + ((size_t)(b * T + i0)) * D + h * 64;
    #pragma unroll
    for (int p = 0; p < 8; p++) {
        int idx = p * 128 + tid;
        int r = idx >> 4, c4 = (idx & 15) * 4;
        cpasync16(&S->Qs[r][c4], &qsrc[(size_t)r * D + c4], true);
    }
    #pragma unroll
    for (int p = 0; p < 4; p++) {
        int idx = p * 128 + tid;
        int r = idx >> 3, c8 = (idx & 7) * 8;
        int l0 = base0 + r;      l0 = min(max(l0, 0), LL - 1);
        int l1 = base0 + 64 + r; l1 = min(max(l1, 0), LL - 1);
        cpasync16(&S->Ps[0][r][c8 >> 1], &g_pb[((size_t)(b * LL + l0)) * D + h * 64 + c8], true);
        cpasync16(&S->Ps[1][r][c8 >> 1], &g_pb[((size_t)(b * LL + l1)) * D + h * 64 + c8], true);
    }
    asm volatile("cp.async.commit_group;");
    if (tid < 16) {
        *(float4*)&S->cbS[tid * 4] = *(const float4*)&cb[h * 64 + tid * 4];
        *(float4*)&S->pbS[tid * 4] = *(const float4*)&pb[h * 64 + tid * 4];
    }

    // inline rel_shift wraparound value (only needed by i0==0 CTAs)
    float gfixv = 0.f;
    if (i0 == 0 && warp == 0) {
        float a0 = __bfloat162float(__float2bfloat16_rn(
            g_q[((size_t)(b * T + 1)) * D + h * 64 + lane] + pb[h * 64 + lane]));
        float a1 = __bfloat162float(__float2bfloat16_rn(
            g_q[((size_t)(b * T + 1)) * D + h * 64 + lane + 32] + pb[h * 64 + lane + 32]));
        float p0 = __bfloat162float(g_pb[((size_t)(b * LL)) * D + h * 64 + lane]);
        float p1 = __bfloat162float(g_pb[((size_t)(b * LL)) * D + h * 64 + lane + 32]);
        float sd = a0 * p0 + a1 * p1;
        #pragma unroll
        for (int o = 16; o > 0; o >>= 1) sd += __shfl_xor_sync(0xFFFFFFFFu, sd, o);
        gfixv = sd;
    }

    asm volatile("cp.async.wait_group 0;");
    __syncthreads();

    unsigned acf[4][4], apf[4][4];
    #pragma unroll
    for (int kb = 0; kb < 4; kb++) {
        int k0 = kb * 16 + 2 * q;
        float q00 = S->Qs[row0][k0],       q01 = S->Qs[row0][k0 + 1];
        float q10 = S->Qs[row0 + 8][k0],   q11 = S->Qs[row0 + 8][k0 + 1];
        float q02 = S->Qs[row0][k0 + 8],   q03 = S->Qs[row0][k0 + 9];
        float q12 = S->Qs[row0 + 8][k0 + 8], q13 = S->Qs[row0 + 8][k0 + 9];
        float c0 = S->cbS[k0], c1 = S->cbS[k0 + 1], c8v = S->cbS[k0 + 8], c9 = S->cbS[k0 + 9];
        float p0 = S->pbS[k0], p1 = S->pbS[k0 + 1], p8 = S->pbS[k0 + 8], p9 = S->pbS[k0 + 9];
        acf[kb][0] = pack_bf16(q00 + c0, q01 + c1);
        acf[kb][1] = pack_bf16(q10 + c0, q11 + c1);
        acf[kb][2] = pack_bf16(q02 + c8v, q03 + c9);
        acf[kb][3] = pack_bf16(q12 + c8v, q13 + c9);
        apf[kb][0] = pack_bf16(q00 + p0, q01 + p1);
        apf[kb][1] = pack_bf16(q10 + p0, q11 + p1);
        apf[kb][2] = pack_bf16(q02 + p8, q03 + p9);
        apf[kb][3] = pack_bf16(q12 + p8, q13 + p9);
    }

    pos_chunk(S, 0, base0, apf, row0, nsel, bcsel, q);
    pos_chunk(S, 1, base0 + 64, apf, row0, nsel, bcsel, q);
    __syncthreads();
    #pragma unroll
    for (int p = 0; p < 4; p++) {
        int idx = p * 128 + tid;
        int r = idx >> 3, c8 = (idx & 7) * 8;
        int l = base0 + 128 + r; l = min(max(l, 0), LL - 1);
        cpasync16(&S->Ps[0][r][c8 >> 1], &g_pb[((size_t)(b * LL + l)) * D + h * 64 + c8], true);
    }
    asm volatile("cp.async.commit_group;");
    asm volatile("cp.async.wait_group 0;");
    __syncthreads();
    pos_chunk(S, 0, base0 + 128, apf, row0, nsel, bcsel, q);
    __syncthreads();

    {
        const __nv_bfloat16* kb_ = g_kb + ((size_t)(b * T)) * D + h * 64;
        const __nv_bfloat16* vt_ = g_vt + ((size_t)z) * 64 * 1024;
        #pragma unroll
        for (int p = 0; p < 4; p++) {
            int idx = p * 128 + tid;
            int r = idx >> 3, c8 = (idx & 7) * 8;
            cpasync16(&S->Ks[0][r][c8 >> 1], &kb_[(size_t)r * D + c8], true);
            cpasync16(&S->Vt[0][r][c8 >> 1], &vt_[(size_t)r * 1024 + c8], true);
            int l = base0 + 192 + r; l = min(max(l, 0), LL - 1);
            cpasync16(&S->Ps[0][r][c8 >> 1], &g_pb[((size_t)(b * LL + l)) * D + h * 64 + c8], true);
        }
        asm volatile("cp.async.commit_group;");
    }

    float accO[8][4] = {};
    float sumA = 0.f, sumB = 0.f;

    for (int jt = 0; jt < 16; jt++) {
        asm volatile("cp.async.wait_group 0;");
        __syncthreads();
        int st = jt & 1;
        if (jt < 15) {
            int st2 = st ^ 1;
            const __nv_bfloat16* kb_ = g_kb + ((size_t)(b * T + (jt + 1) * 64)) * D + h * 64;
            const __nv_bfloat16* vt_ = g_vt + ((size_t)z) * 64 * 1024 + (jt + 1) * 64;
            #pragma unroll
            for (int p = 0; p < 4; p++) {
                int idx = p * 128 + tid;
                int r = idx >> 3, c8 = (idx & 7) * 8;
                cpasync16(&S->Ks[st2][r][c8 >> 1], &kb_[(size_t)r * D + c8], true);
                cpasync16(&S->Vt[st2][r][c8 >> 1], &vt_[(size_t)r * 1024 + c8], true);
                int l = base0 + 192 + 64 * (jt + 1) + r; l = min(max(l, 0), LL - 1);
                cpasync16(&S->Ps[st2][r][c8 >> 1], &g_pb[((size_t)(b * LL + l)) * D + h * 64 + c8], true);
            }
            asm volatile("cp.async.commit_group;");
        }

        // content scores via ldmatrix
        float accC[8][4] = {};
        #pragma unroll
        for (int ntp = 0; ntp < 4; ntp++) {
            unsigned base = sptr(&S->Ks[st][ntp * 16 + nsel][bcsel]);
            #pragma unroll
            for (int kb2 = 0; kb2 < 4; kb2++) {
                unsigned bfr[4];
                ldsm4(bfr, base + kb2 * 32);
                mma_bf16(accC[ntp * 2],     acf[kb2], bfr);
                mma_bf16(accC[ntp * 2 + 1], acf[kb2], bfr + 2);
            }
        }
        if (jt < 15) pos_chunk(S, st, base0 + 192 + 64 * jt, apf, row0, nsel, bcsel, q);

        // V bases for this stage
        unsigned vbase[4];
        #pragma unroll
        for (int n2p = 0; n2p < 4; n2p++)
            vbase[n2p] = sptr(&S->Vt[st][n2p * 16 + nsel][bcsel]);

        int basew = 1024 + 64 * jt - i0;
        bool fixc = (i0 == 0) && (jt == 15) && (warp == 0) && (g == 0) && (q == 3);
        #pragma unroll
        for (int kb2 = 0; kb2 < 4; kb2++) {
            unsigned a[4];
            #pragma unroll
            for (int half = 0; half < 2; half++) {
                int nt = kb2 * 2 + half;
                int jl = nt * 8 + 2 * q;
                int il0 = row0, il1 = row0 + 8;
                float r00 = __bfloat162float(S->R[il0][(basew + jl - il0) & 255]);
                float r01 = __bfloat162float(S->R[il0][(basew + jl + 1 - il0) & 255]);
                float r10 = __bfloat162float(S->R[il1][(basew + jl - il1) & 255]);
                float r11 = __bfloat162float(S->R[il1][(basew + jl + 1 - il1) & 255]);
                if (fixc && nt == 7) r01 = gfixv;
                float e0 = __expf((accC[nt][0] + r00) * 0.125f);
                float e1 = __expf((accC[nt][1] + r01) * 0.125f);
                float e2 = __expf((accC[nt][2] + r10) * 0.125f);
                float e3 = __expf((accC[nt][3] + r11) * 0.125f);
                sumA += e0 + e1; sumB += e2 + e3;
                a[half * 2]     = pack_bf16(e0, e1);
                a[half * 2 + 1] = pack_bf16(e2, e3);
            }
            #pragma unroll
            for (int n2p = 0; n2p < 4; n2p++) {
                unsigned vfr[4];
                ldsm4(vfr, vbase[n2p] + kb2 * 32);
                mma_bf16(accO[n2p * 2],     a, vfr);
                mma_bf16(accO[n2p * 2 + 1], a, vfr + 2);
            }
        }
    }

    sumA += __shfl_xor_sync(0xFFFFFFFFu, sumA, 1);
    sumA += __shfl_xor_sync(0xFFFFFFFFu, sumA, 2);
    sumB += __shfl_xor_sync(0xFFFFFFFFu, sumB, 1);
    sumB += __shfl_xor_sync(0xFFFFFFFFu, sumB, 2);
    float invA = 1.f / sumA, invB = 1.f / sumB;
    #pragma unroll
    for (int n2 = 0; n2 < 8; n2++) {
        int col = h * 64 + n2 * 8 + 2 * q;
        size_t r = (size_t)(b * T + i0 + row0);
        *(float2*)&g_o[r * D + col] = make_float2(accO[n2][0] * invA, accO[n2][1] * invA);
        *(float2*)&g_o[(r + 8) * D + col] = make_float2(accO[n2][2] * invB, accO[n2][3] * invB);
    }
}

extern "C" void kernel_launch(void* const* d_in, const int* in_sizes, int n_in,
                              void* d_out, int out_size) {
    const float* x     = (const float*)d_in[0];
    const float* pos   = (const float*)d_in[1];
    const float* cb    = (const float*)d_in[2];
    const float* pb    = (const float*)d_in[3];
    const float* gamma = (const float*)d_in[4];
    const float* beta  = (const float*)d_in[5];
    const float* Wq    = (const float*)d_in[6];
    const float* bq    = (const float*)d_in[7];
    const float* Wk    = (const float*)d_in[8];
    const float* bk    = (const float*)d_in[9];
    const float* Wv    = (const float*)d_in[10];
    const float* bv    = (const float*)d_in[11];
    const float* Wp    = (const float*)d_in[12];
    const float* Wo    = (const float*)d_in[13];
    const float* bo    = (const float*)d_in[14];
    float* out = (float*)d_out;

    float* o;
    cudaGetSymbolAddress((void**)&o, g_o);

    cudaFuncSetAttribute(projall_kernel, cudaFuncAttributeMaxDynamicSharedMemorySize,
                         (int)sizeof(PSmem));
    cudaFuncSetAttribute(proj64, cudaFuncAttributeMaxDynamicSharedMemorySize,
                         (int)sizeof(Proj64Smem));
    cudaFuncSetAttribute(flash_kernel, cudaFuncAttributeMaxDynamicSharedMemorySize,
                         (int)sizeof(FlashSmem));

    // 1. merged prep: weight transpose + pos convert + LayerNorm
    prep_kernel<<<13308, 256>>>(x, gamma, beta, pos, Wq, Wk, Wv, Wp);

    // 2. unified projections (q/k/v/pos, bf16, ldmatrix, 3-stage pipeline)
    projall_kernel<<<dim3(4, 160), 256, sizeof(PSmem)>>>(bq, bk, bv);

    // 3. fused flash attention (bf16 mma, ldmatrix operands)
    flash_kernel<<<dim3(16, 32), 128, sizeof(FlashSmem)>>>(cb, pb);

    // 4. output projection + bias + residual (tf32 for precision)
    proj64<<<dim3(4, 64), 256, sizeof(Proj64Smem)>>>(o, Wo, bo, x, out, BT);
}

// round 11
// speedup vs baseline: 3.1480x; 1.1038x over previous
#include <cuda_runtime.h>
#include <cuda_bf16.h>
#include <cuda_fp16.h>
#include <math.h>

#define BB 4
#define T 1024
#define D 512
#define H 8
#define LL 2047
#define BT (BB*T)      // 4096
#define BL (BB*LL)     // 8188

__device__ __nv_bfloat16 g_yb[BT*D];           // LN output, bf16
__device__ __nv_bfloat16 g_wt[4*512*512];      // transposed bf16 weights: q,k,v,p
__device__ __half        g_wto[512*512];       // transposed fp16 Wo
__device__ __nv_bfloat16 g_posb[(size_t)BL*D]; // pos in bf16
__device__ float g_q[BT*D];    // q + bq (f32)
__device__ __half g_oh[BT*D];  // attention output, fp16
__device__ __nv_bfloat16 g_kb[BT*D];
__device__ __nv_bfloat16 g_pb[(size_t)BL*D];
__device__ __nv_bfloat16 g_vt[(size_t)BB*H*64*1024];  // [b*H+h][d][j]

// ---------------- helpers ----------------
__device__ __forceinline__ unsigned pack_bf16(float a, float b) {
    __nv_bfloat162 h = __floats2bfloat162_rn(a, b);
    return *(unsigned*)&h;
}
__device__ __forceinline__ unsigned sptr(const void* p) {
    return (unsigned)__cvta_generic_to_shared(p);
}
__device__ __forceinline__ void ldsm4(unsigned r[4], unsigned saddr) {
    asm volatile("ldmatrix.sync.aligned.m8n8.x4.shared.b16 {%0,%1,%2,%3}, [%4];"
        : "=r"(r[0]), "=r"(r[1]), "=r"(r[2]), "=r"(r[3]) : "r"(saddr));
}
__device__ __forceinline__ void mma_bf16(float d[4], const unsigned a[4], const unsigned b[2]) {
    asm volatile("mma.sync.aligned.m16n8k16.row.col.f32.bf16.bf16.f32 "
        "{%0,%1,%2,%3},{%4,%5,%6,%7},{%8,%9},{%0,%1,%2,%3};\n"
        : "+f"(d[0]), "+f"(d[1]), "+f"(d[2]), "+f"(d[3])
        : "r"(a[0]), "r"(a[1]), "r"(a[2]), "r"(a[3]), "r"(b[0]), "r"(b[1]));
}
__device__ __forceinline__ void mma_f16(float d[4], const unsigned a[4], const unsigned b[2]) {
    asm volatile("mma.sync.aligned.m16n8k16.row.col.f32.f16.f16.f32 "
        "{%0,%1,%2,%3},{%4,%5,%6,%7},{%8,%9},{%0,%1,%2,%3};\n"
        : "+f"(d[0]), "+f"(d[1]), "+f"(d[2]), "+f"(d[3])
        : "r"(a[0]), "r"(a[1]), "r"(a[2]), "r"(a[3]), "r"(b[0]), "r"(b[1]));
}
__device__ __forceinline__ void cpasync16(void* dst, const void* src, bool pred) {
    unsigned d = (unsigned)__cvta_generic_to_shared(dst);
    int sz = pred ? 16 : 0;
    asm volatile("cp.async.cg.shared.global [%0], [%1], 16, %2;\n"
                 :: "r"(d), "l"(src), "r"(sz));
}

// ---------------- merged prep: weight transposes + pos->bf16 + LayerNorm ----------------
__global__ void prep_kernel(const float* __restrict__ x, const float* __restrict__ gamma,
                            const float* __restrict__ beta, const float* __restrict__ pos,
                            const float* __restrict__ Wq, const float* __restrict__ Wk,
                            const float* __restrict__ Wv, const float* __restrict__ Wp,
                            const float* __restrict__ Wo) {
    __shared__ float tile[32][33];
    __shared__ float ss[8], ssq[8], mb[2];
    int bid = blockIdx.x;
    int tid = threadIdx.x;
    if (bid < 1280) {
        int z = bid >> 8;
        int w = bid & 255;
        const float* W = (z == 0) ? Wq : (z == 1) ? Wk : (z == 2) ? Wv : (z == 3) ? Wp : Wo;
        int k0 = (w >> 4) * 32, n0 = (w & 15) * 32;
        #pragma unroll
        for (int p = 0; p < 4; p++) {
            int r = p * 8 + (tid >> 5), c = tid & 31;
            tile[r][c] = W[(size_t)(k0 + r) * 512 + n0 + c];
        }
        __syncthreads();
        #pragma unroll
        for (int p = 0; p < 4; p++) {
            int r = p * 8 + (tid >> 5), c = tid & 31;
            if (z < 4)
                g_wt[(size_t)z * 262144 + (size_t)(n0 + r) * 512 + k0 + c] =
                    __float2bfloat16_rn(tile[c][r]);
            else
                g_wto[(size_t)(n0 + r) * 512 + k0 + c] = __float2half_rn(tile[c][r]);
        }
    } else if (bid < 1280 + 8188) {
        size_t i = ((size_t)(bid - 1280) * 256 + tid) * 2;
        float2 v = *(const float2*)&pos[i];
        ((unsigned*)g_posb)[i >> 1] = pack_bf16(v.x, v.y);
    } else {
        int row = bid - 9468;
        const float* xr = x + (size_t)row * D;
        __nv_bfloat16* yr = g_yb + (size_t)row * D;
        float v0 = xr[tid], v1 = xr[tid + 256];
        float s = v0 + v1, sq = v0 * v0 + v1 * v1;
        #pragma unroll
        for (int o = 16; o > 0; o >>= 1) {
            s  += __shfl_xor_sync(0xFFFFFFFFu, s, o);
            sq += __shfl_xor_sync(0xFFFFFFFFu, sq, o);
        }
        if ((tid & 31) == 0) { ss[tid >> 5] = s; ssq[tid >> 5] = sq; }
        __syncthreads();
        if (tid == 0) {
            float S = 0.f, SQ = 0.f;
            #pragma unroll
            for (int i2 = 0; i2 < 8; i2++) { S += ss[i2]; SQ += ssq[i2]; }
            float mean = S * (1.0f / D);
            float var = SQ * (1.0f / D) - mean * mean;
            mb[0] = mean;
            mb[1] = rsqrtf(var + 1e-3f);
        }
        __syncthreads();
        float mean = mb[0], rstd = mb[1];
        yr[tid]       = __float2bfloat16_rn((v0 - mean) * rstd * gamma[tid]       + beta[tid]);
        yr[tid + 256] = __float2bfloat16_rn((v1 - mean) * rstd * gamma[tid + 256] + beta[tid + 256]);
    }
}

// ---------------- unified bf16 projection: q/k/v/pos, 128x128x(K64) tiles, 3-stage ----------------
struct PSmem {
    unsigned As[3][128][36];
    unsigned Bs[3][128][36];
};

__device__ __forceinline__ void pall_load(PSmem* S, int buf,
                                          const __nv_bfloat16* A, const __nv_bfloat16* Bt,
                                          int i0, int j0, int kk, int M, int tid) {
    #pragma unroll
    for (int p = 0; p < 4; p++) {
        int idx = p * 256 + tid;
        int r = idx >> 3, c4 = (idx & 7) * 4;
        cpasync16(&S->As[buf][r][c4], &A[(size_t)(i0 + r) * 512 + kk + c4 * 2], (i0 + r) < M);
    }
    #pragma unroll
    for (int p = 0; p < 4; p++) {
        int idx = p * 256 + tid;
        int r = idx >> 3, c4 = (idx & 7) * 4;
        cpasync16(&S->Bs[buf][r][c4], &Bt[(size_t)(j0 + r) * 512 + kk + c4 * 2], true);
    }
    asm volatile("cp.async.commit_group;");
}

__global__ void __launch_bounds__(256, 2) projall_kernel(
        const float* __restrict__ bq, const float* __restrict__ bk,
        const float* __restrict__ bv) {
    extern __shared__ char raw[];
    PSmem* S = (PSmem*)raw;
    int y = blockIdx.y;
    int zi, i0;
    if (y < 96) { zi = y >> 5; i0 = (y & 31) * 128; }
    else        { zi = 3;      i0 = (y - 96) * 128; }
    int M = (zi == 3) ? BL : BT;
    const __nv_bfloat16* A  = (zi == 3) ? g_posb : g_yb;
    const __nv_bfloat16* Bt = g_wt + (size_t)zi * 262144;
    const float* bias = (zi == 0) ? bq : (zi == 1) ? bk : (zi == 2) ? bv : nullptr;
    int j0 = blockIdx.x * 128;
    int tid = threadIdx.x;
    int warp = tid >> 5, lane = tid & 31;
    int wy = warp >> 2, wx = warp & 3;
    int g = lane >> 2, q = lane & 3;
    int rsel = lane & 15;
    int csel = (lane & 16) ? 4 : 0;
    int nsel = (lane & 7) + ((lane & 16) ? 8 : 0);
    int bcsel = (lane & 8) ? 4 : 0;
    float acc[4][4][4] = {};

    pall_load(S, 0, A, Bt, i0, j0, 0, M, tid);
    pall_load(S, 1, A, Bt, i0, j0, 64, M, tid);
    int buf = 0, ldb = 2;
    for (int s = 0; s < 8; s++) {
        if (s < 7) asm volatile("cp.async.wait_group 1;");
        else       asm volatile("cp.async.wait_group 0;");
        __syncthreads();
        if (s < 6) {
            pall_load(S, ldb, A, Bt, i0, j0, (s + 2) * 64, M, tid);
            ldb = (ldb == 2) ? 0 : ldb + 1;
        }
        unsigned abase[4], bbase[2];
        #pragma unroll
        for (int mt = 0; mt < 4; mt++)
            abase[mt] = sptr(&S->As[buf][wy * 64 + mt * 16 + rsel][csel]);
        #pragma unroll
        for (int ntp = 0; ntp < 2; ntp++)
            bbase[ntp] = sptr(&S->Bs[buf][wx * 32 + ntp * 16 + nsel][bcsel]);
        #pragma unroll
        for (int kb = 0; kb < 4; kb++) {
            unsigned afr[4][4], bfr[2][4];
            #pragma unroll
            for (int mt = 0; mt < 4; mt++) ldsm4(afr[mt], abase[mt] + kb * 32);
            #pragma unroll
            for (int ntp = 0; ntp < 2; ntp++) ldsm4(bfr[ntp], bbase[ntp] + kb * 32);
            #pragma unroll
            for (int mt = 0; mt < 4; mt++)
                #pragma unroll
                for (int nt = 0; nt < 4; nt++)
                    mma_bf16(acc[mt][nt], afr[mt], &bfr[nt >> 1][(nt & 1) * 2]);
        }
        buf = (buf == 2) ? 0 : buf + 1;
    }

    if (zi == 2) {
        __syncthreads();
        __nv_bfloat16* st = (__nv_bfloat16*)S->As;   // pitch 130 bf16
        #pragma unroll
        for (int mt = 0; mt < 4; mt++)
            #pragma unroll
            for (int nt = 0; nt < 4; nt++) {
                int cl = wx * 32 + nt * 8 + q * 2;
                float b0 = bias[j0 + cl], b1 = bias[j0 + cl + 1];
                #pragma unroll
                for (int half = 0; half < 2; half++) {
                    int rl = wy * 64 + mt * 16 + g + half * 8;
                    *(unsigned*)&st[rl * 130 + cl] =
                        pack_bf16(acc[mt][nt][half * 2 + 0] + b0,
                                  acc[mt][nt][half * 2 + 1] + b1);
                }
            }
        __syncthreads();
        int b_ = i0 >> 10;
        int irow = i0 & 1023;
        #pragma unroll
        for (int rep = 0; rep < 32; rep++) {
            int dp = rep * 4 + (tid >> 6);
            int m2 = (tid & 63) * 2;
            int gc = j0 + dp;
            int h_ = gc >> 6, d_ = gc & 63;
            __nv_bfloat162 hh;
            hh.x = st[m2 * 130 + dp];
            hh.y = st[(m2 + 1) * 130 + dp];
            *(unsigned*)&g_vt[(((size_t)(b_ * 8 + h_)) * 64 + d_) * 1024 + irow + m2] =
                *(unsigned*)&hh;
        }
        return;
    }

    #pragma unroll
    for (int mt = 0; mt < 4; mt++)
        #pragma unroll
        for (int nt = 0; nt < 4; nt++) {
            int c = j0 + wx * 32 + nt * 8 + q * 2;
            float b0 = bias ? bias[c] : 0.f;
            float b1 = bias ? bias[c + 1] : 0.f;
            #pragma unroll
            for (int half = 0; half < 2; half++) {
                int rr = i0 + wy * 64 + mt * 16 + g + half * 8;
                if (rr >= M) continue;
                float e0 = acc[mt][nt][half * 2 + 0] + b0;
                float e1 = acc[mt][nt][half * 2 + 1] + b1;
                if (zi == 0)
                    *(float2*)&g_q[(size_t)rr * 512 + c] = make_float2(e0, e1);
                else if (zi == 1)
                    ((unsigned*)g_kb)[((size_t)rr * 512 + c) >> 1] = pack_bf16(e0, e1);
                else
                    ((unsigned*)g_pb)[((size_t)rr * 512 + c) >> 1] = pack_bf16(e0, e1);
            }
        }
}

// ---------------- fp16 output projection: out = o @ Wo^T + bo + x; 64x128 tiles ----------------
struct POSmem {
    unsigned As[3][64][36];
    unsigned Bs[3][128][36];
};

__device__ __forceinline__ void pout_load(POSmem* S, int buf, int i0, int j0, int kk, int tid) {
    #pragma unroll
    for (int p = 0; p < 2; p++) {
        int idx = p * 256 + tid;
        int r = idx >> 3, c4 = (idx & 7) * 4;
        cpasync16(&S->As[buf][r][c4], &g_oh[(size_t)(i0 + r) * 512 + kk + c4 * 2], true);
    }
    #pragma unroll
    for (int p = 0; p < 4; p++) {
        int idx = p * 256 + tid;
        int r = idx >> 3, c4 = (idx & 7) * 4;
        cpasync16(&S->Bs[buf][r][c4], &g_wto[(size_t)(j0 + r) * 512 + kk + c4 * 2], true);
    }
    asm volatile("cp.async.commit_group;");
}

__global__ void __launch_bounds__(256, 2) projout_kernel(
        const float* __restrict__ bo, const float* __restrict__ x,
        float* __restrict__ out) {
    extern __shared__ char raw[];
    POSmem* S = (POSmem*)raw;
    int i0 = blockIdx.y * 64, j0 = blockIdx.x * 128;
    int tid = threadIdx.x;
    int warp = tid >> 5, lane = tid & 31;
    int wy = warp >> 2, wx = warp & 3;     // 2(M) x 4(N); warp tile 32 x 32
    int g = lane >> 2, q = lane & 3;
    int rsel = lane & 15;
    int csel = (lane & 16) ? 4 : 0;
    int nsel = (lane & 7) + ((lane & 16) ? 8 : 0);
    int bcsel = (lane & 8) ? 4 : 0;
    float acc[2][4][4] = {};

    pout_load(S, 0, i0, j0, 0, tid);
    pout_load(S, 1, i0, j0, 64, tid);
    int buf = 0, ldb = 2;
    for (int s = 0; s < 8; s++) {
        if (s < 7) asm volatile("cp.async.wait_group 1;");
        else       asm volatile("cp.async.wait_group 0;");
        __syncthreads();
        if (s < 6) {
            pout_load(S, ldb, i0, j0, (s + 2) * 64, tid);
            ldb = (ldb == 2) ? 0 : ldb + 1;
        }
        unsigned abase[2], bbase[2];
        #pragma unroll
        for (int mt = 0; mt < 2; mt++)
            abase[mt] = sptr(&S->As[buf][wy * 32 + mt * 16 + rsel][csel]);
        #pragma unroll
        for (int ntp = 0; ntp < 2; ntp++)
            bbase[ntp] = sptr(&S->Bs[buf][wx * 32 + ntp * 16 + nsel][bcsel]);
        #pragma unroll
        for (int kb = 0; kb < 4; kb++) {
            unsigned afr[2][4], bfr[2][4];
            #pragma unroll
            for (int mt = 0; mt < 2; mt++) ldsm4(afr[mt], abase[mt] + kb * 32);
            #pragma unroll
            for (int ntp = 0; ntp < 2; ntp++) ldsm4(bfr[ntp], bbase[ntp] + kb * 32);
            #pragma unroll
            for (int mt = 0; mt < 2; mt++)
                #pragma unroll
                for (int nt = 0; nt < 4; nt++)
                    mma_f16(acc[mt][nt], afr[mt], &bfr[nt >> 1][(nt & 1) * 2]);
        }
        buf = (buf == 2) ? 0 : buf + 1;
    }
    #pragma unroll
    for (int mt = 0; mt < 2; mt++)
        #pragma unroll
        for (int nt = 0; nt < 4; nt++) {
            int c = j0 + wx * 32 + nt * 8 + q * 2;
            float b0 = bo[c], b1 = bo[c + 1];
            #pragma unroll
            for (int half = 0; half < 2; half++) {
                int rr = i0 + wy * 32 + mt * 16 + g + half * 8;
                float e0 = acc[mt][nt][half * 2 + 0] + b0 + x[(size_t)rr * 512 + c];
                float e1 = acc[mt][nt][half * 2 + 1] + b1 + x[(size_t)rr * 512 + c + 1];
                *(float2*)&out[(size_t)rr * 512 + c] = make_float2(e0, e1);
            }
        }
}

// ---------------- flash attention: bf16 k16, ldmatrix operands, 2 CTAs/SM ----------------
struct FlashSmem {
    unsigned Ks[2][64][36];
    unsigned Ps[2][64][36];
    unsigned Vt[2][64][36];
    __nv_bfloat16 R[64][264];
    float Qs[64][68];
    float cbS[64], pbS[64];
};

__device__ __forceinline__ void pos_chunk(FlashSmem* S, int stage, int cbase,
                                          const unsigned apf[4][4], int row0,
                                          int nsel, int bcsel, int q) {
    float accP[8][4] = {};
    #pragma unroll
    for (int ntp = 0; ntp < 4; ntp++) {
        unsigned base = sptr(&S->Ps[stage][ntp * 16 + nsel][bcsel]);
        #pragma unroll
        for (int kb = 0; kb < 4; kb++) {
            unsigned bfr[4];
            ldsm4(bfr, base + kb * 32);
            mma_bf16(accP[ntp * 2],     apf[kb], bfr);
            mma_bf16(accP[ntp * 2 + 1], apf[kb], bfr + 2);
        }
    }
    #pragma unroll
    for (int nt = 0; nt < 8; nt++) {
        int s0 = (cbase + nt * 8 + 2 * q) & 255;
        *(__nv_bfloat162*)&S->R[row0][s0]     = __floats2bfloat162_rn(accP[nt][0], accP[nt][1]);
        *(__nv_bfloat162*)&S->R[row0 + 8][s0] = __floats2bfloat162_rn(accP[nt][2], accP[nt][3]);
    }
}

__global__ void __launch_bounds__(128, 2) flash_kernel(const float* __restrict__ cb,
                                                       const float* __restrict__ pb) {
    extern __shared__ char raw[];
    FlashSmem* S = (FlashSmem*)raw;
    int z = blockIdx.y; int b = z >> 3, h = z & 7;
    int i0 = blockIdx.x * 64;
    int tid = threadIdx.x;
    int warp = tid >> 5, lane = tid & 31;
    int g = lane >> 2, q = lane & 3;
    int row0 = warp * 16 + g;
    int nsel = (lane & 7) + ((lane & 16) ? 8 : 0);
    int bcsel = (lane & 8) ? 4 : 0;
    const int base0 = 1024 - i0 - 128;

    const float* qsrc = g_q + ((size_t)(b * T + i0)) * D + h * 64;
    #pragma unroll
    for (int p = 0; p < 8; p++) {
        int idx = p * 128 + tid;
        int r = idx >> 4, c4 = (idx & 15) * 4;
        cpasync16(&S->Qs[r][c4], &qsrc[(size_t)r * D + c4], true);
    }
    #pragma unroll
    for (int p = 0; p < 4; p++) {
        int idx = p * 128 + tid;
        int r = idx >> 3, c8 = (idx & 7) * 8;
        int l0 = base0 + r;      l0 = min(max(l0, 0), LL - 1);
        int l1 = base0 + 64 + r; l1 = min(max(l1, 0), LL - 1);
        cpasync16(&S->Ps[0][r][c8 >> 1], &g_pb[((size_t)(b * LL + l0)) * D + h * 64 + c8], true);
        cpasync16(&S->Ps[1][r][c8 >> 1], &g_pb[((size_t)(b * LL + l1)) * D + h * 64 + c8], true);
    }
    asm volatile("cp.async.commit_group;");
    if (tid < 16) {
        *(float4*)&S->cbS[tid * 4] = *(const float4*)&cb[h * 64 + tid * 4];
        *(float4*)&S->pbS[tid * 4] = *(const float4*)&pb[h * 64 + tid * 4];
    }

    float gfixv = 0.f;
    if (i0 == 0 && warp == 0) {
        float a0 = __bfloat162float(__float2bfloat16_rn(
            g_q[((size_t)(b * T + 1)) * D + h * 64 + lane] + pb[h * 64 + lane]));
        float a1 = __bfloat162float(__float2bfloat16_rn(
            g_q[((size_t)(b * T + 1)) * D + h * 64 + lane + 32] + pb[h * 64 + lane + 32]));
        float p0 = __bfloat162float(g_pb[((size_t)(b * LL)) * D + h * 64 + lane]);
        float p1 = __bfloat162float(g_pb[((size_t)(b * LL)) * D + h * 64 + lane + 32]);
        float sd = a0 * p0 + a1 * p1;
        #pragma unroll
        for (int o = 16; o > 0; o >>= 1) sd += __shfl_xor_sync(0xFFFFFFFFu, sd, o);
        gfixv = sd;
    }

    asm volatile("cp.async.wait_group 0;");
    __syncthreads();

    unsigned acf[4][4], apf[4][4];
    #pragma unroll
    for (int kb = 0; kb < 4; kb++) {
        int k0 = kb * 16 + 2 * q;
        float q00 = S->Qs[row0][k0],       q01 = S->Qs[row0][k0 + 1];
        float q10 = S->Qs[row0 + 8][k0],   q11 = S->Qs[row0 + 8][k0 + 1];
        float q02 = S->Qs[row0][k0 + 8],   q03 = S->Qs[row0][k0 + 9];
        float q12 = S->Qs[row0 + 8][k0 + 8], q13 = S->Qs[row0 + 8][k0 + 9];
        float c0 = S->cbS[k0], c1 = S->cbS[k0 + 1], c8v = S->cbS[k0 + 8], c9 = S->cbS[k0 + 9];
        float p0 = S->pbS[k0], p1 = S->pbS[k0 + 1], p8 = S->pbS[k0 + 8], p9 = S->pbS[k0 + 9];
        acf[kb][0] = pack_bf16(q00 + c0, q01 + c1);
        acf[kb][1] = pack_bf16(q10 + c0, q11 + c1);
        acf[kb][2] = pack_bf16(q02 + c8v, q03 + c9);
        acf[kb][3] = pack_bf16(q12 + c8v, q13 + c9);
        apf[kb][0] = pack_bf16(q00 + p0, q01 + p1);
        apf[kb][1] = pack_bf16(q10 + p0, q11 + p1);
        apf[kb][2] = pack_bf16(q02 + p8, q03 + p9);
        apf[kb][3] = pack_bf16(q12 + p8, q13 + p9);
    }

    pos_chunk(S, 0, base0, apf, row0, nsel, bcsel, q);
    pos_chunk(S, 1, base0 + 64, apf, row0, nsel, bcsel, q);
    __syncthreads();
    #pragma unroll
    for (int p = 0; p < 4; p++) {
        int idx = p * 128 + tid;
        int r = idx >> 3, c8 = (idx & 7) * 8;
        int l = base0 + 128 + r; l = min(max(l, 0), LL - 1);
        cpasync16(&S->Ps[0][r][c8 >> 1], &g_pb[((size_t)(b * LL + l)) * D + h * 64 + c8], true);
    }
    asm volatile("cp.async.commit_group;");
    asm volatile("cp.async.wait_group 0;");
    __syncthreads();
    pos_chunk(S, 0, base0 + 128, apf, row0, nsel, bcsel, q);
    __syncthreads();

    {
        const __nv_bfloat16* kb_ = g_kb + ((size_t)(b * T)) * D + h * 64;
        const __nv_bfloat16* vt_ = g_vt + ((size_t)z) * 64 * 1024;
        #pragma unroll
        for (int p = 0; p < 4; p++) {
            int idx = p * 128 + tid;
            int r = idx >> 3, c8 = (idx & 7) * 8;
            cpasync16(&S->Ks[0][r][c8 >> 1], &kb_[(size_t)r * D + c8], true);
            cpasync16(&S->Vt[0][r][c8 >> 1], &vt_[(size_t)r * 1024 + c8], true);
            int l = base0 + 192 + r; l = min(max(l, 0), LL - 1);
            cpasync16(&S->Ps[0][r][c8 >> 1], &g_pb[((size_t)(b * LL + l)) * D + h * 64 + c8], true);
        }
        asm volatile("cp.async.commit_group;");
    }

    float accO[8][4] = {};
    float sumA = 0.f, sumB = 0.f;

    for (int jt = 0; jt < 16; jt++) {
        asm volatile("cp.async.wait_group 0;");
        __syncthreads();
        int st = jt & 1;
        if (jt < 15) {
            int st2 = st ^ 1;
            const __nv_bfloat16* kb_ = g_kb + ((size_t)(b * T + (jt + 1) * 64)) * D + h * 64;
            const __nv_bfloat16* vt_ = g_vt + ((size_t)z) * 64 * 1024 + (jt + 1) * 64;
            #pragma unroll
            for (int p = 0; p < 4; p++) {
                int idx = p * 128 + tid;
                int r = idx >> 3, c8 = (idx & 7) * 8;
                cpasync16(&S->Ks[st2][r][c8 >> 1], &kb_[(size_t)r * D + c8], true);
                cpasync16(&S->Vt[st2][r][c8 >> 1], &vt_[(size_t)r * 1024 + c8], true);
                int l = base0 + 192 + 64 * (jt + 1) + r; l = min(max(l, 0), LL - 1);
                cpasync16(&S->Ps[st2][r][c8 >> 1], &g_pb[((size_t)(b * LL + l)) * D + h * 64 + c8], true);
            }
            asm volatile("cp.async.commit_group;");
        }

        float accC[8][4] = {};
        #pragma unroll
        for (int ntp = 0; ntp < 4; ntp++) {
            unsigned base = sptr(&S->Ks[st][ntp * 16 + nsel][bcsel]);
            #pragma unroll
            for (int kb2 = 0; kb2 < 4; kb2++) {
                unsigned bfr[4];
                ldsm4(bfr, base + kb2 * 32);
                mma_bf16(accC[ntp * 2],     acf[kb2], bfr);
                mma_bf16(accC[ntp * 2 + 1], acf[kb2], bfr + 2);
            }
        }
        if (jt < 15) pos_chunk(S, st, base0 + 192 + 64 * jt, apf, row0, nsel, bcsel, q);

        unsigned vbase[4];
        #pragma unroll
        for (int n2p = 0; n2p < 4; n2p++)
            vbase[n2p] = sptr(&S->Vt[st][n2p * 16 + nsel][bcsel]);

        int basew = 1024 + 64 * jt - i0;
        bool fixc = (i0 == 0) && (jt == 15) && (warp == 0) && (g == 0) && (q == 3);
        #pragma unroll
        for (int kb2 = 0; kb2 < 4; kb2++) {
            unsigned a[4];
            #pragma unroll
            for (int half = 0; half < 2; half++) {
                int nt = kb2 * 2 + half;
                int jl = nt * 8 + 2 * q;
                int il0 = row0, il1 = row0 + 8;
                float r00 = __bfloat162float(S->R[il0][(basew + jl - il0) & 255]);
                float r01 = __bfloat162float(S->R[il0][(basew + jl + 1 - il0) & 255]);
                float r10 = __bfloat162float(S->R[il1][(basew + jl - il1) & 255]);
                float r11 = __bfloat162float(S->R[il1][(basew + jl + 1 - il1) & 255]);
                if (fixc && nt == 7) r01 = gfixv;
                float e0 = __expf((accC[nt][0] + r00) * 0.125f);
                float e1 = __expf((accC[nt][1] + r01) * 0.125f);
                float e2 = __expf((accC[nt][2] + r10) * 0.125f);
                float e3 = __expf((accC[nt][3] + r11) * 0.125f);
                sumA += e0 + e1; sumB += e2 + e3;
                a[half * 2]     = pack_bf16(e0, e1);
                a[half * 2 + 1] = pack_bf16(e2, e3);
            }
            #pragma unroll
            for (int n2p = 0; n2p < 4; n2p++) {
                unsigned vfr[4];
                ldsm4(vfr, vbase[n2p] + kb2 * 32);
                mma_bf16(accO[n2p * 2],     a, vfr);
                mma_bf16(accO[n2p * 2 + 1], a, vfr + 2);
            }
        }
    }

    sumA += __shfl_xor_sync(0xFFFFFFFFu, sumA, 1);
    sumA += __shfl_xor_sync(0xFFFFFFFFu, sumA, 2);
    sumB += __shfl_xor_sync(0xFFFFFFFFu, sumB, 1);
    sumB += __shfl_xor_sync(0xFFFFFFFFu, sumB, 2);
    float invA = 1.f / sumA, invB = 1.f / sumB;
    #pragma unroll
    for (int n2 = 0; n2 < 8; n2++) {
        int col = h * 64 + n2 * 8 + 2 * q;
        size_t r = (size_t)(b * T + i0 + row0);
        __half2 h0 = __floats2half2_rn(accO[n2][0] * invA, accO[n2][1] * invA);
        __half2 h1 = __floats2half2_rn(accO[n2][2] * invB, accO[n2][3] * invB);
        *(unsigned*)&g_oh[r * D + col] = *(unsigned*)&h0;
        *(unsigned*)&g_oh[(r + 8) * D + col] = *(unsigned*)&h1;
    }
}

extern "C" void kernel_launch(void* const* d_in, const int* in_sizes, int n_in,
                              void* d_out, int out_size) {
    const float* x     = (const float*)d_in[0];
    const float* pos   = (const float*)d_in[1];
    const float* cb    = (const float*)d_in[2];
    const float* pb    = (const float*)d_in[3];
    const float* gamma = (const float*)d_in[4];
    const float* beta  = (const float*)d_in[5];
    const float* Wq    = (const float*)d_in[6];
    const float* bq    = (const float*)d_in[7];
    const float* Wk    = (const float*)d_in[8];
    const float* bk    = (const float*)d_in[9];
    const float* Wv    = (const float*)d_in[10];
    const float* bv    = (const float*)d_in[11];
    const float* Wp    = (const float*)d_in[12];
    const float* Wo    = (const float*)d_in[13];
    const float* bo    = (const float*)d_in[14];
    float* out = (float*)d_out;

    cudaFuncSetAttribute(projall_kernel, cudaFuncAttributeMaxDynamicSharedMemorySize,
                         (int)sizeof(PSmem));
    cudaFuncSetAttribute(projout_kernel, cudaFuncAttributeMaxDynamicSharedMemorySize,
                         (int)sizeof(POSmem));
    cudaFuncSetAttribute(flash_kernel, cudaFuncAttributeMaxDynamicSharedMemorySize,
                         (int)sizeof(FlashSmem));

    // 1. merged prep: 5 weight transposes + pos convert + LayerNorm
    prep_kernel<<<13564, 256>>>(x, gamma, beta, pos, Wq, Wk, Wv, Wp, Wo);

    // 2. unified projections (q/k/v/pos, bf16, ldmatrix, 3-stage pipeline)
    projall_kernel<<<dim3(4, 160), 256, sizeof(PSmem)>>>(bq, bk, bv);

    // 3. fused flash attention (bf16 mma; o written as fp16)
    flash_kernel<<<dim3(16, 32), 128, sizeof(FlashSmem)>>>(cb, pb);

    // 4. output projection (fp16 mma) + bias + residual
    projout_kernel<<<dim3(4, 64), 256, sizeof(POSmem)>>>(bo, x, out);
}

// round 14
// speedup vs baseline: 3.1962x; 1.0153x over previous
#include <cuda_runtime.h>
#include <cuda_bf16.h>
#include <cuda_fp16.h>
#include <math.h>

#define BB 4
#define T 1024
#define D 512
#define H 8
#define LL 2047
#define BT (BB*T)      // 4096
#define BL (BB*LL)     // 8188

__device__ __nv_bfloat16 g_yb[BT*D];           // LN output, bf16
__device__ __nv_bfloat16 g_wt[4*512*512];      // transposed bf16 weights: q,k,v,p
__device__ __half        g_wto[512*512];       // transposed fp16 Wo
__device__ __nv_bfloat16 g_posb[(size_t)BL*D]; // pos in bf16
__device__ float g_q[BT*D];    // q + bq (f32)
__device__ __half g_oh[BT*D];  // attention output, fp16
__device__ __nv_bfloat16 g_kb[BT*D];
__device__ __nv_bfloat16 g_pb[(size_t)BL*D];
__device__ __nv_bfloat16 g_vt[(size_t)BB*H*64*1024];  // [b*H+h][d][j]

// ---------------- helpers ----------------
__device__ __forceinline__ unsigned pack_bf16(float a, float b) {
    __nv_bfloat162 h = __floats2bfloat162_rn(a, b);
    return *(unsigned*)&h;
}
__device__ __forceinline__ unsigned sptr(const void* p) {
    return (unsigned)__cvta_generic_to_shared(p);
}
__device__ __forceinline__ void ldsm4(unsigned r[4], unsigned saddr) {
    asm volatile("ldmatrix.sync.aligned.m8n8.x4.shared.b16 {%0,%1,%2,%3}, [%4];"
        : "=r"(r[0]), "=r"(r[1]), "=r"(r[2]), "=r"(r[3]) : "r"(saddr));
}
__device__ __forceinline__ void mma_bf16(float d[4], const unsigned a[4], const unsigned b[2]) {
    asm volatile("mma.sync.aligned.m16n8k16.row.col.f32.bf16.bf16.f32 "
        "{%0,%1,%2,%3},{%4,%5,%6,%7},{%8,%9},{%0,%1,%2,%3};\n"
        : "+f"(d[0]), "+f"(d[1]), "+f"(d[2]), "+f"(d[3])
        : "r"(a[0]), "r"(a[1]), "r"(a[2]), "r"(a[3]), "r"(b[0]), "r"(b[1]));
}
__device__ __forceinline__ void mma_f16(float d[4], const unsigned a[4], const unsigned b[2]) {
    asm volatile("mma.sync.aligned.m16n8k16.row.col.f32.f16.f16.f32 "
        "{%0,%1,%2,%3},{%4,%5,%6,%7},{%8,%9},{%0,%1,%2,%3};\n"
        : "+f"(d[0]), "+f"(d[1]), "+f"(d[2]), "+f"(d[3])
        : "r"(a[0]), "r"(a[1]), "r"(a[2]), "r"(a[3]), "r"(b[0]), "r"(b[1]));
}
__device__ __forceinline__ void cpasync16(void* dst, const void* src, bool pred) {
    unsigned d = (unsigned)__cvta_generic_to_shared(dst);
    int sz = pred ? 16 : 0;
    asm volatile("cp.async.cg.shared.global [%0], [%1], 16, %2;\n"
                 :: "r"(d), "l"(src), "r"(sz));
}
__device__ __forceinline__ void gdc_wait() {
    asm volatile("griddepcontrol.wait;" ::: "memory");
}
__device__ __forceinline__ void gdc_launch() {
    asm volatile("griddepcontrol.launch_dependents;");
}

// ---------------- merged prep: weight transposes + pos->bf16 + LayerNorm ----------------
__global__ void prep_kernel(const float* __restrict__ x, const float* __restrict__ gamma,
                            const float* __restrict__ beta, const float* __restrict__ pos,
                            const float* __restrict__ Wq, const float* __restrict__ Wk,
                            const float* __restrict__ Wv, const float* __restrict__ Wp,
                            const float* __restrict__ Wo) {
    __shared__ float tile[32][33];
    __shared__ float ss[8], ssq[8], mb[2];
    int bid = blockIdx.x;
    int tid = threadIdx.x;
    if (bid < 1280) {
        int z = bid >> 8;
        int w = bid & 255;
        const float* W = (z == 0) ? Wq : (z == 1) ? Wk : (z == 2) ? Wv : (z == 3) ? Wp : Wo;
        int k0 = (w >> 4) * 32, n0 = (w & 15) * 32;
        #pragma unroll
        for (int p = 0; p < 4; p++) {
            int r = p * 8 + (tid >> 5), c = tid & 31;
            tile[r][c] = W[(size_t)(k0 + r) * 512 + n0 + c];
        }
        __syncthreads();
        #pragma unroll
        for (int p = 0; p < 4; p++) {
            int r = p * 8 + (tid >> 5), c = tid & 31;
            if (z < 4)
                g_wt[(size_t)z * 262144 + (size_t)(n0 + r) * 512 + k0 + c] =
                    __float2bfloat16_rn(tile[c][r]);
            else
                g_wto[(size_t)(n0 + r) * 512 + k0 + c] = __float2half_rn(tile[c][r]);
        }
    } else if (bid < 1280 + 4094) {
        size_t i = ((size_t)(bid - 1280) * 256 + tid) * 4;
        float4 v = *(const float4*)&pos[i];
        uint2 u;
        u.x = pack_bf16(v.x, v.y);
        u.y = pack_bf16(v.z, v.w);
        *(uint2*)&g_posb[i] = u;
    } else {
        int row = bid - 5374;
        const float* xr = x + (size_t)row * D;
        __nv_bfloat16* yr = g_yb + (size_t)row * D;
        float v0 = xr[tid], v1 = xr[tid + 256];
        float s = v0 + v1, sq = v0 * v0 + v1 * v1;
        #pragma unroll
        for (int o = 16; o > 0; o >>= 1) {
            s  += __shfl_xor_sync(0xFFFFFFFFu, s, o);
            sq += __shfl_xor_sync(0xFFFFFFFFu, sq, o);
        }
        if ((tid & 31) == 0) { ss[tid >> 5] = s; ssq[tid >> 5] = sq; }
        __syncthreads();
        if (tid == 0) {
            float S = 0.f, SQ = 0.f;
            #pragma unroll
            for (int i2 = 0; i2 < 8; i2++) { S += ss[i2]; SQ += ssq[i2]; }
            float mean = S * (1.0f / D);
            float var = SQ * (1.0f / D) - mean * mean;
            mb[0] = mean;
            mb[1] = rsqrtf(var + 1e-3f);
        }
        __syncthreads();
        float mean = mb[0], rstd = mb[1];
        yr[tid]       = __float2bfloat16_rn((v0 - mean) * rstd * gamma[tid]       + beta[tid]);
        yr[tid + 256] = __float2bfloat16_rn((v1 - mean) * rstd * gamma[tid + 256] + beta[tid + 256]);
    }
    gdc_launch();
}

// ---------------- unified bf16 projection: q/k/v/pos, 128x128x(K64) tiles, 3-stage ----------------
struct PSmem {
    unsigned As[3][128][36];
    unsigned Bs[3][128][36];
};

__device__ __forceinline__ void pall_load(PSmem* S, int buf,
                                          const __nv_bfloat16* A, const __nv_bfloat16* Bt,
                                          int i0, int j0, int kk, int M, int tid) {
    #pragma unroll
    for (int p = 0; p < 4; p++) {
        int idx = p * 256 + tid;
        int r = idx >> 3, c4 = (idx & 7) * 4;
        cpasync16(&S->As[buf][r][c4], &A[(size_t)(i0 + r) * 512 + kk + c4 * 2], (i0 + r) < M);
    }
    #pragma unroll
    for (int p = 0; p < 4; p++) {
        int idx = p * 256 + tid;
        int r = idx >> 3, c4 = (idx & 7) * 4;
        cpasync16(&S->Bs[buf][r][c4], &Bt[(size_t)(j0 + r) * 512 + kk + c4 * 2], true);
    }
    asm volatile("cp.async.commit_group;");
}

__global__ void __launch_bounds__(256, 2) projall_kernel(
        const float* __restrict__ bq, const float* __restrict__ bk,
        const float* __restrict__ bv) {
    extern __shared__ char raw[];
    PSmem* S = (PSmem*)raw;
    gdc_wait();
    int y = blockIdx.y;
    int zi, i0;
    if (y < 96) { zi = y >> 5; i0 = (y & 31) * 128; }
    else        { zi = 3;      i0 = (y - 96) * 128; }
    int M = (zi == 3) ? BL : BT;
    const __nv_bfloat16* A  = (zi == 3) ? g_posb : g_yb;
    const __nv_bfloat16* Bt = g_wt + (size_t)zi * 262144;
    const float* bias = (zi == 0) ? bq : (zi == 1) ? bk : (zi == 2) ? bv : nullptr;
    int j0 = blockIdx.x * 128;
    int tid = threadIdx.x;
    int warp = tid >> 5, lane = tid & 31;
    int wy = warp >> 2, wx = warp & 3;
    int g = lane >> 2, q = lane & 3;
    int rsel = lane & 15;
    int csel = (lane & 16) ? 4 : 0;
    int nsel = (lane & 7) + ((lane & 16) ? 8 : 0);
    int bcsel = (lane & 8) ? 4 : 0;
    float acc[4][4][4] = {};

    pall_load(S, 0, A, Bt, i0, j0, 0, M, tid);
    pall_load(S, 1, A, Bt, i0, j0, 64, M, tid);
    int buf = 0, ldb = 2;
    for (int s = 0; s < 8; s++) {
        if (s < 7) asm volatile("cp.async.wait_group 1;");
        else       asm volatile("cp.async.wait_group 0;");
        __syncthreads();
        if (s < 6) {
            pall_load(S, ldb, A, Bt, i0, j0, (s + 2) * 64, M, tid);
            ldb = (ldb == 2) ? 0 : ldb + 1;
        }
        unsigned abase[4], bbase[2];
        #pragma unroll
        for (int mt = 0; mt < 4; mt++)
            abase[mt] = sptr(&S->As[buf][wy * 64 + mt * 16 + rsel][csel]);
        #pragma unroll
        for (int ntp = 0; ntp < 2; ntp++)
            bbase[ntp] = sptr(&S->Bs[buf][wx * 32 + ntp * 16 + nsel][bcsel]);
        #pragma unroll
        for (int kb = 0; kb < 4; kb++) {
            unsigned afr[4][4], bfr[2][4];
            #pragma unroll
            for (int mt = 0; mt < 4; mt++) ldsm4(afr[mt], abase[mt] + kb * 32);
            #pragma unroll
            for (int ntp = 0; ntp < 2; ntp++) ldsm4(bfr[ntp], bbase[ntp] + kb * 32);
            #pragma unroll
            for (int mt = 0; mt < 4; mt++)
                #pragma unroll
                for (int nt = 0; nt < 4; nt++)
                    mma_bf16(acc[mt][nt], afr[mt], &bfr[nt >> 1][(nt & 1) * 2]);
        }
        buf = (buf == 2) ? 0 : buf + 1;
    }

    if (zi == 2) {
        __syncthreads();
        __nv_bfloat16* st = (__nv_bfloat16*)S->As;   // pitch 130 bf16
        #pragma unroll
        for (int mt = 0; mt < 4; mt++)
            #pragma unroll
            for (int nt = 0; nt < 4; nt++) {
                int cl = wx * 32 + nt * 8 + q * 2;
                float b0 = bias[j0 + cl], b1 = bias[j0 + cl + 1];
                #pragma unroll
                for (int half = 0; half < 2; half++) {
                    int rl = wy * 64 + mt * 16 + g + half * 8;
                    *(unsigned*)&st[rl * 130 + cl] =
                        pack_bf16(acc[mt][nt][half * 2 + 0] + b0,
                                  acc[mt][nt][half * 2 + 1] + b1);
                }
            }
        __syncthreads();
        int b_ = i0 >> 10;
        int irow = i0 & 1023;
        #pragma unroll
        for (int rep = 0; rep < 32; rep++) {
            int dp = rep * 4 + (tid >> 6);
            int m2 = (tid & 63) * 2;
            int gc = j0 + dp;
            int h_ = gc >> 6, d_ = gc & 63;
            __nv_bfloat162 hh;
            hh.x = st[m2 * 130 + dp];
            hh.y = st[(m2 + 1) * 130 + dp];
            *(unsigned*)&g_vt[(((size_t)(b_ * 8 + h_)) * 64 + d_) * 1024 + irow + m2] =
                *(unsigned*)&hh;
        }
        gdc_launch();
        return;
    }

    #pragma unroll
    for (int mt = 0; mt < 4; mt++)
        #pragma unroll
        for (int nt = 0; nt < 4; nt++) {
            int c = j0 + wx * 32 + nt * 8 + q * 2;
            float b0 = bias ? bias[c] : 0.f;
            float b1 = bias ? bias[c + 1] : 0.f;
            #pragma unroll
            for (int half = 0; half < 2; half++) {
                int rr = i0 + wy * 64 + mt * 16 + g + half * 8;
                if (rr >= M) continue;
                float e0 = acc[mt][nt][half * 2 + 0] + b0;
                float e1 = acc[mt][nt][half * 2 + 1] + b1;
                if (zi == 0)
                    *(float2*)&g_q[(size_t)rr * 512 + c] = make_float2(e0, e1);
                else if (zi == 1)
                    ((unsigned*)g_kb)[((size_t)rr * 512 + c) >> 1] = pack_bf16(e0, e1);
                else
                    ((unsigned*)g_pb)[((size_t)rr * 512 + c) >> 1] = pack_bf16(e0, e1);
            }
        }
    gdc_launch();
}

// ---------------- fp16 output projection: out = o @ Wo^T + bo + x; x prefetched ----------------
// 2-stage buffers, prefetch distance 1 (load target never the live buffer)
struct POSmem {
    unsigned As[2][64][36];
    unsigned Bs[2][128][36];
    float Xs[64][132];    // pitch 132 floats = 528 B (16B multiple for cp.async)
};

__device__ __forceinline__ void pout_load(POSmem* S, int buf, int i0, int j0, int kk, int tid) {
    #pragma unroll
    for (int p = 0; p < 2; p++) {
        int idx = p * 256 + tid;
        int r = idx >> 3, c4 = (idx & 7) * 4;
        cpasync16(&S->As[buf][r][c4], &g_oh[(size_t)(i0 + r) * 512 + kk + c4 * 2], true);
    }
    #pragma unroll
    for (int p = 0; p < 4; p++) {
        int idx = p * 256 + tid;
        int r = idx >> 3, c4 = (idx & 7) * 4;
        cpasync16(&S->Bs[buf][r][c4], &g_wto[(size_t)(j0 + r) * 512 + kk + c4 * 2], true);
    }
    asm volatile("cp.async.commit_group;");
}

__global__ void __launch_bounds__(256, 2) projout_kernel(
        const float* __restrict__ bo, const float* __restrict__ x,
        float* __restrict__ out) {
    extern __shared__ char raw[];
    POSmem* S = (POSmem*)raw;
    gdc_wait();
    int i0 = blockIdx.y * 64, j0 = blockIdx.x * 128;
    int tid = threadIdx.x;
    int warp = tid >> 5, lane = tid & 31;
    int wy = warp >> 2, wx = warp & 3;
    int g = lane >> 2, q = lane & 3;
    int rsel = lane & 15;
    int csel = (lane & 16) ? 4 : 0;
    int nsel = (lane & 7) + ((lane & 16) ? 8 : 0);
    int bcsel = (lane & 8) ? 4 : 0;
    float acc[2][4][4] = {};

    // prefetch residual x tile (its own group; drained by the first wait)
    #pragma unroll
    for (int p = 0; p < 8; p++) {
        int idx = p * 256 + tid;
        int r = idx >> 5, c4 = (idx & 31) * 4;
        cpasync16(&S->Xs[r][c4], &x[(size_t)(i0 + r) * 512 + j0 + c4], true);
    }
    asm volatile("cp.async.commit_group;");

    pout_load(S, 0, i0, j0, 0, tid);
    for (int s = 0; s < 8; s++) {
        asm volatile("cp.async.wait_group 0;");
        __syncthreads();
        if (s < 7)
            pout_load(S, (s + 1) & 1, i0, j0, (s + 1) * 64, tid);  // distinct from live buf
        int buf = s & 1;
        unsigned abase[2], bbase[2];
        #pragma unroll
        for (int mt = 0; mt < 2; mt++)
            abase[mt] = sptr(&S->As[buf][wy * 32 + mt * 16 + rsel][csel]);
        #pragma unroll
        for (int ntp = 0; ntp < 2; ntp++)
            bbase[ntp] = sptr(&S->Bs[buf][wx * 32 + ntp * 16 + nsel][bcsel]);
        #pragma unroll
        for (int kb = 0; kb < 4; kb++) {
            unsigned afr[2][4], bfr[2][4];
            #pragma unroll
            for (int mt = 0; mt < 2; mt++) ldsm4(afr[mt], abase[mt] + kb * 32);
            #pragma unroll
            for (int ntp = 0; ntp < 2; ntp++) ldsm4(bfr[ntp], bbase[ntp] + kb * 32);
            #pragma unroll
            for (int mt = 0; mt < 2; mt++)
                #pragma unroll
                for (int nt = 0; nt < 4; nt++)
                    mma_f16(acc[mt][nt], afr[mt], &bfr[nt >> 1][(nt & 1) * 2]);
        }
    }
    #pragma unroll
    for (int mt = 0; mt < 2; mt++)
        #pragma unroll
        for (int nt = 0; nt < 4; nt++) {
            int cl = wx * 32 + nt * 8 + q * 2;
            int c = j0 + cl;
            float b0 = bo[c], b1 = bo[c + 1];
            #pragma unroll
            for (int half = 0; half < 2; half++) {
                int rl = wy * 32 + mt * 16 + g + half * 8;
                int rr = i0 + rl;
                float e0 = acc[mt][nt][half * 2 + 0] + b0 + S->Xs[rl][cl];
                float e1 = acc[mt][nt][half * 2 + 1] + b1 + S->Xs[rl][cl + 1];
                *(float2*)&out[(size_t)rr * 512 + c] = make_float2(e0, e1);
            }
        }
}

// ---------------- flash attention: bf16 k16, ldmatrix operands, 2 CTAs/SM ----------------
struct FlashSmem {
    unsigned Ks[2][64][36];
    unsigned Ps[2][64][36];
    unsigned Vt[2][64][36];
    __nv_bfloat16 R[64][264];
    float Qs[64][68];
    float cbS[64], pbS[64];
};

__device__ __forceinline__ void pos_chunk(FlashSmem* S, int stage, int cbase,
                                          const unsigned apf[4][4], int row0,
                                          int nsel, int bcsel, int q) {
    float accP[8][4] = {};
    #pragma unroll
    for (int ntp = 0; ntp < 4; ntp++) {
        unsigned base = sptr(&S->Ps[stage][ntp * 16 + nsel][bcsel]);
        #pragma unroll
        for (int kb = 0; kb < 4; kb++) {
            unsigned bfr[4];
            ldsm4(bfr, base + kb * 32);
            mma_bf16(accP[ntp * 2],     apf[kb], bfr);
            mma_bf16(accP[ntp * 2 + 1], apf[kb], bfr + 2);
        }
    }
    #pragma unroll
    for (int nt = 0; nt < 8; nt++) {
        int s0 = (cbase + nt * 8 + 2 * q) & 255;
        *(__nv_bfloat162*)&S->R[row0][s0]     = __floats2bfloat162_rn(accP[nt][0], accP[nt][1]);
        *(__nv_bfloat162*)&S->R[row0 + 8][s0] = __floats2bfloat162_rn(accP[nt][2], accP[nt][3]);
    }
}

__global__ void __launch_bounds__(128, 2) flash_kernel(const float* __restrict__ cb,
                                                       const float* __restrict__ pb) {
    extern __shared__ char raw[];
    FlashSmem* S = (FlashSmem*)raw;
    gdc_wait();
    int z = blockIdx.y; int b = z >> 3, h = z & 7;
    int i0 = blockIdx.x * 64;
    int tid = threadIdx.x;
    int warp = tid >> 5, lane = tid & 31;
    int g = lane >> 2, q = lane & 3;
    int row0 = warp * 16 + g;
    int nsel = (lane & 7) + ((lane & 16) ? 8 : 0);
    int bcsel = (lane & 8) ? 4 : 0;
    const int base0 = 1024 - i0 - 128;

    const float* qsrc = g_q + ((size_t)(b * T + i0)) * D + h * 64;
    #pragma unroll
    for (int p = 0; p < 8; p++) {
        int idx = p * 128 + tid;
        int r = idx >> 4, c4 = (idx & 15) * 4;
        cpasync16(&S->Qs[r][c4], &qsrc[(size_t)r * D + c4], true);
    }
    #pragma unroll
    for (int p = 0; p < 4; p++) {
        int idx = p * 128 + tid;
        int r = idx >> 3, c8 = (idx & 7) * 8;
        int l0 = base0 + r;      l0 = min(max(l0, 0), LL - 1);
        int l1 = base0 + 64 + r; l1 = min(max(l1, 0), LL - 1);
        cpasync16(&S->Ps[0][r][c8 >> 1], &g_pb[((size_t)(b * LL + l0)) * D + h * 64 + c8], true);
        cpasync16(&S->Ps[1][r][c8 >> 1], &g_pb[((size_t)(b * LL + l1)) * D + h * 64 + c8], true);
    }
    asm volatile("cp.async.commit_group;");
    if (tid < 16) {
        *(float4*)&S->cbS[tid * 4] = *(const float4*)&cb[h * 64 + tid * 4];
        *(float4*)&S->pbS[tid * 4] = *(const float4*)&pb[h * 64 + tid * 4];
    }

    float gfixv = 0.f;
    if (i0 == 0 && warp == 0) {
        float a0 = __bfloat162float(__float2bfloat16_rn(
            g_q[((size_t)(b * T + 1)) * D + h * 64 + lane] + pb[h * 64 + lane]));
        float a1 = __bfloat162float(__float2bfloat16_rn(
            g_q[((size_t)(b * T + 1)) * D + h * 64 + lane + 32] + pb[h * 64 + lane + 32]));
        float p0 = __bfloat162float(g_pb[((size_t)(b * LL)) * D + h * 64 + lane]);
        float p1 = __bfloat162float(g_pb[((size_t)(b * LL)) * D + h * 64 + lane + 32]);
        float sd = a0 * p0 + a1 * p1;
        #pragma unroll
        for (int o = 16; o > 0; o >>= 1) sd += __shfl_xor_sync(0xFFFFFFFFu, sd, o);
        gfixv = sd;
    }

    asm volatile("cp.async.wait_group 0;");
    __syncthreads();

    unsigned acf[4][4], apf[4][4];
    #pragma unroll
    for (int kb = 0; kb < 4; kb++) {
        int k0 = kb * 16 + 2 * q;
        float q00 = S->Qs[row0][k0],       q01 = S->Qs[row0][k0 + 1];
        float q10 = S->Qs[row0 + 8][k0],   q11 = S->Qs[row0 + 8][k0 + 1];
        float q02 = S->Qs[row0][k0 + 8],   q03 = S->Qs[row0][k0 + 9];
        float q12 = S->Qs[row0 + 8][k0 + 8], q13 = S->Qs[row0 + 8][k0 + 9];
        float c0 = S->cbS[k0], c1 = S->cbS[k0 + 1], c8v = S->cbS[k0 + 8], c9 = S->cbS[k0 + 9];
        float p0 = S->pbS[k0], p1 = S->pbS[k0 + 1], p8 = S->pbS[k0 + 8], p9 = S->pbS[k0 + 9];
        acf[kb][0] = pack_bf16(q00 + c0, q01 + c1);
        acf[kb][1] = pack_bf16(q10 + c0, q11 + c1);
        acf[kb][2] = pack_bf16(q02 + c8v, q03 + c9);
        acf[kb][3] = pack_bf16(q12 + c8v, q13 + c9);
        apf[kb][0] = pack_bf16(q00 + p0, q01 + p1);
        apf[kb][1] = pack_bf16(q10 + p0, q11 + p1);
        apf[kb][2] = pack_bf16(q02 + p8, q03 + p9);
        apf[kb][3] = pack_bf16(q12 + p8, q13 + p9);
    }

    pos_chunk(S, 0, base0, apf, row0, nsel, bcsel, q);
    pos_chunk(S, 1, base0 + 64, apf, row0, nsel, bcsel, q);
    __syncthreads();
    #pragma unroll
    for (int p = 0; p < 4; p++) {
        int idx = p * 128 + tid;
        int r = idx >> 3, c8 = (idx & 7) * 8;
        int l = base0 + 128 + r; l = min(max(l, 0), LL - 1);
        cpasync16(&S->Ps[0][r][c8 >> 1], &g_pb[((size_t)(b * LL + l)) * D + h * 64 + c8], true);
    }
    asm volatile("cp.async.commit_group;");
    asm volatile("cp.async.wait_group 0;");
    __syncthreads();
    pos_chunk(S, 0, base0 + 128, apf, row0, nsel, bcsel, q);
    __syncthreads();

    {
        const __nv_bfloat16* kb_ = g_kb + ((size_t)(b * T)) * D + h * 64;
        const __nv_bfloat16* vt_ = g_vt + ((size_t)z) * 64 * 1024;
        #pragma unroll
        for (int p = 0; p < 4; p++) {
            int idx = p * 128 + tid;
            int r = idx >> 3, c8 = (idx & 7) * 8;
            cpasync16(&S->Ks[0][r][c8 >> 1], &kb_[(size_t)r * D + c8], true);
            cpasync16(&S->Vt[0][r][c8 >> 1], &vt_[(size_t)r * 1024 + c8], true);
            int l = base0 + 192 + r; l = min(max(l, 0), LL - 1);
            cpasync16(&S->Ps[0][r][c8 >> 1], &g_pb[((size_t)(b * LL + l)) * D + h * 64 + c8], true);
        }
        asm volatile("cp.async.commit_group;");
    }

    float accO[8][4] = {};
    float sumA = 0.f, sumB = 0.f;

    for (int jt = 0; jt < 16; jt++) {
        asm volatile("cp.async.wait_group 0;");
        __syncthreads();
        int st = jt & 1;
        if (jt < 15) {
            int st2 = st ^ 1;
            const __nv_bfloat16* kb_ = g_kb + ((size_t)(b * T + (jt + 1) * 64)) * D + h * 64;
            const __nv_bfloat16* vt_ = g_vt + ((size_t)z) * 64 * 1024 + (jt + 1) * 64;
            #pragma unroll
            for (int p = 0; p < 4; p++) {
                int idx = p * 128 + tid;
                int r = idx >> 3, c8 = (idx & 7) * 8;
                cpasync16(&S->Ks[st2][r][c8 >> 1], &kb_[(size_t)r * D + c8], true);
                cpasync16(&S->Vt[st2][r][c8 >> 1], &vt_[(size_t)r * 1024 + c8], true);
                int l = base0 + 192 + 64 * (jt + 1) + r; l = min(max(l, 0), LL - 1);
                cpasync16(&S->Ps[st2][r][c8 >> 1], &g_pb[((size_t)(b * LL + l)) * D + h * 64 + c8], true);
            }
            asm volatile("cp.async.commit_group;");
        }

        float accC[8][4] = {};
        #pragma unroll
        for (int ntp = 0; ntp < 4; ntp++) {
            unsigned base = sptr(&S->Ks[st][ntp * 16 + nsel][bcsel]);
            #pragma unroll
            for (int kb2 = 0; kb2 < 4; kb2++) {
                unsigned bfr[4];
                ldsm4(bfr, base + kb2 * 32);
                mma_bf16(accC[ntp * 2],     acf[kb2], bfr);
                mma_bf16(accC[ntp * 2 + 1], acf[kb2], bfr + 2);
            }
        }
        if (jt < 15) pos_chunk(S, st, base0 + 192 + 64 * jt, apf, row0, nsel, bcsel, q);

        unsigned vbase[4];
        #pragma unroll
        for (int n2p = 0; n2p < 4; n2p++)
            vbase[n2p] = sptr(&S->Vt[st][n2p * 16 + nsel][bcsel]);

        int basew = 1024 + 64 * jt - i0;
        bool fixc = (i0 == 0) && (jt == 15) && (warp == 0) && (g == 0) && (q == 3);
        #pragma unroll
        for (int kb2 = 0; kb2 < 4; kb2++) {
            unsigned a[4];
            #pragma unroll
            for (int half = 0; half < 2; half++) {
                int nt = kb2 * 2 + half;
                int jl = nt * 8 + 2 * q;
                int il0 = row0, il1 = row0 + 8;
                float r00 = __bfloat162float(S->R[il0][(basew + jl - il0) & 255]);
                float r01 = __bfloat162float(S->R[il0][(basew + jl + 1 - il0) & 255]);
                float r10 = __bfloat162float(S->R[il1][(basew + jl - il1) & 255]);
                float r11 = __bfloat162float(S->R[il1][(basew + jl + 1 - il1) & 255]);
                if (fixc && nt == 7) r01 = gfixv;
                float e0 = __expf((accC[nt][0] + r00) * 0.125f);
                float e1 = __expf((accC[nt][1] + r01) * 0.125f);
                float e2 = __expf((accC[nt][2] + r10) * 0.125f);
                float e3 = __expf((accC[nt][3] + r11) * 0.125f);
                sumA += e0 + e1; sumB += e2 + e3;
                a[half * 2]     = pack_bf16(e0, e1);
                a[half * 2 + 1] = pack_bf16(e2, e3);
            }
            #pragma unroll
            for (int n2p = 0; n2p < 4; n2p++) {
                unsigned vfr[4];
                ldsm4(vfr, vbase[n2p] + kb2 * 32);
                mma_bf16(accO[n2p * 2],     a, vfr);
                mma_bf16(accO[n2p * 2 + 1], a, vfr + 2);
            }
        }
    }

    sumA += __shfl_xor_sync(0xFFFFFFFFu, sumA, 1);
    sumA += __shfl_xor_sync(0xFFFFFFFFu, sumA, 2);
    sumB += __shfl_xor_sync(0xFFFFFFFFu, sumB, 1);
    sumB += __shfl_xor_sync(0xFFFFFFFFu, sumB, 2);
    float invA = 1.f / sumA, invB = 1.f / sumB;
    #pragma unroll
    for (int n2 = 0; n2 < 8; n2++) {
        int col = h * 64 + n2 * 8 + 2 * q;
        size_t r = (size_t)(b * T + i0 + row0);
        __half2 h0 = __floats2half2_rn(accO[n2][0] * invA, accO[n2][1] * invA);
        __half2 h1 = __floats2half2_rn(accO[n2][2] * invB, accO[n2][3] * invB);
        *(unsigned*)&g_oh[r * D + col] = *(unsigned*)&h0;
        *(unsigned*)&g_oh[(r + 8) * D + col] = *(unsigned*)&h1;
    }
    gdc_launch();
}

extern "C" void kernel_launch(void* const* d_in, const int* in_sizes, int n_in,
                              void* d_out, int out_size) {
    const float* x     = (const float*)d_in[0];
    const float* pos   = (const float*)d_in[1];
    const float* cb    = (const float*)d_in[2];
    const float* pb    = (const float*)d_in[3];
    const float* gamma = (const float*)d_in[4];
    const float* beta  = (const float*)d_in[5];
    const float* Wq    = (const float*)d_in[6];
    const float* bq    = (const float*)d_in[7];
    const float* Wk    = (const float*)d_in[8];
    const float* bk    = (const float*)d_in[9];
    const float* Wv    = (const float*)d_in[10];
    const float* bv    = (const float*)d_in[11];
    const float* Wp    = (const float*)d_in[12];
    const float* Wo    = (const float*)d_in[13];
    const float* bo    = (const float*)d_in[14];
    float* out = (float*)d_out;

    cudaFuncSetAttribute(projall_kernel, cudaFuncAttributeMaxDynamicSharedMemorySize,
                         (int)sizeof(PSmem));
    cudaFuncSetAttribute(projout_kernel, cudaFuncAttributeMaxDynamicSharedMemorySize,
                         (int)sizeof(POSmem));
    cudaFuncSetAttribute(flash_kernel, cudaFuncAttributeMaxDynamicSharedMemorySize,
                         (int)sizeof(FlashSmem));

    // PDL launch attribute (secondary kernels may begin while predecessor drains)
    cudaLaunchAttribute pdl[1];
    pdl[0].id = cudaLaunchAttributeProgrammaticStreamSerialization;
    pdl[0].val.programmaticStreamSerializationAllowed = 1;

    // 1. merged prep: 5 weight transposes + pos convert (float4) + LayerNorm
    prep_kernel<<<9470, 256>>>(x, gamma, beta, pos, Wq, Wk, Wv, Wp, Wo);

    // 2. unified projections (q/k/v/pos, bf16, ldmatrix, 3-stage pipeline)
    {
        cudaLaunchConfig_t cfg = {};
        cfg.gridDim = dim3(4, 160);
        cfg.blockDim = dim3(256);
        cfg.dynamicSmemBytes = sizeof(PSmem);
        cfg.attrs = pdl; cfg.numAttrs = 1;
        cudaLaunchKernelEx(&cfg, projall_kernel, bq, bk, bv);
    }

    // 3. fused flash attention (bf16 mma; o written as fp16)
    {
        cudaLaunchConfig_t cfg = {};
        cfg.gridDim = dim3(16, 32);
        cfg.blockDim = dim3(128);
        cfg.dynamicSmemBytes = sizeof(FlashSmem);
        cfg.attrs = pdl; cfg.numAttrs = 1;
        cudaLaunchKernelEx(&cfg, flash_kernel, cb, pb);
    }

    // 4. output projection (fp16 mma) + bias + residual (x prefetched)
    {
        cudaLaunchConfig_t cfg = {};
        cfg.gridDim = dim3(4, 64);
        cfg.blockDim = dim3(256);
        cfg.dynamicSmemBytes = sizeof(POSmem);
        cfg.attrs = pdl; cfg.numAttrs = 1;
        cudaLaunchKernelEx(&cfg, projout_kernel, bo, x, out);
    }
}